// round 1
// baseline (speedup 1.0000x reference)
#include <cuda_runtime.h>
#include <cuda_bf16.h>
#include <cstdint>

// ---------------- problem constants ----------------
#define B_  16
#define H_  32
#define W_  64
#define WH  33            // W/2+1
#define C_  768
#define NBLK 4
#define BS_ 192           // C/NBLK
#define P_  (B_*H_*WH)    // 16896 frequency positions

// GEMM tiling
#define BM 64
#define BN 64
#define BK 16

// ---------------- scratch (feature-major [C, P]) ----------------
__device__ float g_xr[(size_t)C_ * P_];
__device__ float g_xi[(size_t)C_ * P_];
__device__ float g_r1[(size_t)C_ * P_];
__device__ float g_i1[(size_t)C_ * P_];
__device__ float g_r2[(size_t)C_ * P_];
__device__ float g_i2[(size_t)C_ * P_];

// =====================================================================
// Kernel 1: bias GEMM  out[m,c] = sum_k x[m,k]*bw[c,k] + bb[c]
// =====================================================================
__global__ __launch_bounds__(256) void bias_gemm(
    const float* __restrict__ X, const float* __restrict__ Wm,
    const float* __restrict__ bb, float* __restrict__ out)
{
    __shared__ float As[BM][BK];
    __shared__ float Bs[BN][BK + 1];
    int tid = threadIdx.x;
    int tx = tid & 15, ty = tid >> 4;
    int m0 = blockIdx.y * BM, c0 = blockIdx.x * BN;
    float acc[4][4] = {};

    for (int kt = 0; kt < C_; kt += BK) {
        int r  = tid >> 2;
        int k4 = (tid & 3) * 4;
        float4 va = *reinterpret_cast<const float4*>(&X [(size_t)(m0 + r) * C_ + kt + k4]);
        As[r][k4] = va.x; As[r][k4+1] = va.y; As[r][k4+2] = va.z; As[r][k4+3] = va.w;
        float4 vb = *reinterpret_cast<const float4*>(&Wm[(size_t)(c0 + r) * C_ + kt + k4]);
        Bs[r][k4] = vb.x; Bs[r][k4+1] = vb.y; Bs[r][k4+2] = vb.z; Bs[r][k4+3] = vb.w;
        __syncthreads();
        #pragma unroll
        for (int kk = 0; kk < BK; kk++) {
            float a[4], b[4];
            #pragma unroll
            for (int i = 0; i < 4; i++) a[i] = As[ty*4+i][kk];
            #pragma unroll
            for (int j = 0; j < 4; j++) b[j] = Bs[tx*4+j][kk];
            #pragma unroll
            for (int i = 0; i < 4; i++)
                #pragma unroll
                for (int j = 0; j < 4; j++) acc[i][j] += a[i] * b[j];
        }
        __syncthreads();
    }
    #pragma unroll
    for (int i = 0; i < 4; i++) {
        size_t m = m0 + ty*4 + i;
        #pragma unroll
        for (int j = 0; j < 4; j++) {
            int c = c0 + tx*4 + j;
            out[m * C_ + c] = acc[i][j] + bb[c];
        }
    }
}

// =====================================================================
// Kernel 2: forward 2D rFFT (ortho) per (b,c) plane via separable DFT
// writes g_xr/g_xi at [c*P_ + b*1056 + (m*33+k)]
// =====================================================================
__global__ __launch_bounds__(256) void fft_fwd(const float* __restrict__ X)
{
    int c = blockIdx.x, b = blockIdx.y;
    __shared__ float twc[64], tws[64];                 // e^{-2*pi*i*n/64}
    __shared__ float sIn[H_ * W_];                     // 2048
    __shared__ float sFr[H_ * WH], sFi[H_ * WH];       // 1056 each
    int tid = threadIdx.x;
    if (tid < 64) {
        float s, cc;
        sincospif(-(float)tid / 32.0f, &s, &cc);
        twc[tid] = cc; tws[tid] = s;
    }
    const float* xp = X + (size_t)b * (H_ * W_) * C_ + c;
    for (int i = tid; i < H_ * W_; i += blockDim.x) sIn[i] = xp[(size_t)i * C_];
    __syncthreads();

    // row real DFT along W: Fr[r][k] = sum_w in[r][w] e^{-2pi i k w/64}
    for (int t = tid; t < H_ * WH; t += blockDim.x) {
        int r = t / WH, k = t % WH;
        const float* row = &sIn[r * W_];
        float ar = 0.f, ai = 0.f;
        #pragma unroll 8
        for (int w = 0; w < W_; w++) {
            int idx = (k * w) & 63;
            float v = row[w];
            ar += v * twc[idx];
            ai += v * tws[idx];
        }
        sFr[t] = ar; sFi[t] = ai;
    }
    __syncthreads();

    // column DFT along H: G[m][k] = sum_h F[h][k] e^{-2pi i h m/32}
    const float scale = 0.0220970869120796f;   // 1/sqrt(2048)
    size_t base = (size_t)c * P_ + (size_t)b * (H_ * WH);
    for (int t = tid; t < H_ * WH; t += blockDim.x) {
        int m = t / WH, k = t % WH;
        float ar = 0.f, ai = 0.f;
        #pragma unroll 8
        for (int h = 0; h < H_; h++) {
            int idx = (2 * h * m) & 63;
            float cr = sFr[h * WH + k], ci = sFi[h * WH + k];
            float tc = twc[idx], ts = tws[idx];
            ar += cr * tc - ci * ts;
            ai += cr * ts + ci * tc;
        }
        g_xr[base + t] = ar * scale;
        g_xi[base + t] = ai * scale;
    }
}

// =====================================================================
// Kernel 3: layer1  r1 = relu(Wr^T xr - Wi^T xi + br), i1 = relu(Wi^T xr + Wr^T xi + bi)
// per nb-block; Out[j,p] = sum_d W[d,j]*In[d,p]
// =====================================================================
__global__ __launch_bounds__(256) void freq_layer1(
    const float* __restrict__ w1, const float* __restrict__ b1)
{
    int nb = blockIdx.z;
    int p0 = blockIdx.x * 64;
    int j0 = blockIdx.y * 64;
    const float* Wr = w1 + (size_t)nb * BS_ * BS_;
    const float* Wi = w1 + (size_t)(NBLK + nb) * BS_ * BS_;
    const float* Xr = g_xr + (size_t)nb * BS_ * P_;
    const float* Xi = g_xi + (size_t)nb * BS_ * P_;

    __shared__ float sWr[BK][64], sWi[BK][64], sXr[BK][64], sXi[BK][64];
    int tid = threadIdx.x;
    int tx = tid & 15, ty = tid >> 4;
    float accR[4][4] = {}, accI[4][4] = {};

    for (int kt = 0; kt < BS_; kt += BK) {
        int d  = tid >> 4;
        int c4 = (tid & 15) * 4;
        *(float4*)&sWr[d][c4] = *(const float4*)&Wr[(size_t)(kt + d) * BS_ + j0 + c4];
        *(float4*)&sWi[d][c4] = *(const float4*)&Wi[(size_t)(kt + d) * BS_ + j0 + c4];
        *(float4*)&sXr[d][c4] = *(const float4*)&Xr[(size_t)(kt + d) * P_  + p0 + c4];
        *(float4*)&sXi[d][c4] = *(const float4*)&Xi[(size_t)(kt + d) * P_  + p0 + c4];
        __syncthreads();
        #pragma unroll
        for (int kk = 0; kk < BK; kk++) {
            float wr[4], wi[4], xr[4], xi[4];
            #pragma unroll
            for (int i = 0; i < 4; i++) { wr[i] = sWr[kk][ty*4+i]; wi[i] = sWi[kk][ty*4+i]; }
            #pragma unroll
            for (int j = 0; j < 4; j++) { xr[j] = sXr[kk][tx*4+j]; xi[j] = sXi[kk][tx*4+j]; }
            #pragma unroll
            for (int i = 0; i < 4; i++)
                #pragma unroll
                for (int j = 0; j < 4; j++) {
                    accR[i][j] += wr[i]*xr[j] - wi[i]*xi[j];
                    accI[i][j] += wi[i]*xr[j] + wr[i]*xi[j];
                }
        }
        __syncthreads();
    }
    const float* br = b1 + (size_t)nb * BS_;
    const float* bi = b1 + (size_t)(NBLK + nb) * BS_;
    #pragma unroll
    for (int i = 0; i < 4; i++) {
        int j = j0 + ty*4 + i;
        float vbr = br[j], vbi = bi[j];
        size_t ro = (size_t)(nb * BS_ + j) * P_;
        #pragma unroll
        for (int jj = 0; jj < 4; jj++) {
            int p = p0 + tx*4 + jj;
            float r = accR[i][jj] + vbr; r = r > 0.f ? r : 0.f;
            float u = accI[i][jj] + vbi; u = u > 0.f ? u : 0.f;
            g_r1[ro + p] = r;
            g_i1[ro + p] = u;
        }
    }
}

// =====================================================================
// Kernel 4/5: layer2.  phase0: r2 = W2r^T r1 - W2i^T i1 + b2r
//                      phase1: i2 = W2i^T r2 + W2r^T i1 + b2i
// =====================================================================
__global__ __launch_bounds__(256) void freq_layer2(
    const float* __restrict__ w2, const float* __restrict__ b2, int phase)
{
    int nb = blockIdx.z;
    int p0 = blockIdx.x * 64;
    int j0 = blockIdx.y * 64;
    const float* A  = (phase == 0 ? g_r1 : g_r2) + (size_t)nb * BS_ * P_;
    const float* Bm = g_i1 + (size_t)nb * BS_ * P_;
    const float* Wa = w2 + (size_t)((phase == 0 ? 0 : NBLK) + nb) * BS_ * BS_;
    const float* Wb = w2 + (size_t)((phase == 0 ? NBLK : 0) + nb) * BS_ * BS_;
    const float* bias = b2 + (size_t)(phase == 0 ? 0 : NBLK) * BS_ + (size_t)nb * BS_;
    float* O = (phase == 0 ? g_r2 : g_i2) + (size_t)nb * BS_ * P_;
    float sgn = (phase == 0) ? -1.f : 1.f;

    __shared__ float sWa[BK][64], sWb[BK][64], sA[BK][64], sB[BK][64];
    int tid = threadIdx.x;
    int tx = tid & 15, ty = tid >> 4;
    float acc[4][4] = {};

    for (int kt = 0; kt < BS_; kt += BK) {
        int d  = tid >> 4;
        int c4 = (tid & 15) * 4;
        *(float4*)&sWa[d][c4] = *(const float4*)&Wa[(size_t)(kt + d) * BS_ + j0 + c4];
        *(float4*)&sWb[d][c4] = *(const float4*)&Wb[(size_t)(kt + d) * BS_ + j0 + c4];
        *(float4*)&sA [d][c4] = *(const float4*)&A [(size_t)(kt + d) * P_  + p0 + c4];
        *(float4*)&sB [d][c4] = *(const float4*)&Bm[(size_t)(kt + d) * P_  + p0 + c4];
        __syncthreads();
        #pragma unroll
        for (int kk = 0; kk < BK; kk++) {
            float wa[4], wb[4], av[4], bv[4];
            #pragma unroll
            for (int i = 0; i < 4; i++) { wa[i] = sWa[kk][ty*4+i]; wb[i] = sWb[kk][ty*4+i]; }
            #pragma unroll
            for (int j = 0; j < 4; j++) { av[j] = sA[kk][tx*4+j]; bv[j] = sB[kk][tx*4+j]; }
            #pragma unroll
            for (int i = 0; i < 4; i++)
                #pragma unroll
                for (int j = 0; j < 4; j++)
                    acc[i][j] += wa[i]*av[j] + sgn * wb[i]*bv[j];
        }
        __syncthreads();
    }
    #pragma unroll
    for (int i = 0; i < 4; i++) {
        int j = j0 + ty*4 + i;
        float vb = bias[j];
        size_t ro = (size_t)j * P_;
        #pragma unroll
        for (int jj = 0; jj < 4; jj++) {
            int p = p0 + tx*4 + jj;
            O[ro + p] = acc[i][jj] + vb;
        }
    }
}

// =====================================================================
// Kernel 6: inverse 2D rFFT (ortho), accumulate into d_out
// =====================================================================
__global__ __launch_bounds__(256) void fft_inv(float* __restrict__ out)
{
    int c = blockIdx.x, b = blockIdx.y;
    __shared__ float twc[64], tws[64];                 // e^{+2*pi*i*n/64}
    __shared__ float sGr[H_ * WH], sGi[H_ * WH];
    __shared__ float sFr[H_ * WH], sFi[H_ * WH];
    int tid = threadIdx.x;
    if (tid < 64) {
        float s, cc;
        sincospif((float)tid / 32.0f, &s, &cc);
        twc[tid] = cc; tws[tid] = s;
    }
    size_t base = (size_t)c * P_ + (size_t)b * (H_ * WH);
    for (int t = tid; t < H_ * WH; t += blockDim.x) {
        sGr[t] = g_r2[base + t];
        sGi[t] = g_i2[base + t];
    }
    __syncthreads();

    // inverse along H (full complex): F[h][k] = sum_m G[m][k] e^{+2pi i h m/32}
    for (int t = tid; t < H_ * WH; t += blockDim.x) {
        int h = t / WH, k = t % WH;
        float ar = 0.f, ai = 0.f;
        #pragma unroll 8
        for (int m = 0; m < H_; m++) {
            int idx = (2 * h * m) & 63;
            float gr = sGr[m * WH + k], gi = sGi[m * WH + k];
            float tc = twc[idx], ts = tws[idx];
            ar += gr * tc - gi * ts;
            ai += gr * ts + gi * tc;
        }
        sFr[t] = ar; sFi[t] = ai;
    }
    __syncthreads();

    // inverse real along W; imag of DC & Nyquist ignored (C2R semantics)
    const float scale = 0.0220970869120796f;   // 1/sqrt(2048)
    float* op = out + (size_t)b * (H_ * W_) * C_ + c;
    for (int t = tid; t < H_ * W_; t += blockDim.x) {
        int h = t / W_, w = t % W_;
        const float* fr = &sFr[h * WH];
        const float* fi = &sFi[h * WH];
        float v = fr[0] + ((w & 1) ? -fr[32] : fr[32]);
        #pragma unroll 8
        for (int k = 1; k < 32; k++) {
            int idx = (k * w) & 63;
            v += 2.f * (fr[k] * twc[idx] - fi[k] * tws[idx]);
        }
        op[(size_t)t * C_] += v * scale;
    }
}

// =====================================================================
extern "C" void kernel_launch(void* const* d_in, const int* in_sizes, int n_in,
                              void* d_out, int out_size)
{
    const float* x  = (const float*)d_in[0];
    const float* w1 = (const float*)d_in[1];
    const float* b1 = (const float*)d_in[2];
    const float* w2 = (const float*)d_in[3];
    const float* b2 = (const float*)d_in[4];
    const float* bw = (const float*)d_in[5];
    const float* bb = (const float*)d_in[6];
    float* out = (float*)d_out;

    dim3 gGemm(C_ / BN, (B_ * H_ * W_) / BM);       // (12, 512)
    bias_gemm<<<gGemm, 256>>>(x, bw, bb, out);

    dim3 gPlane(C_, B_);                             // (768, 16)
    fft_fwd<<<gPlane, 256>>>(x);

    dim3 gFreq(P_ / 64, BS_ / 64, NBLK);             // (264, 3, 4)
    freq_layer1<<<gFreq, 256>>>(w1, b1);
    freq_layer2<<<gFreq, 256>>>(w2, b2, 0);
    freq_layer2<<<gFreq, 256>>>(w2, b2, 1);

    fft_inv<<<gPlane, 256>>>(out);
}

// round 2
// speedup vs baseline: 1.4347x; 1.4347x over previous
#include <cuda_runtime.h>
#include <cuda_bf16.h>
#include <cstdint>

// ---------------- problem constants ----------------
#define B_  16
#define H_  32
#define W_  64
#define WH  33            // W/2+1
#define C_  768
#define NBLK 4
#define BS_ 192           // C/NBLK
#define P_  (B_*H_*WH)    // 16896 frequency positions
#define NKC (WH*C_)       // 25344 = flattened (k,c) per (b,h) row

#define SC_ORTHO 0.0220970869120796f   // 1/sqrt(2048)

// GEMM tiling (bias)
#define BM 64
#define BN 64
#define BK 16

// ---------------- scratch: [P, C] layout (channel contiguous) ----------------
// aliases: Y (W-DFT result) lives in g_r1/g_i1; F (H-inverse result) in g_xr/g_xi
__device__ float g_xr[(size_t)P_ * C_];
__device__ float g_xi[(size_t)P_ * C_];
__device__ float g_r1[(size_t)P_ * C_];
__device__ float g_i1[(size_t)P_ * C_];
__device__ float g_r2[(size_t)P_ * C_];
__device__ float g_i2[(size_t)P_ * C_];

// twiddle tables
__device__ float g_t1c[WH * W_];   // cos(2*pi*k*w/64)
__device__ float g_t1s[WH * W_];   // -sin(2*pi*k*w/64)
__device__ float g_t2c[H_ * H_];   // cos(2*pi*m*h/32)
__device__ float g_t2s[H_ * H_];   // -sin(2*pi*m*h/32)

__global__ void init_tables()
{
    int tid = threadIdx.x;
    for (int i = tid; i < WH * W_; i += blockDim.x) {
        int k = i / W_, w = i % W_;
        float s, c;
        sincospif(-(float)(k * w) / 32.0f, &s, &c);
        g_t1c[i] = c; g_t1s[i] = s;
    }
    for (int i = tid; i < H_ * H_; i += blockDim.x) {
        int m = i / H_, h = i % H_;
        float s, c;
        sincospif(-(float)(m * h) / 16.0f, &s, &c);
        g_t2c[i] = c; g_t2s[i] = s;
    }
}

// =====================================================================
// Kernel 1: bias GEMM  out[m,c] = sum_k x[m,k]*bw[c,k] + bb[c]
// =====================================================================
__global__ __launch_bounds__(256) void bias_gemm(
    const float* __restrict__ X, const float* __restrict__ Wm,
    const float* __restrict__ bb, float* __restrict__ out)
{
    __shared__ float As[BM][BK + 1];
    __shared__ float Bs[BN][BK + 1];
    int tid = threadIdx.x;
    int tx = tid & 15, ty = tid >> 4;
    int m0 = blockIdx.y * BM, c0 = blockIdx.x * BN;
    float acc[4][4] = {};

    for (int kt = 0; kt < C_; kt += BK) {
        int r  = tid >> 2;
        int k4 = (tid & 3) * 4;
        float4 va = *reinterpret_cast<const float4*>(&X [(size_t)(m0 + r) * C_ + kt + k4]);
        As[r][k4] = va.x; As[r][k4+1] = va.y; As[r][k4+2] = va.z; As[r][k4+3] = va.w;
        float4 vb = *reinterpret_cast<const float4*>(&Wm[(size_t)(c0 + r) * C_ + kt + k4]);
        Bs[r][k4] = vb.x; Bs[r][k4+1] = vb.y; Bs[r][k4+2] = vb.z; Bs[r][k4+3] = vb.w;
        __syncthreads();
        #pragma unroll
        for (int kk = 0; kk < BK; kk++) {
            float a[4], b[4];
            #pragma unroll
            for (int i = 0; i < 4; i++) a[i] = As[ty*4+i][kk];
            #pragma unroll
            for (int j = 0; j < 4; j++) b[j] = Bs[tx*4+j][kk];
            #pragma unroll
            for (int i = 0; i < 4; i++)
                #pragma unroll
                for (int j = 0; j < 4; j++) acc[i][j] += a[i] * b[j];
        }
        __syncthreads();
    }
    #pragma unroll
    for (int i = 0; i < 4; i++) {
        size_t m = m0 + ty*4 + i;
        #pragma unroll
        for (int j = 0; j < 4; j++) {
            int c = c0 + tx*4 + j;
            out[m * C_ + c] = acc[i][j] + bb[c];
        }
    }
}

// =====================================================================
// Kernel 2: forward DFT along W.
// x[(bh*64+w)*768+c] -> Y[(bh*33+k)*768+c]  (Y in g_r1/g_i1)
// block: (bh, c-chunk of 64). threads 256 = 16 c-quads x 16 k-groups.
// =====================================================================
__global__ __launch_bounds__(256) void fft_w_fwd(const float* __restrict__ X)
{
    int bh = blockIdx.x;
    int c0 = blockIdx.y * 64;
    __shared__ float sX[W_][64];            // [w][c]  16KB
    __shared__ float sTc[WH * W_];          // 8.4KB
    __shared__ float sTs[WH * W_];
    int tid = threadIdx.x;

    for (int i = tid; i < WH * W_; i += 256) { sTc[i] = g_t1c[i]; sTs[i] = g_t1s[i]; }
    const float* xp = X + (size_t)bh * 64 * C_ + c0;
    for (int i = tid; i < W_ * 16; i += 256) {
        int w = i >> 4, q = i & 15;
        *(float4*)&sX[w][q * 4] = *(const float4*)&xp[(size_t)w * C_ + q * 4];
    }
    __syncthreads();

    int quad = tid & 15, kg = tid >> 4;     // k in {kg, kg+16, kg+32}
    float ar[3][4] = {}, ai[3][4] = {};
    #pragma unroll 8
    for (int w = 0; w < W_; w++) {
        float4 v = *(const float4*)&sX[w][quad * 4];
        #pragma unroll
        for (int i = 0; i < 3; i++) {
            int k = kg + 16 * i;
            if (k < WH) {
                float tc = sTc[k * W_ + w], ts = sTs[k * W_ + w];
                ar[i][0] += v.x * tc; ai[i][0] += v.x * ts;
                ar[i][1] += v.y * tc; ai[i][1] += v.y * ts;
                ar[i][2] += v.z * tc; ai[i][2] += v.z * ts;
                ar[i][3] += v.w * tc; ai[i][3] += v.w * ts;
            }
        }
    }
    #pragma unroll
    for (int i = 0; i < 3; i++) {
        int k = kg + 16 * i;
        if (k < WH) {
            size_t o = ((size_t)bh * WH + k) * C_ + c0 + quad * 4;
            *(float4*)&g_r1[o] = *(float4*)&ar[i][0];
            *(float4*)&g_i1[o] = *(float4*)&ai[i][0];
        }
    }
}

// =====================================================================
// Kernel 3: forward DFT along H (complex), ortho scale applied.
// Y[(b*32+h)*25344+n] -> Z=g_xr/g_xi[(b*32+m)*25344+n]
// block: (n-chunk of 128, b). threads 256 = 32 n-quads x 8 m-groups.
// =====================================================================
__global__ __launch_bounds__(256) void fft_h_fwd()
{
    int n0 = blockIdx.x * 128;
    int b  = blockIdx.y;
    __shared__ float sYr[H_][128], sYi[H_][128];   // 32KB
    __shared__ float sA[H_ * H_], sB[H_ * H_];     // 8KB
    int tid = threadIdx.x;

    for (int i = tid; i < H_ * H_; i += 256) { sA[i] = g_t2c[i]; sB[i] = g_t2s[i]; }
    const float* Yr = g_r1 + (size_t)b * H_ * NKC + n0;
    const float* Yi = g_i1 + (size_t)b * H_ * NKC + n0;
    for (int i = tid; i < H_ * 32; i += 256) {
        int h = i >> 5, q = i & 31;
        *(float4*)&sYr[h][q * 4] = *(const float4*)&Yr[(size_t)h * NKC + q * 4];
        *(float4*)&sYi[h][q * 4] = *(const float4*)&Yi[(size_t)h * NKC + q * 4];
    }
    __syncthreads();

    int quad = tid & 31, mg = tid >> 5;
    float zr[4][4] = {}, zi[4][4] = {};
    #pragma unroll 8
    for (int h = 0; h < H_; h++) {
        float4 yr = *(const float4*)&sYr[h][quad * 4];
        float4 yi = *(const float4*)&sYi[h][quad * 4];
        #pragma unroll
        for (int i = 0; i < 4; i++) {
            int m = mg * 4 + i;
            float a = sA[m * H_ + h], s = sB[m * H_ + h];
            zr[i][0] += a * yr.x - s * yi.x;  zi[i][0] += a * yi.x + s * yr.x;
            zr[i][1] += a * yr.y - s * yi.y;  zi[i][1] += a * yi.y + s * yr.y;
            zr[i][2] += a * yr.z - s * yi.z;  zi[i][2] += a * yi.z + s * yr.z;
            zr[i][3] += a * yr.w - s * yi.w;  zi[i][3] += a * yi.w + s * yr.w;
        }
    }
    float* Zr = g_xr + (size_t)b * H_ * NKC + n0;
    float* Zi = g_xi + (size_t)b * H_ * NKC + n0;
    #pragma unroll
    for (int i = 0; i < 4; i++) {
        int m = mg * 4 + i;
        float4 vr, vi;
        vr.x = zr[i][0] * SC_ORTHO; vr.y = zr[i][1] * SC_ORTHO;
        vr.z = zr[i][2] * SC_ORTHO; vr.w = zr[i][3] * SC_ORTHO;
        vi.x = zi[i][0] * SC_ORTHO; vi.y = zi[i][1] * SC_ORTHO;
        vi.z = zi[i][2] * SC_ORTHO; vi.w = zi[i][3] * SC_ORTHO;
        *(float4*)&Zr[(size_t)m * NKC + quad * 4] = vr;
        *(float4*)&Zi[(size_t)m * NKC + quad * 4] = vi;
    }
}

// =====================================================================
// Kernel 4: layer1 in [P,C] layout.
// r1 = relu(xr@Wr - xi@Wi + br), i1 = relu(xr@Wi + xi@Wr + bi)
// block: (p-tile 64, j-tile 64, nb). threads 256, 4x4 per thread, dual out.
// =====================================================================
__global__ __launch_bounds__(256) void freq_l1(
    const float* __restrict__ w1, const float* __restrict__ b1)
{
    int p0 = blockIdx.x * 64;
    int j0 = blockIdx.y * 64;
    int nb = blockIdx.z;
    const float* Wr = w1 + (size_t)nb * BS_ * BS_;
    const float* Wi = w1 + (size_t)(NBLK + nb) * BS_ * BS_;

    __shared__ float sXr[64][BK + 1], sXi[64][BK + 1];
    __shared__ float sWr[BK][64], sWi[BK][64];
    int tid = threadIdx.x;
    int tx = tid & 15, ty = tid >> 4;
    float accR[4][4] = {}, accI[4][4] = {};

    int pl = tid >> 2, dq = (tid & 3) * 4;     // X fill: 64 p x 4 d-quads
    int dl = tid >> 4, jq = (tid & 15) * 4;    // W fill: 16 d x 16 j-quads

    for (int kt = 0; kt < BS_; kt += BK) {
        float4 vr = *(const float4*)&g_xr[(size_t)(p0 + pl) * C_ + nb * BS_ + kt + dq];
        float4 vi = *(const float4*)&g_xi[(size_t)(p0 + pl) * C_ + nb * BS_ + kt + dq];
        sXr[pl][dq] = vr.x; sXr[pl][dq+1] = vr.y; sXr[pl][dq+2] = vr.z; sXr[pl][dq+3] = vr.w;
        sXi[pl][dq] = vi.x; sXi[pl][dq+1] = vi.y; sXi[pl][dq+2] = vi.z; sXi[pl][dq+3] = vi.w;
        *(float4*)&sWr[dl][jq] = *(const float4*)&Wr[(size_t)(kt + dl) * BS_ + j0 + jq];
        *(float4*)&sWi[dl][jq] = *(const float4*)&Wi[(size_t)(kt + dl) * BS_ + j0 + jq];
        __syncthreads();
        #pragma unroll
        for (int kk = 0; kk < BK; kk++) {
            float xr[4], xi[4];
            #pragma unroll
            for (int i = 0; i < 4; i++) { xr[i] = sXr[ty*4+i][kk]; xi[i] = sXi[ty*4+i][kk]; }
            float4 wr = *(const float4*)&sWr[kk][tx * 4];
            float4 wi = *(const float4*)&sWi[kk][tx * 4];
            float wrv[4] = {wr.x, wr.y, wr.z, wr.w};
            float wiv[4] = {wi.x, wi.y, wi.z, wi.w};
            #pragma unroll
            for (int i = 0; i < 4; i++)
                #pragma unroll
                for (int j = 0; j < 4; j++) {
                    accR[i][j] += xr[i] * wrv[j] - xi[i] * wiv[j];
                    accI[i][j] += xr[i] * wiv[j] + xi[i] * wrv[j];
                }
        }
        __syncthreads();
    }
    const float* br = b1 + (size_t)nb * BS_;
    const float* bi = b1 + (size_t)(NBLK + nb) * BS_;
    #pragma unroll
    for (int i = 0; i < 4; i++) {
        size_t ro = (size_t)(p0 + ty*4 + i) * C_ + nb * BS_ + j0 + tx * 4;
        float4 vr, vi;
        float* pr = &vr.x; float* pi = &vi.x;
        #pragma unroll
        for (int j = 0; j < 4; j++) {
            int jj = j0 + tx*4 + j;
            float r = accR[i][j] + br[jj]; pr[j] = r > 0.f ? r : 0.f;
            float u = accI[i][j] + bi[jj]; pi[j] = u > 0.f ? u : 0.f;
        }
        *(float4*)&g_r1[ro] = vr;
        *(float4*)&g_i1[ro] = vi;
    }
}

// =====================================================================
// Kernel 5/6: layer2 in [P,C] layout.
// phase0: r2 = r1@W2r - i1@W2i + b2r
// phase1: i2 = r2@W2i + i1@W2r + b2i
// =====================================================================
__global__ __launch_bounds__(256) void freq_l2(
    const float* __restrict__ w2, const float* __restrict__ b2, int phase)
{
    int p0 = blockIdx.x * 64;
    int j0 = blockIdx.y * 64;
    int nb = blockIdx.z;
    const float* A  = (phase == 0 ? g_r1 : g_r2);
    const float* Bm = g_i1;
    const float* Wa = w2 + (size_t)((phase == 0 ? 0 : NBLK) + nb) * BS_ * BS_;
    const float* Wb = w2 + (size_t)((phase == 0 ? NBLK : 0) + nb) * BS_ * BS_;
    const float* bias = b2 + (size_t)(phase == 0 ? 0 : NBLK) * BS_ + (size_t)nb * BS_;
    float* O = (phase == 0 ? g_r2 : g_i2);
    float sgn = (phase == 0) ? -1.f : 1.f;

    __shared__ float sA_[64][BK + 1], sB_[64][BK + 1];
    __shared__ float sWa[BK][64], sWb[BK][64];
    int tid = threadIdx.x;
    int tx = tid & 15, ty = tid >> 4;
    float acc[4][4] = {};

    int pl = tid >> 2, dq = (tid & 3) * 4;
    int dl = tid >> 4, jq = (tid & 15) * 4;

    for (int kt = 0; kt < BS_; kt += BK) {
        float4 va = *(const float4*)&A [(size_t)(p0 + pl) * C_ + nb * BS_ + kt + dq];
        float4 vb = *(const float4*)&Bm[(size_t)(p0 + pl) * C_ + nb * BS_ + kt + dq];
        sA_[pl][dq] = va.x; sA_[pl][dq+1] = va.y; sA_[pl][dq+2] = va.z; sA_[pl][dq+3] = va.w;
        sB_[pl][dq] = vb.x; sB_[pl][dq+1] = vb.y; sB_[pl][dq+2] = vb.z; sB_[pl][dq+3] = vb.w;
        *(float4*)&sWa[dl][jq] = *(const float4*)&Wa[(size_t)(kt + dl) * BS_ + j0 + jq];
        *(float4*)&sWb[dl][jq] = *(const float4*)&Wb[(size_t)(kt + dl) * BS_ + j0 + jq];
        __syncthreads();
        #pragma unroll
        for (int kk = 0; kk < BK; kk++) {
            float av[4], bv[4];
            #pragma unroll
            for (int i = 0; i < 4; i++) { av[i] = sA_[ty*4+i][kk]; bv[i] = sB_[ty*4+i][kk]; }
            float4 wa = *(const float4*)&sWa[kk][tx * 4];
            float4 wb = *(const float4*)&sWb[kk][tx * 4];
            float wav[4] = {wa.x, wa.y, wa.z, wa.w};
            float wbv[4] = {wb.x, wb.y, wb.z, wb.w};
            #pragma unroll
            for (int i = 0; i < 4; i++)
                #pragma unroll
                for (int j = 0; j < 4; j++)
                    acc[i][j] += av[i] * wav[j] + sgn * (bv[i] * wbv[j]);
        }
        __syncthreads();
    }
    #pragma unroll
    for (int i = 0; i < 4; i++) {
        size_t ro = (size_t)(p0 + ty*4 + i) * C_ + nb * BS_ + j0 + tx * 4;
        float4 v;
        float* pv = &v.x;
        #pragma unroll
        for (int j = 0; j < 4; j++) pv[j] = acc[i][j] + bias[j0 + tx*4 + j];
        *(float4*)&O[ro] = v;
    }
}

// =====================================================================
// Kernel 7: inverse DFT along H (complex).
// G=g_r2/g_i2[(b*32+m)*25344+n] -> F=g_xr/g_xi[(b*32+h)*25344+n]
// Fr = gr*t2c + gi*t2s ; Fi = gi*t2c - gr*t2s   (t2s = -sin)
// =====================================================================
__global__ __launch_bounds__(256) void fft_h_inv()
{
    int n0 = blockIdx.x * 128;
    int b  = blockIdx.y;
    __shared__ float sGr[H_][128], sGi[H_][128];
    __shared__ float sA[H_ * H_], sB[H_ * H_];
    int tid = threadIdx.x;

    for (int i = tid; i < H_ * H_; i += 256) { sA[i] = g_t2c[i]; sB[i] = g_t2s[i]; }
    const float* Gr = g_r2 + (size_t)b * H_ * NKC + n0;
    const float* Gi = g_i2 + (size_t)b * H_ * NKC + n0;
    for (int i = tid; i < H_ * 32; i += 256) {
        int m = i >> 5, q = i & 31;
        *(float4*)&sGr[m][q * 4] = *(const float4*)&Gr[(size_t)m * NKC + q * 4];
        *(float4*)&sGi[m][q * 4] = *(const float4*)&Gi[(size_t)m * NKC + q * 4];
    }
    __syncthreads();

    int quad = tid & 31, hg = tid >> 5;
    float fr[4][4] = {}, fi[4][4] = {};
    #pragma unroll 8
    for (int m = 0; m < H_; m++) {
        float4 gr = *(const float4*)&sGr[m][quad * 4];
        float4 gi = *(const float4*)&sGi[m][quad * 4];
        #pragma unroll
        for (int i = 0; i < 4; i++) {
            int h = hg * 4 + i;
            float a = sA[h * H_ + m], s = sB[h * H_ + m];   // note [h][m] == [m][h] symmetric table
            fr[i][0] += a * gr.x + s * gi.x;  fi[i][0] += a * gi.x - s * gr.x;
            fr[i][1] += a * gr.y + s * gi.y;  fi[i][1] += a * gi.y - s * gr.y;
            fr[i][2] += a * gr.z + s * gi.z;  fi[i][2] += a * gi.z - s * gr.z;
            fr[i][3] += a * gr.w + s * gi.w;  fi[i][3] += a * gi.w - s * gr.w;
        }
    }
    float* Fr = g_xr + (size_t)b * H_ * NKC + n0;
    float* Fi = g_xi + (size_t)b * H_ * NKC + n0;
    #pragma unroll
    for (int i = 0; i < 4; i++) {
        int h = hg * 4 + i;
        *(float4*)&Fr[(size_t)h * NKC + quad * 4] = *(float4*)&fr[i][0];
        *(float4*)&Fi[(size_t)h * NKC + quad * 4] = *(float4*)&fi[i][0];
    }
}

// =====================================================================
// Kernel 8: inverse real DFT along W, accumulate into out.
// out[(bh*64+w)*768+c] += sum_k frs[k]*t1c[k][w] + fis[k]*t1s[k][w]
// where frs/fis are pre-weighted (x2 for k=1..31) and pre-scaled.
// =====================================================================
__global__ __launch_bounds__(256) void fft_w_inv(float* __restrict__ out)
{
    int bh = blockIdx.x;
    int c0 = blockIdx.y * 64;
    __shared__ float sFr[WH][64], sFi[WH][64];   // 16.9KB
    __shared__ float sTc[WH * W_], sTs[WH * W_]; // 16.9KB
    int tid = threadIdx.x;

    for (int i = tid; i < WH * W_; i += 256) { sTc[i] = g_t1c[i]; sTs[i] = g_t1s[i]; }
    const float* Fr = g_xr + (size_t)bh * WH * C_ + c0;
    const float* Fi = g_xi + (size_t)bh * WH * C_ + c0;
    for (int i = tid; i < WH * 16; i += 256) {
        int k = i >> 4, q = i & 15;
        float wt = (k == 0 || k == 32) ? SC_ORTHO : 2.f * SC_ORTHO;
        float4 vr = *(const float4*)&Fr[(size_t)k * C_ + q * 4];
        float4 vi = *(const float4*)&Fi[(size_t)k * C_ + q * 4];
        vr.x *= wt; vr.y *= wt; vr.z *= wt; vr.w *= wt;
        vi.x *= wt; vi.y *= wt; vi.z *= wt; vi.w *= wt;
        *(float4*)&sFr[k][q * 4] = vr;
        *(float4*)&sFi[k][q * 4] = vi;
    }
    __syncthreads();

    int quad = tid & 15, wg = tid >> 4;   // 16 c-quads x 16 w-groups (4 w each)
    float acc[4][4] = {};
    #pragma unroll 8
    for (int k = 0; k < WH; k++) {
        float4 fr = *(const float4*)&sFr[k][quad * 4];
        float4 fi = *(const float4*)&sFi[k][quad * 4];
        #pragma unroll
        for (int i = 0; i < 4; i++) {
            int w = wg * 4 + i;
            float tc = sTc[k * W_ + w], ts = sTs[k * W_ + w];
            acc[i][0] += fr.x * tc + fi.x * ts;
            acc[i][1] += fr.y * tc + fi.y * ts;
            acc[i][2] += fr.z * tc + fi.z * ts;
            acc[i][3] += fr.w * tc + fi.w * ts;
        }
    }
    float* op = out + (size_t)bh * 64 * C_ + c0;
    #pragma unroll
    for (int i = 0; i < 4; i++) {
        int w = wg * 4 + i;
        float4 cur = *(float4*)&op[(size_t)w * C_ + quad * 4];
        cur.x += acc[i][0]; cur.y += acc[i][1];
        cur.z += acc[i][2]; cur.w += acc[i][3];
        *(float4*)&op[(size_t)w * C_ + quad * 4] = cur;
    }
}

// =====================================================================
extern "C" void kernel_launch(void* const* d_in, const int* in_sizes, int n_in,
                              void* d_out, int out_size)
{
    const float* x  = (const float*)d_in[0];
    const float* w1 = (const float*)d_in[1];
    const float* b1 = (const float*)d_in[2];
    const float* w2 = (const float*)d_in[3];
    const float* b2 = (const float*)d_in[4];
    const float* bw = (const float*)d_in[5];
    const float* bb = (const float*)d_in[6];
    float* out = (float*)d_out;

    init_tables<<<1, 256>>>();

    dim3 gGemm(C_ / BN, (B_ * H_ * W_) / BM);       // (12, 512)
    bias_gemm<<<gGemm, 256>>>(x, bw, bb, out);

    fft_w_fwd<<<dim3(B_ * H_, C_ / 64), 256>>>(x);          // (512, 12)
    fft_h_fwd<<<dim3(NKC / 128, B_), 256>>>();               // (198, 16)

    dim3 gFreq(P_ / 64, BS_ / 64, NBLK);             // (264, 3, 4)
    freq_l1<<<gFreq, 256>>>(w1, b1);
    freq_l2<<<gFreq, 256>>>(w2, b2, 0);
    freq_l2<<<gFreq, 256>>>(w2, b2, 1);

    fft_h_inv<<<dim3(NKC / 128, B_), 256>>>();               // (198, 16)
    fft_w_inv<<<dim3(B_ * H_, C_ / 64), 256>>>(out);         // (512, 12)
}

// round 4
// speedup vs baseline: 1.9831x; 1.3822x over previous
#include <cuda_runtime.h>
#include <cuda_bf16.h>
#include <cstdint>

// ---------------- problem constants ----------------
#define B_  16
#define H_  32
#define W_  64
#define WH  33            // W/2+1
#define C_  768
#define NBLK 4
#define BS_ 192           // C/NBLK
#define P_  (B_*H_*WH)    // 16896 frequency positions
#define NKC (WH*C_)       // 25344
#define NTOK (B_*H_*W_)   // 32768 spatial tokens

#define SC_ORTHO 0.0220970869120796f   // 1/sqrt(2048)

#define BK 16

// ---------------- scratch ----------------
__device__ float g_xr[(size_t)P_ * C_];
__device__ float g_xi[(size_t)P_ * C_];
__device__ float g_r1[(size_t)P_ * C_];
__device__ float g_i1[(size_t)P_ * C_];
__device__ float g_r2[(size_t)P_ * C_];
__device__ float g_i2[(size_t)P_ * C_];

// twiddle tables
__device__ float g_t1c[WH * W_];
__device__ float g_t1s[WH * W_];
__device__ float g_t2c[H_ * H_];
__device__ float g_t2s[H_ * H_];

// =====================================================================
// portable tensor-core helpers (mma.sync + ldmatrix, sm_80+)
// =====================================================================
__device__ __forceinline__ uint32_t smem_u32(const void* p) {
    uint32_t a;
    asm("{ .reg .u64 t; cvta.to.shared.u64 t, %1; cvt.u32.u64 %0, t; }" : "=r"(a) : "l"(p));
    return a;
}
__device__ __forceinline__ void mma_bf16(float* d, const uint32_t* a, const uint32_t* b) {
    asm volatile("mma.sync.aligned.m16n8k16.row.col.f32.bf16.bf16.f32 "
        "{%0,%1,%2,%3}, {%4,%5,%6,%7}, {%8,%9}, {%0,%1,%2,%3};"
        : "+f"(d[0]), "+f"(d[1]), "+f"(d[2]), "+f"(d[3])
        : "r"(a[0]), "r"(a[1]), "r"(a[2]), "r"(a[3]), "r"(b[0]), "r"(b[1]));
}
__device__ __forceinline__ void ldsm_x4(uint32_t* r, uint32_t addr) {
    asm volatile("ldmatrix.sync.aligned.m8n8.x4.shared.b16 {%0,%1,%2,%3}, [%4];"
        : "=r"(r[0]), "=r"(r[1]), "=r"(r[2]), "=r"(r[3]) : "r"(addr));
}
__device__ __forceinline__ void ldsm_x2(uint32_t* r, uint32_t addr) {
    asm volatile("ldmatrix.sync.aligned.m8n8.x2.shared.b16 {%0,%1}, [%2];"
        : "=r"(r[0]), "=r"(r[1]) : "r"(addr));
}

// =====================================================================
__global__ void init_tables()
{
    int tid = threadIdx.x;
    for (int i = tid; i < WH * W_; i += blockDim.x) {
        int k = i / W_, w = i % W_;
        float s, c;
        sincospif(-(float)(k * w) / 32.0f, &s, &c);
        g_t1c[i] = c; g_t1s[i] = s;
    }
    for (int i = tid; i < H_ * H_; i += blockDim.x) {
        int m = i / H_, h = i % H_;
        float s, c;
        sincospif(-(float)(m * h) / 16.0f, &s, &c);
        g_t2c[i] = c; g_t2s[i] = s;
    }
}

// =====================================================================
// bias GEMM via mma.sync bf16 split-precision:
// out[m,c] = sum_k X[m,k] * Wm[c,k] + bb[c]
// tiles: block 128x128, K-chunk 32; 8 warps of 64x32.
// =====================================================================
#define TBM 128
#define TBN 128
#define TBK 32
#define APAD 8
#define KPAD (TBK + APAD)   // 40 halfs/row -> 80B stride, conflict-free for ldmatrix

__global__ __launch_bounds__(256) void bias_mma(
    const float* __restrict__ X, const float* __restrict__ Wm,
    const float* __restrict__ bb, float* __restrict__ out)
{
    __shared__ __align__(16) __nv_bfloat16 sAhi[TBM][KPAD];
    __shared__ __align__(16) __nv_bfloat16 sAlo[TBM][KPAD];
    __shared__ __align__(16) __nv_bfloat16 sBhi[TBN][KPAD];
    __shared__ __align__(16) __nv_bfloat16 sBlo[TBN][KPAD];

    int tid = threadIdx.x;
    int wid = tid >> 5, lane = tid & 31;
    int wm = wid >> 2, wn = wid & 3;            // 2 x 4 warp grid
    int m0 = blockIdx.y * TBM, n0 = blockIdx.x * TBN;

    float acc[4][4][4] = {};                    // [Mfrag][Nfrag][4]

    // ldmatrix base lane mapping
    int aRow = lane & 15, aKoff = (lane >> 4) * 8;        // A x4
    int bRow = lane & 7,  bKoff = ((lane >> 3) & 1) * 8;  // B x2 (lanes 0-15 used)

    for (int kt = 0; kt < C_; kt += TBK) {
        // fill smem: 128 rows x 8 float4 (A and B each): 1024 float4, 4 per thread
        #pragma unroll
        for (int it = 0; it < 4; it++) {
            int lin = tid + 256 * it;
            int r = lin >> 3, cq = (lin & 7) * 4;
            float4 va = *(const float4*)&X [(size_t)(m0 + r) * C_ + kt + cq];
            float4 vb = *(const float4*)&Wm[(size_t)(n0 + r) * C_ + kt + cq];
            float av[4] = {va.x, va.y, va.z, va.w};
            float bv[4] = {vb.x, vb.y, vb.z, vb.w};
            __nv_bfloat16 ah[4], al[4], bh[4], bl[4];
            #pragma unroll
            for (int q = 0; q < 4; q++) {
                ah[q] = __float2bfloat16(av[q]);
                al[q] = __float2bfloat16(av[q] - __bfloat162float(ah[q]));
                bh[q] = __float2bfloat16(bv[q]);
                bl[q] = __float2bfloat16(bv[q] - __bfloat162float(bh[q]));
            }
            *(uint2*)&sAhi[r][cq] = *(uint2*)ah;
            *(uint2*)&sAlo[r][cq] = *(uint2*)al;
            *(uint2*)&sBhi[r][cq] = *(uint2*)bh;
            *(uint2*)&sBlo[r][cq] = *(uint2*)bl;
        }
        __syncthreads();

        #pragma unroll
        for (int s = 0; s < 2; s++) {           // two K=16 steps
            int k0 = s * 16;
            uint32_t a_hi[4][4], a_lo[4][4], b_hi[4][2], b_lo[4][2];
            #pragma unroll
            for (int i = 0; i < 4; i++) {
                int row = wm * 64 + i * 16 + aRow;
                ldsm_x4(a_hi[i], smem_u32(&sAhi[row][k0 + aKoff]));
                ldsm_x4(a_lo[i], smem_u32(&sAlo[row][k0 + aKoff]));
            }
            #pragma unroll
            for (int j = 0; j < 4; j++) {
                int row = wn * 32 + j * 8 + bRow;
                ldsm_x2(b_hi[j], smem_u32(&sBhi[row][k0 + bKoff]));
                ldsm_x2(b_lo[j], smem_u32(&sBlo[row][k0 + bKoff]));
            }
            #pragma unroll
            for (int i = 0; i < 4; i++)
                #pragma unroll
                for (int j = 0; j < 4; j++) {
                    mma_bf16(acc[i][j], a_hi[i], b_hi[j]);
                    mma_bf16(acc[i][j], a_hi[i], b_lo[j]);
                    mma_bf16(acc[i][j], a_lo[i], b_hi[j]);
                }
        }
        __syncthreads();
    }

    // epilogue: add bias, store float2 pairs
    int group = lane >> 2, qid = lane & 3;
    #pragma unroll
    for (int i = 0; i < 4; i++) {
        #pragma unroll
        for (int j = 0; j < 4; j++) {
            int col = n0 + wn * 32 + j * 8 + qid * 2;
            float b0 = bb[col], b1 = bb[col + 1];
            int r0 = m0 + wm * 64 + i * 16 + group;
            float2 v0 = {acc[i][j][0] + b0, acc[i][j][1] + b1};
            float2 v1 = {acc[i][j][2] + b0, acc[i][j][3] + b1};
            *(float2*)&out[(size_t)r0 * C_ + col]       = v0;
            *(float2*)&out[(size_t)(r0 + 8) * C_ + col] = v1;
        }
    }
}

// =====================================================================
// Kernel 2: forward DFT along W.  x -> Y (g_r1/g_i1)
// =====================================================================
__global__ __launch_bounds__(256) void fft_w_fwd(const float* __restrict__ X)
{
    int bh = blockIdx.x;
    int c0 = blockIdx.y * 64;
    __shared__ float sX[W_][64];
    __shared__ float sTc[WH * W_];
    __shared__ float sTs[WH * W_];
    int tid = threadIdx.x;

    for (int i = tid; i < WH * W_; i += 256) { sTc[i] = g_t1c[i]; sTs[i] = g_t1s[i]; }
    const float* xp = X + (size_t)bh * 64 * C_ + c0;
    for (int i = tid; i < W_ * 16; i += 256) {
        int w = i >> 4, q = i & 15;
        *(float4*)&sX[w][q * 4] = *(const float4*)&xp[(size_t)w * C_ + q * 4];
    }
    __syncthreads();

    int quad = tid & 15, kg = tid >> 4;
    float ar[3][4] = {}, ai[3][4] = {};
    #pragma unroll 8
    for (int w = 0; w < W_; w++) {
        float4 v = *(const float4*)&sX[w][quad * 4];
        #pragma unroll
        for (int i = 0; i < 3; i++) {
            int k = kg + 16 * i;
            if (k < WH) {
                float tc = sTc[k * W_ + w], ts = sTs[k * W_ + w];
                ar[i][0] += v.x * tc; ai[i][0] += v.x * ts;
                ar[i][1] += v.y * tc; ai[i][1] += v.y * ts;
                ar[i][2] += v.z * tc; ai[i][2] += v.z * ts;
                ar[i][3] += v.w * tc; ai[i][3] += v.w * ts;
            }
        }
    }
    #pragma unroll
    for (int i = 0; i < 3; i++) {
        int k = kg + 16 * i;
        if (k < WH) {
            size_t o = ((size_t)bh * WH + k) * C_ + c0 + quad * 4;
            *(float4*)&g_r1[o] = *(float4*)&ar[i][0];
            *(float4*)&g_i1[o] = *(float4*)&ai[i][0];
        }
    }
}

// =====================================================================
// Kernel 3: forward DFT along H (complex), ortho scaled. Y -> g_xr/g_xi
// =====================================================================
__global__ __launch_bounds__(256) void fft_h_fwd()
{
    int n0 = blockIdx.x * 128;
    int b  = blockIdx.y;
    __shared__ float sYr[H_][128], sYi[H_][128];
    __shared__ float sA[H_ * H_], sB[H_ * H_];
    int tid = threadIdx.x;

    for (int i = tid; i < H_ * H_; i += 256) { sA[i] = g_t2c[i]; sB[i] = g_t2s[i]; }
    const float* Yr = g_r1 + (size_t)b * H_ * NKC + n0;
    const float* Yi = g_i1 + (size_t)b * H_ * NKC + n0;
    for (int i = tid; i < H_ * 32; i += 256) {
        int h = i >> 5, q = i & 31;
        *(float4*)&sYr[h][q * 4] = *(const float4*)&Yr[(size_t)h * NKC + q * 4];
        *(float4*)&sYi[h][q * 4] = *(const float4*)&Yi[(size_t)h * NKC + q * 4];
    }
    __syncthreads();

    int quad = tid & 31, mg = tid >> 5;
    float zr[4][4] = {}, zi[4][4] = {};
    #pragma unroll 8
    for (int h = 0; h < H_; h++) {
        float4 yr = *(const float4*)&sYr[h][quad * 4];
        float4 yi = *(const float4*)&sYi[h][quad * 4];
        #pragma unroll
        for (int i = 0; i < 4; i++) {
            int m = mg * 4 + i;
            float a = sA[m * H_ + h], s = sB[m * H_ + h];
            zr[i][0] += a * yr.x - s * yi.x;  zi[i][0] += a * yi.x + s * yr.x;
            zr[i][1] += a * yr.y - s * yi.y;  zi[i][1] += a * yi.y + s * yr.y;
            zr[i][2] += a * yr.z - s * yi.z;  zi[i][2] += a * yi.z + s * yr.z;
            zr[i][3] += a * yr.w - s * yi.w;  zi[i][3] += a * yi.w + s * yr.w;
        }
    }
    float* Zr = g_xr + (size_t)b * H_ * NKC + n0;
    float* Zi = g_xi + (size_t)b * H_ * NKC + n0;
    #pragma unroll
    for (int i = 0; i < 4; i++) {
        int m = mg * 4 + i;
        float4 vr, vi;
        vr.x = zr[i][0] * SC_ORTHO; vr.y = zr[i][1] * SC_ORTHO;
        vr.z = zr[i][2] * SC_ORTHO; vr.w = zr[i][3] * SC_ORTHO;
        vi.x = zi[i][0] * SC_ORTHO; vi.y = zi[i][1] * SC_ORTHO;
        vi.z = zi[i][2] * SC_ORTHO; vi.w = zi[i][3] * SC_ORTHO;
        *(float4*)&Zr[(size_t)m * NKC + quad * 4] = vr;
        *(float4*)&Zi[(size_t)m * NKC + quad * 4] = vi;
    }
}

// =====================================================================
// Kernel 4: layer1 in [P,C] layout (fp32 SIMT)
// =====================================================================
__global__ __launch_bounds__(256) void freq_l1(
    const float* __restrict__ w1, const float* __restrict__ b1)
{
    int p0 = blockIdx.x * 64;
    int j0 = blockIdx.y * 64;
    int nb = blockIdx.z;
    const float* Wr = w1 + (size_t)nb * BS_ * BS_;
    const float* Wi = w1 + (size_t)(NBLK + nb) * BS_ * BS_;

    __shared__ float sXr[64][BK + 1], sXi[64][BK + 1];
    __shared__ float sWr[BK][64], sWi[BK][64];
    int tid = threadIdx.x;
    int tx = tid & 15, ty = tid >> 4;
    float accR[4][4] = {}, accI[4][4] = {};

    int pl = tid >> 2, dq = (tid & 3) * 4;
    int dl = tid >> 4, jq = (tid & 15) * 4;

    for (int kt = 0; kt < BS_; kt += BK) {
        float4 vr = *(const float4*)&g_xr[(size_t)(p0 + pl) * C_ + nb * BS_ + kt + dq];
        float4 vi = *(const float4*)&g_xi[(size_t)(p0 + pl) * C_ + nb * BS_ + kt + dq];
        sXr[pl][dq] = vr.x; sXr[pl][dq+1] = vr.y; sXr[pl][dq+2] = vr.z; sXr[pl][dq+3] = vr.w;
        sXi[pl][dq] = vi.x; sXi[pl][dq+1] = vi.y; sXi[pl][dq+2] = vi.z; sXi[pl][dq+3] = vi.w;
        *(float4*)&sWr[dl][jq] = *(const float4*)&Wr[(size_t)(kt + dl) * BS_ + j0 + jq];
        *(float4*)&sWi[dl][jq] = *(const float4*)&Wi[(size_t)(kt + dl) * BS_ + j0 + jq];
        __syncthreads();
        #pragma unroll
        for (int kk = 0; kk < BK; kk++) {
            float xr[4], xi[4];
            #pragma unroll
            for (int i = 0; i < 4; i++) { xr[i] = sXr[ty*4+i][kk]; xi[i] = sXi[ty*4+i][kk]; }
            float4 wr = *(const float4*)&sWr[kk][tx * 4];
            float4 wi = *(const float4*)&sWi[kk][tx * 4];
            float wrv[4] = {wr.x, wr.y, wr.z, wr.w};
            float wiv[4] = {wi.x, wi.y, wi.z, wi.w};
            #pragma unroll
            for (int i = 0; i < 4; i++)
                #pragma unroll
                for (int j = 0; j < 4; j++) {
                    accR[i][j] += xr[i] * wrv[j] - xi[i] * wiv[j];
                    accI[i][j] += xr[i] * wiv[j] + xi[i] * wrv[j];
                }
        }
        __syncthreads();
    }
    const float* br = b1 + (size_t)nb * BS_;
    const float* bi = b1 + (size_t)(NBLK + nb) * BS_;
    #pragma unroll
    for (int i = 0; i < 4; i++) {
        size_t ro = (size_t)(p0 + ty*4 + i) * C_ + nb * BS_ + j0 + tx * 4;
        float4 vr, vi;
        float* pr = &vr.x; float* pi = &vi.x;
        #pragma unroll
        for (int j = 0; j < 4; j++) {
            int jj = j0 + tx*4 + j;
            float r = accR[i][j] + br[jj]; pr[j] = r > 0.f ? r : 0.f;
            float u = accI[i][j] + bi[jj]; pi[j] = u > 0.f ? u : 0.f;
        }
        *(float4*)&g_r1[ro] = vr;
        *(float4*)&g_i1[ro] = vi;
    }
}

// =====================================================================
// Kernel 5/6: layer2 (fp32 SIMT)
// =====================================================================
__global__ __launch_bounds__(256) void freq_l2(
    const float* __restrict__ w2, const float* __restrict__ b2, int phase)
{
    int p0 = blockIdx.x * 64;
    int j0 = blockIdx.y * 64;
    int nb = blockIdx.z;
    const float* A  = (phase == 0 ? g_r1 : g_r2);
    const float* Bm = g_i1;
    const float* Wa = w2 + (size_t)((phase == 0 ? 0 : NBLK) + nb) * BS_ * BS_;
    const float* Wb = w2 + (size_t)((phase == 0 ? NBLK : 0) + nb) * BS_ * BS_;
    const float* bias = b2 + (size_t)(phase == 0 ? 0 : NBLK) * BS_ + (size_t)nb * BS_;
    float* O = (phase == 0 ? g_r2 : g_i2);
    float sgn = (phase == 0) ? -1.f : 1.f;

    __shared__ float sA_[64][BK + 1], sB_[64][BK + 1];
    __shared__ float sWa[BK][64], sWb[BK][64];
    int tid = threadIdx.x;
    int tx = tid & 15, ty = tid >> 4;
    float acc[4][4] = {};

    int pl = tid >> 2, dq = (tid & 3) * 4;
    int dl = tid >> 4, jq = (tid & 15) * 4;

    for (int kt = 0; kt < BS_; kt += BK) {
        float4 va = *(const float4*)&A [(size_t)(p0 + pl) * C_ + nb * BS_ + kt + dq];
        float4 vb = *(const float4*)&Bm[(size_t)(p0 + pl) * C_ + nb * BS_ + kt + dq];
        sA_[pl][dq] = va.x; sA_[pl][dq+1] = va.y; sA_[pl][dq+2] = va.z; sA_[pl][dq+3] = va.w;
        sB_[pl][dq] = vb.x; sB_[pl][dq+1] = vb.y; sB_[pl][dq+2] = vb.z; sB_[pl][dq+3] = vb.w;
        *(float4*)&sWa[dl][jq] = *(const float4*)&Wa[(size_t)(kt + dl) * BS_ + j0 + jq];
        *(float4*)&sWb[dl][jq] = *(const float4*)&Wb[(size_t)(kt + dl) * BS_ + j0 + jq];
        __syncthreads();
        #pragma unroll
        for (int kk = 0; kk < BK; kk++) {
            float av[4], bv[4];
            #pragma unroll
            for (int i = 0; i < 4; i++) { av[i] = sA_[ty*4+i][kk]; bv[i] = sB_[ty*4+i][kk]; }
            float4 wa = *(const float4*)&sWa[kk][tx * 4];
            float4 wb = *(const float4*)&sWb[kk][tx * 4];
            float wav[4] = {wa.x, wa.y, wa.z, wa.w};
            float wbv[4] = {wb.x, wb.y, wb.z, wb.w};
            #pragma unroll
            for (int i = 0; i < 4; i++)
                #pragma unroll
                for (int j = 0; j < 4; j++)
                    acc[i][j] += av[i] * wav[j] + sgn * (bv[i] * wbv[j]);
        }
        __syncthreads();
    }
    #pragma unroll
    for (int i = 0; i < 4; i++) {
        size_t ro = (size_t)(p0 + ty*4 + i) * C_ + nb * BS_ + j0 + tx * 4;
        float4 v;
        float* pv = &v.x;
        #pragma unroll
        for (int j = 0; j < 4; j++) pv[j] = acc[i][j] + bias[j0 + tx*4 + j];
        *(float4*)&O[ro] = v;
    }
}

// =====================================================================
// Kernel 7: inverse DFT along H
// =====================================================================
__global__ __launch_bounds__(256) void fft_h_inv()
{
    int n0 = blockIdx.x * 128;
    int b  = blockIdx.y;
    __shared__ float sGr[H_][128], sGi[H_][128];
    __shared__ float sA[H_ * H_], sB[H_ * H_];
    int tid = threadIdx.x;

    for (int i = tid; i < H_ * H_; i += 256) { sA[i] = g_t2c[i]; sB[i] = g_t2s[i]; }
    const float* Gr = g_r2 + (size_t)b * H_ * NKC + n0;
    const float* Gi = g_i2 + (size_t)b * H_ * NKC + n0;
    for (int i = tid; i < H_ * 32; i += 256) {
        int m = i >> 5, q = i & 31;
        *(float4*)&sGr[m][q * 4] = *(const float4*)&Gr[(size_t)m * NKC + q * 4];
        *(float4*)&sGi[m][q * 4] = *(const float4*)&Gi[(size_t)m * NKC + q * 4];
    }
    __syncthreads();

    int quad = tid & 31, hg = tid >> 5;
    float fr[4][4] = {}, fi[4][4] = {};
    #pragma unroll 8
    for (int m = 0; m < H_; m++) {
        float4 gr = *(const float4*)&sGr[m][quad * 4];
        float4 gi = *(const float4*)&sGi[m][quad * 4];
        #pragma unroll
        for (int i = 0; i < 4; i++) {
            int h = hg * 4 + i;
            float a = sA[h * H_ + m], s = sB[h * H_ + m];
            fr[i][0] += a * gr.x + s * gi.x;  fi[i][0] += a * gi.x - s * gr.x;
            fr[i][1] += a * gr.y + s * gi.y;  fi[i][1] += a * gi.y - s * gr.y;
            fr[i][2] += a * gr.z + s * gi.z;  fi[i][2] += a * gi.z - s * gr.z;
            fr[i][3] += a * gr.w + s * gi.w;  fi[i][3] += a * gi.w - s * gr.w;
        }
    }
    float* Fr = g_xr + (size_t)b * H_ * NKC + n0;
    float* Fi = g_xi + (size_t)b * H_ * NKC + n0;
    #pragma unroll
    for (int i = 0; i < 4; i++) {
        int h = hg * 4 + i;
        *(float4*)&Fr[(size_t)h * NKC + quad * 4] = *(float4*)&fr[i][0];
        *(float4*)&Fi[(size_t)h * NKC + quad * 4] = *(float4*)&fi[i][0];
    }
}

// =====================================================================
// Kernel 8: inverse real DFT along W, accumulate into out
// =====================================================================
__global__ __launch_bounds__(256) void fft_w_inv(float* __restrict__ out)
{
    int bh = blockIdx.x;
    int c0 = blockIdx.y * 64;
    __shared__ float sFr[WH][64], sFi[WH][64];
    __shared__ float sTc[WH * W_], sTs[WH * W_];
    int tid = threadIdx.x;

    for (int i = tid; i < WH * W_; i += 256) { sTc[i] = g_t1c[i]; sTs[i] = g_t1s[i]; }
    const float* Fr = g_xr + (size_t)bh * WH * C_ + c0;
    const float* Fi = g_xi + (size_t)bh * WH * C_ + c0;
    for (int i = tid; i < WH * 16; i += 256) {
        int k = i >> 4, q = i & 15;
        float wt = (k == 0 || k == 32) ? SC_ORTHO : 2.f * SC_ORTHO;
        float4 vr = *(const float4*)&Fr[(size_t)k * C_ + q * 4];
        float4 vi = *(const float4*)&Fi[(size_t)k * C_ + q * 4];
        vr.x *= wt; vr.y *= wt; vr.z *= wt; vr.w *= wt;
        vi.x *= wt; vi.y *= wt; vi.z *= wt; vi.w *= wt;
        *(float4*)&sFr[k][q * 4] = vr;
        *(float4*)&sFi[k][q * 4] = vi;
    }
    __syncthreads();

    int quad = tid & 15, wg = tid >> 4;
    float acc[4][4] = {};
    #pragma unroll 8
    for (int k = 0; k < WH; k++) {
        float4 fr = *(const float4*)&sFr[k][quad * 4];
        float4 fi = *(const float4*)&sFi[k][quad * 4];
        #pragma unroll
        for (int i = 0; i < 4; i++) {
            int w = wg * 4 + i;
            float tc = sTc[k * W_ + w], ts = sTs[k * W_ + w];
            acc[i][0] += fr.x * tc + fi.x * ts;
            acc[i][1] += fr.y * tc + fi.y * ts;
            acc[i][2] += fr.z * tc + fi.z * ts;
            acc[i][3] += fr.w * tc + fi.w * ts;
        }
    }
    float* op = out + (size_t)bh * 64 * C_ + c0;
    #pragma unroll
    for (int i = 0; i < 4; i++) {
        int w = wg * 4 + i;
        float4 cur = *(float4*)&op[(size_t)w * C_ + quad * 4];
        cur.x += acc[i][0]; cur.y += acc[i][1];
        cur.z += acc[i][2]; cur.w += acc[i][3];
        *(float4*)&op[(size_t)w * C_ + quad * 4] = cur;
    }
}

// =====================================================================
extern "C" void kernel_launch(void* const* d_in, const int* in_sizes, int n_in,
                              void* d_out, int out_size)
{
    const float* x  = (const float*)d_in[0];
    const float* w1 = (const float*)d_in[1];
    const float* b1 = (const float*)d_in[2];
    const float* w2 = (const float*)d_in[3];
    const float* b2 = (const float*)d_in[4];
    const float* bw = (const float*)d_in[5];
    const float* bb = (const float*)d_in[6];
    float* out = (float*)d_out;

    init_tables<<<1, 256>>>();

    // tensor-core bias GEMM (split-bf16, 3 terms)
    bias_mma<<<dim3(C_ / TBN, NTOK / TBM), 256>>>(x, bw, bb, out);

    fft_w_fwd<<<dim3(B_ * H_, C_ / 64), 256>>>(x);
    fft_h_fwd<<<dim3(NKC / 128, B_), 256>>>();

    dim3 gFreq(P_ / 64, BS_ / 64, NBLK);
    freq_l1<<<gFreq, 256>>>(w1, b1);
    freq_l2<<<gFreq, 256>>>(w2, b2, 0);
    freq_l2<<<gFreq, 256>>>(w2, b2, 1);

    fft_h_inv<<<dim3(NKC / 128, B_), 256>>>();
    fft_w_inv<<<dim3(B_ * H_, C_ / 64), 256>>>(out);
}

// round 5
// speedup vs baseline: 3.1328x; 1.5797x over previous
#include <cuda_runtime.h>
#include <cuda_bf16.h>
#include <cstdint>

// ---------------- problem constants ----------------
#define B_  16
#define H_  32
#define W_  64
#define WH  33            // W/2+1
#define C_  768
#define NBLK 4
#define BS_ 192           // C/NBLK
#define P_  (B_*H_*WH)    // 16896 frequency positions
#define NKC (WH*C_)       // 25344
#define NTOK (B_*H_*W_)   // 32768 spatial tokens

#define SC_ORTHO 0.0220970869120796f   // 1/sqrt(2048)

// ---------------- scratch ----------------
__device__ float g_xr[(size_t)P_ * C_];
__device__ float g_xi[(size_t)P_ * C_];
__device__ float g_r1[(size_t)P_ * C_];
__device__ float g_i1[(size_t)P_ * C_];
__device__ float g_r2[(size_t)P_ * C_];
__device__ float g_i2[(size_t)P_ * C_];

// twiddle tables
__device__ float g_t1c[WH * W_];
__device__ float g_t1s[WH * W_];
__device__ float g_t2c[H_ * H_];
__device__ float g_t2s[H_ * H_];

// =====================================================================
// portable tensor-core helpers (mma.sync + ldmatrix)
// =====================================================================
__device__ __forceinline__ uint32_t smem_u32(const void* p) {
    uint32_t a;
    asm("{ .reg .u64 t; cvta.to.shared.u64 t, %1; cvt.u32.u64 %0, t; }" : "=r"(a) : "l"(p));
    return a;
}
__device__ __forceinline__ void mma_bf16(float* d, const uint32_t* a, const uint32_t* b) {
    asm volatile("mma.sync.aligned.m16n8k16.row.col.f32.bf16.bf16.f32 "
        "{%0,%1,%2,%3}, {%4,%5,%6,%7}, {%8,%9}, {%0,%1,%2,%3};"
        : "+f"(d[0]), "+f"(d[1]), "+f"(d[2]), "+f"(d[3])
        : "r"(a[0]), "r"(a[1]), "r"(a[2]), "r"(a[3]), "r"(b[0]), "r"(b[1]));
}
__device__ __forceinline__ void ldsm_x4(uint32_t* r, uint32_t addr) {
    asm volatile("ldmatrix.sync.aligned.m8n8.x4.shared.b16 {%0,%1,%2,%3}, [%4];"
        : "=r"(r[0]), "=r"(r[1]), "=r"(r[2]), "=r"(r[3]) : "r"(addr));
}
__device__ __forceinline__ void ldsm_x2(uint32_t* r, uint32_t addr) {
    asm volatile("ldmatrix.sync.aligned.m8n8.x2.shared.b16 {%0,%1}, [%2];"
        : "=r"(r[0]), "=r"(r[1]) : "r"(addr));
}
__device__ __forceinline__ void ldsm_x2_t(uint32_t* r, uint32_t addr) {
    asm volatile("ldmatrix.sync.aligned.m8n8.x2.trans.shared.b16 {%0,%1}, [%2];"
        : "=r"(r[0]), "=r"(r[1]) : "r"(addr));
}
__device__ __forceinline__ void split4(float4 v, __nv_bfloat16* h, __nv_bfloat16* l) {
    float a[4] = {v.x, v.y, v.z, v.w};
    #pragma unroll
    for (int q = 0; q < 4; q++) {
        h[q] = __float2bfloat16(a[q]);
        l[q] = __float2bfloat16(a[q] - __bfloat162float(h[q]));
    }
}

// =====================================================================
__global__ void init_tables()
{
    int tid = threadIdx.x;
    for (int i = tid; i < WH * W_; i += blockDim.x) {
        int k = i / W_, w = i % W_;
        float s, c;
        sincospif(-(float)(k * w) / 32.0f, &s, &c);
        g_t1c[i] = c; g_t1s[i] = s;
    }
    for (int i = tid; i < H_ * H_; i += blockDim.x) {
        int m = i / H_, h = i % H_;
        float s, c;
        sincospif(-(float)(m * h) / 16.0f, &s, &c);
        g_t2c[i] = c; g_t2s[i] = s;
    }
}

// =====================================================================
// bias GEMM via mma.sync bf16 split-precision (validated R4)
// =====================================================================
#define TBM 128
#define TBN 128
#define TBK 32
#define APAD 8
#define KPAD (TBK + APAD)

__global__ __launch_bounds__(256) void bias_mma(
    const float* __restrict__ X, const float* __restrict__ Wm,
    const float* __restrict__ bb, float* __restrict__ out)
{
    __shared__ __align__(16) __nv_bfloat16 sAhi[TBM][KPAD];
    __shared__ __align__(16) __nv_bfloat16 sAlo[TBM][KPAD];
    __shared__ __align__(16) __nv_bfloat16 sBhi[TBN][KPAD];
    __shared__ __align__(16) __nv_bfloat16 sBlo[TBN][KPAD];

    int tid = threadIdx.x;
    int wid = tid >> 5, lane = tid & 31;
    int wm = wid >> 2, wn = wid & 3;
    int m0 = blockIdx.y * TBM, n0 = blockIdx.x * TBN;

    float acc[4][4][4] = {};

    int aRow = lane & 15, aKoff = (lane >> 4) * 8;
    int bRow = lane & 7,  bKoff = ((lane >> 3) & 1) * 8;

    for (int kt = 0; kt < C_; kt += TBK) {
        #pragma unroll
        for (int it = 0; it < 4; it++) {
            int lin = tid + 256 * it;
            int r = lin >> 3, cq = (lin & 7) * 4;
            float4 va = *(const float4*)&X [(size_t)(m0 + r) * C_ + kt + cq];
            float4 vb = *(const float4*)&Wm[(size_t)(n0 + r) * C_ + kt + cq];
            __nv_bfloat16 ah[4], al[4], bh[4], bl[4];
            split4(va, ah, al);
            split4(vb, bh, bl);
            *(uint2*)&sAhi[r][cq] = *(uint2*)ah;
            *(uint2*)&sAlo[r][cq] = *(uint2*)al;
            *(uint2*)&sBhi[r][cq] = *(uint2*)bh;
            *(uint2*)&sBlo[r][cq] = *(uint2*)bl;
        }
        __syncthreads();

        #pragma unroll
        for (int s = 0; s < 2; s++) {
            int k0 = s * 16;
            uint32_t a_hi[4][4], a_lo[4][4], b_hi[4][2], b_lo[4][2];
            #pragma unroll
            for (int i = 0; i < 4; i++) {
                int row = wm * 64 + i * 16 + aRow;
                ldsm_x4(a_hi[i], smem_u32(&sAhi[row][k0 + aKoff]));
                ldsm_x4(a_lo[i], smem_u32(&sAlo[row][k0 + aKoff]));
            }
            #pragma unroll
            for (int j = 0; j < 4; j++) {
                int row = wn * 32 + j * 8 + bRow;
                ldsm_x2(b_hi[j], smem_u32(&sBhi[row][k0 + bKoff]));
                ldsm_x2(b_lo[j], smem_u32(&sBlo[row][k0 + bKoff]));
            }
            #pragma unroll
            for (int i = 0; i < 4; i++)
                #pragma unroll
                for (int j = 0; j < 4; j++) {
                    mma_bf16(acc[i][j], a_hi[i], b_hi[j]);
                    mma_bf16(acc[i][j], a_hi[i], b_lo[j]);
                    mma_bf16(acc[i][j], a_lo[i], b_hi[j]);
                }
        }
        __syncthreads();
    }

    int group = lane >> 2, qid = lane & 3;
    #pragma unroll
    for (int i = 0; i < 4; i++) {
        #pragma unroll
        for (int j = 0; j < 4; j++) {
            int col = n0 + wn * 32 + j * 8 + qid * 2;
            float b0 = bb[col], b1 = bb[col + 1];
            int r0 = m0 + wm * 64 + i * 16 + group;
            float2 v0 = {acc[i][j][0] + b0, acc[i][j][1] + b1};
            float2 v1 = {acc[i][j][2] + b0, acc[i][j][3] + b1};
            *(float2*)&out[(size_t)r0 * C_ + col]       = v0;
            *(float2*)&out[(size_t)(r0 + 8) * C_ + col] = v1;
        }
    }
}

// =====================================================================
// freq MLP via mma.sync: tiles 128(P) x 64(j) x 16(k), 8 warps (64x16)
// weights [d][j] loaded into [k][n] smem tiles, B frags via ldmatrix.trans
// =====================================================================
#define FM 128
#define FN 64
#define FK 16
#define XPAD (FK + 8)     // 24 halfs = 48B stride (conflict-free)
#define WPAD (FN + 8)     // 72 halfs = 144B stride (conflict-free)

// ---- layer1: r1 = relu(xr@Wr - xi@Wi + br); i1 = relu(xr@Wi + xi@Wr + bi)
__global__ __launch_bounds__(256) void freq_l1_mma(
    const float* __restrict__ w1, const float* __restrict__ b1)
{
    __shared__ __align__(16) __nv_bfloat16 sXrh[FM][XPAD], sXrl[FM][XPAD];
    __shared__ __align__(16) __nv_bfloat16 sXih[FM][XPAD], sXil[FM][XPAD];
    __shared__ __align__(16) __nv_bfloat16 sWrh[FK][WPAD], sWrl[FK][WPAD];
    __shared__ __align__(16) __nv_bfloat16 sWih[FK][WPAD], sWil[FK][WPAD];
    __shared__ __align__(16) __nv_bfloat16 sWnh[FK][WPAD], sWnl[FK][WPAD];  // -Wi

    int tid = threadIdx.x, wid = tid >> 5, lane = tid & 31;
    int wm = wid >> 2, wn = wid & 3;
    int p0 = blockIdx.x * FM, j0 = blockIdx.y * FN, nb = blockIdx.z;
    const float* Wr = w1 + (size_t)nb * BS_ * BS_;
    const float* Wi = w1 + (size_t)(NBLK + nb) * BS_ * BS_;

    float accR[4][2][4] = {}, accI[4][2][4] = {};
    int aRow = lane & 15, aK = (lane >> 4) * 8;
    int bKrow = lane & 15;

    for (int kt = 0; kt < BS_; kt += FK) {
        // X fill: 128 rows x 4 quads, 2 iters
        #pragma unroll
        for (int it = 0; it < 2; it++) {
            int lin = tid + 256 * it;
            int r = lin >> 2, cq = (lin & 3) * 4;
            float4 vr = *(const float4*)&g_xr[(size_t)(p0 + r) * C_ + nb * BS_ + kt + cq];
            float4 vi = *(const float4*)&g_xi[(size_t)(p0 + r) * C_ + nb * BS_ + kt + cq];
            __nv_bfloat16 h[4], l[4];
            split4(vr, h, l);
            *(uint2*)&sXrh[r][cq] = *(uint2*)h;
            *(uint2*)&sXrl[r][cq] = *(uint2*)l;
            split4(vi, h, l);
            *(uint2*)&sXih[r][cq] = *(uint2*)h;
            *(uint2*)&sXil[r][cq] = *(uint2*)l;
        }
        // W fill: 16 rows x 16 quads, 1 iter
        {
            int d = tid >> 4, jq = (tid & 15) * 4;
            float4 vr = *(const float4*)&Wr[(size_t)(kt + d) * BS_ + j0 + jq];
            float4 vi = *(const float4*)&Wi[(size_t)(kt + d) * BS_ + j0 + jq];
            __nv_bfloat16 h[4], l[4];
            split4(vr, h, l);
            *(uint2*)&sWrh[d][jq] = *(uint2*)h;
            *(uint2*)&sWrl[d][jq] = *(uint2*)l;
            split4(vi, h, l);
            *(uint2*)&sWih[d][jq] = *(uint2*)h;
            *(uint2*)&sWil[d][jq] = *(uint2*)l;
            float4 vn = {-vi.x, -vi.y, -vi.z, -vi.w};
            split4(vn, h, l);
            *(uint2*)&sWnh[d][jq] = *(uint2*)h;
            *(uint2*)&sWnl[d][jq] = *(uint2*)l;
        }
        __syncthreads();

        uint32_t axrh[4][4], axrl[4][4], axih[4][4], axil[4][4];
        #pragma unroll
        for (int i = 0; i < 4; i++) {
            int row = wm * 64 + i * 16 + aRow;
            ldsm_x4(axrh[i], smem_u32(&sXrh[row][aK]));
            ldsm_x4(axrl[i], smem_u32(&sXrl[row][aK]));
            ldsm_x4(axih[i], smem_u32(&sXih[row][aK]));
            ldsm_x4(axil[i], smem_u32(&sXil[row][aK]));
        }
        uint32_t bwrh[2][2], bwrl[2][2], bwih[2][2], bwil[2][2], bwnh[2][2], bwnl[2][2];
        #pragma unroll
        for (int j = 0; j < 2; j++) {
            int nf = wn * 16 + j * 8;
            ldsm_x2_t(bwrh[j], smem_u32(&sWrh[bKrow][nf]));
            ldsm_x2_t(bwrl[j], smem_u32(&sWrl[bKrow][nf]));
            ldsm_x2_t(bwih[j], smem_u32(&sWih[bKrow][nf]));
            ldsm_x2_t(bwil[j], smem_u32(&sWil[bKrow][nf]));
            ldsm_x2_t(bwnh[j], smem_u32(&sWnh[bKrow][nf]));
            ldsm_x2_t(bwnl[j], smem_u32(&sWnl[bKrow][nf]));
        }
        #pragma unroll
        for (int i = 0; i < 4; i++)
            #pragma unroll
            for (int j = 0; j < 2; j++) {
                // accR += Xr*Wr + Xi*(-Wi)
                mma_bf16(accR[i][j], axrh[i], bwrh[j]);
                mma_bf16(accR[i][j], axrh[i], bwrl[j]);
                mma_bf16(accR[i][j], axrl[i], bwrh[j]);
                mma_bf16(accR[i][j], axih[i], bwnh[j]);
                mma_bf16(accR[i][j], axih[i], bwnl[j]);
                mma_bf16(accR[i][j], axil[i], bwnh[j]);
                // accI += Xr*Wi + Xi*Wr
                mma_bf16(accI[i][j], axrh[i], bwih[j]);
                mma_bf16(accI[i][j], axrh[i], bwil[j]);
                mma_bf16(accI[i][j], axrl[i], bwih[j]);
                mma_bf16(accI[i][j], axih[i], bwrh[j]);
                mma_bf16(accI[i][j], axih[i], bwrl[j]);
                mma_bf16(accI[i][j], axil[i], bwrh[j]);
            }
        __syncthreads();
    }

    const float* br = b1 + (size_t)nb * BS_;
    const float* bi = b1 + (size_t)(NBLK + nb) * BS_;
    int g = lane >> 2, q = (lane & 3) * 2;
    #pragma unroll
    for (int i = 0; i < 4; i++)
        #pragma unroll
        for (int j = 0; j < 2; j++) {
            int col = j0 + wn * 16 + j * 8 + q;
            float br0 = br[col], br1 = br[col + 1];
            float bi0 = bi[col], bi1 = bi[col + 1];
            int r0 = p0 + wm * 64 + i * 16 + g;
            size_t o0 = (size_t)r0 * C_ + nb * BS_ + col;
            size_t o1 = (size_t)(r0 + 8) * C_ + nb * BS_ + col;
            float2 vr0 = {fmaxf(accR[i][j][0] + br0, 0.f), fmaxf(accR[i][j][1] + br1, 0.f)};
            float2 vr1 = {fmaxf(accR[i][j][2] + br0, 0.f), fmaxf(accR[i][j][3] + br1, 0.f)};
            float2 vi0 = {fmaxf(accI[i][j][0] + bi0, 0.f), fmaxf(accI[i][j][1] + bi1, 0.f)};
            float2 vi1 = {fmaxf(accI[i][j][2] + bi0, 0.f), fmaxf(accI[i][j][3] + bi1, 0.f)};
            *(float2*)&g_r1[o0] = vr0;
            *(float2*)&g_r1[o1] = vr1;
            *(float2*)&g_i1[o0] = vi0;
            *(float2*)&g_i1[o1] = vi1;
        }
}

// ---- layer2: phase0: r2 = r1@W2r - i1@W2i + b2r
//              phase1: i2 = r2@W2i + i1@W2r + b2i
__global__ __launch_bounds__(256) void freq_l2_mma(
    const float* __restrict__ w2, const float* __restrict__ b2, int phase)
{
    __shared__ __align__(16) __nv_bfloat16 sAh[FM][XPAD], sAl[FM][XPAD];
    __shared__ __align__(16) __nv_bfloat16 sBh[FM][XPAD], sBl[FM][XPAD];
    __shared__ __align__(16) __nv_bfloat16 sWah[FK][WPAD], sWal[FK][WPAD];
    __shared__ __align__(16) __nv_bfloat16 sWbh[FK][WPAD], sWbl[FK][WPAD];

    int tid = threadIdx.x, wid = tid >> 5, lane = tid & 31;
    int wm = wid >> 2, wn = wid & 3;
    int p0 = blockIdx.x * FM, j0 = blockIdx.y * FN, nb = blockIdx.z;

    const float* A  = (phase == 0 ? g_r1 : g_r2);
    const float* Bm = g_i1;
    const float* Wa = w2 + (size_t)((phase == 0 ? 0 : NBLK) + nb) * BS_ * BS_;
    const float* Wb = w2 + (size_t)((phase == 0 ? NBLK : 0) + nb) * BS_ * BS_;
    const float* bias = b2 + (size_t)(phase == 0 ? 0 : NBLK) * BS_ + (size_t)nb * BS_;
    float* O = (phase == 0 ? g_r2 : g_i2);
    float sgn = (phase == 0) ? -1.f : 1.f;

    float acc[4][2][4] = {};
    int aRow = lane & 15, aK = (lane >> 4) * 8;
    int bKrow = lane & 15;

    for (int kt = 0; kt < BS_; kt += FK) {
        #pragma unroll
        for (int it = 0; it < 2; it++) {
            int lin = tid + 256 * it;
            int r = lin >> 2, cq = (lin & 3) * 4;
            float4 va = *(const float4*)&A [(size_t)(p0 + r) * C_ + nb * BS_ + kt + cq];
            float4 vb = *(const float4*)&Bm[(size_t)(p0 + r) * C_ + nb * BS_ + kt + cq];
            __nv_bfloat16 h[4], l[4];
            split4(va, h, l);
            *(uint2*)&sAh[r][cq] = *(uint2*)h;
            *(uint2*)&sAl[r][cq] = *(uint2*)l;
            split4(vb, h, l);
            *(uint2*)&sBh[r][cq] = *(uint2*)h;
            *(uint2*)&sBl[r][cq] = *(uint2*)l;
        }
        {
            int d = tid >> 4, jq = (tid & 15) * 4;
            float4 va = *(const float4*)&Wa[(size_t)(kt + d) * BS_ + j0 + jq];
            float4 vb = *(const float4*)&Wb[(size_t)(kt + d) * BS_ + j0 + jq];
            vb.x *= sgn; vb.y *= sgn; vb.z *= sgn; vb.w *= sgn;
            __nv_bfloat16 h[4], l[4];
            split4(va, h, l);
            *(uint2*)&sWah[d][jq] = *(uint2*)h;
            *(uint2*)&sWal[d][jq] = *(uint2*)l;
            split4(vb, h, l);
            *(uint2*)&sWbh[d][jq] = *(uint2*)h;
            *(uint2*)&sWbl[d][jq] = *(uint2*)l;
        }
        __syncthreads();

        uint32_t aah[4][4], aal[4][4], abh[4][4], abl[4][4];
        #pragma unroll
        for (int i = 0; i < 4; i++) {
            int row = wm * 64 + i * 16 + aRow;
            ldsm_x4(aah[i], smem_u32(&sAh[row][aK]));
            ldsm_x4(aal[i], smem_u32(&sAl[row][aK]));
            ldsm_x4(abh[i], smem_u32(&sBh[row][aK]));
            ldsm_x4(abl[i], smem_u32(&sBl[row][aK]));
        }
        uint32_t bah[2][2], bal[2][2], bbh[2][2], bbl[2][2];
        #pragma unroll
        for (int j = 0; j < 2; j++) {
            int nf = wn * 16 + j * 8;
            ldsm_x2_t(bah[j], smem_u32(&sWah[bKrow][nf]));
            ldsm_x2_t(bal[j], smem_u32(&sWal[bKrow][nf]));
            ldsm_x2_t(bbh[j], smem_u32(&sWbh[bKrow][nf]));
            ldsm_x2_t(bbl[j], smem_u32(&sWbl[bKrow][nf]));
        }
        #pragma unroll
        for (int i = 0; i < 4; i++)
            #pragma unroll
            for (int j = 0; j < 2; j++) {
                mma_bf16(acc[i][j], aah[i], bah[j]);
                mma_bf16(acc[i][j], aah[i], bal[j]);
                mma_bf16(acc[i][j], aal[i], bah[j]);
                mma_bf16(acc[i][j], abh[i], bbh[j]);
                mma_bf16(acc[i][j], abh[i], bbl[j]);
                mma_bf16(acc[i][j], abl[i], bbh[j]);
            }
        __syncthreads();
    }

    int g = lane >> 2, q = (lane & 3) * 2;
    #pragma unroll
    for (int i = 0; i < 4; i++)
        #pragma unroll
        for (int j = 0; j < 2; j++) {
            int col = j0 + wn * 16 + j * 8 + q;
            float b0 = bias[col], b1 = bias[col + 1];
            int r0 = p0 + wm * 64 + i * 16 + g;
            float2 v0 = {acc[i][j][0] + b0, acc[i][j][1] + b1};
            float2 v1 = {acc[i][j][2] + b0, acc[i][j][3] + b1};
            *(float2*)&O[(size_t)r0 * C_ + nb * BS_ + col]       = v0;
            *(float2*)&O[(size_t)(r0 + 8) * C_ + nb * BS_ + col] = v1;
        }
}

// =====================================================================
// Kernel 2: forward DFT along W.  x -> Y (g_r1/g_i1)
// =====================================================================
__global__ __launch_bounds__(256) void fft_w_fwd(const float* __restrict__ X)
{
    int bh = blockIdx.x;
    int c0 = blockIdx.y * 64;
    __shared__ float sX[W_][64];
    __shared__ float sTc[WH * W_];
    __shared__ float sTs[WH * W_];
    int tid = threadIdx.x;

    for (int i = tid; i < WH * W_; i += 256) { sTc[i] = g_t1c[i]; sTs[i] = g_t1s[i]; }
    const float* xp = X + (size_t)bh * 64 * C_ + c0;
    for (int i = tid; i < W_ * 16; i += 256) {
        int w = i >> 4, q = i & 15;
        *(float4*)&sX[w][q * 4] = *(const float4*)&xp[(size_t)w * C_ + q * 4];
    }
    __syncthreads();

    int quad = tid & 15, kg = tid >> 4;
    float ar[3][4] = {}, ai[3][4] = {};
    #pragma unroll 8
    for (int w = 0; w < W_; w++) {
        float4 v = *(const float4*)&sX[w][quad * 4];
        #pragma unroll
        for (int i = 0; i < 3; i++) {
            int k = kg + 16 * i;
            if (k < WH) {
                float tc = sTc[k * W_ + w], ts = sTs[k * W_ + w];
                ar[i][0] += v.x * tc; ai[i][0] += v.x * ts;
                ar[i][1] += v.y * tc; ai[i][1] += v.y * ts;
                ar[i][2] += v.z * tc; ai[i][2] += v.z * ts;
                ar[i][3] += v.w * tc; ai[i][3] += v.w * ts;
            }
        }
    }
    #pragma unroll
    for (int i = 0; i < 3; i++) {
        int k = kg + 16 * i;
        if (k < WH) {
            size_t o = ((size_t)bh * WH + k) * C_ + c0 + quad * 4;
            *(float4*)&g_r1[o] = *(float4*)&ar[i][0];
            *(float4*)&g_i1[o] = *(float4*)&ai[i][0];
        }
    }
}

// =====================================================================
// Kernel 3: forward DFT along H (complex), ortho scaled. Y -> g_xr/g_xi
// =====================================================================
__global__ __launch_bounds__(256) void fft_h_fwd()
{
    int n0 = blockIdx.x * 128;
    int b  = blockIdx.y;
    __shared__ float sYr[H_][128], sYi[H_][128];
    __shared__ float sA[H_ * H_], sB[H_ * H_];
    int tid = threadIdx.x;

    for (int i = tid; i < H_ * H_; i += 256) { sA[i] = g_t2c[i]; sB[i] = g_t2s[i]; }
    const float* Yr = g_r1 + (size_t)b * H_ * NKC + n0;
    const float* Yi = g_i1 + (size_t)b * H_ * NKC + n0;
    for (int i = tid; i < H_ * 32; i += 256) {
        int h = i >> 5, q = i & 31;
        *(float4*)&sYr[h][q * 4] = *(const float4*)&Yr[(size_t)h * NKC + q * 4];
        *(float4*)&sYi[h][q * 4] = *(const float4*)&Yi[(size_t)h * NKC + q * 4];
    }
    __syncthreads();

    int quad = tid & 31, mg = tid >> 5;
    float zr[4][4] = {}, zi[4][4] = {};
    #pragma unroll 8
    for (int h = 0; h < H_; h++) {
        float4 yr = *(const float4*)&sYr[h][quad * 4];
        float4 yi = *(const float4*)&sYi[h][quad * 4];
        #pragma unroll
        for (int i = 0; i < 4; i++) {
            int m = mg * 4 + i;
            float a = sA[m * H_ + h], s = sB[m * H_ + h];
            zr[i][0] += a * yr.x - s * yi.x;  zi[i][0] += a * yi.x + s * yr.x;
            zr[i][1] += a * yr.y - s * yi.y;  zi[i][1] += a * yi.y + s * yr.y;
            zr[i][2] += a * yr.z - s * yi.z;  zi[i][2] += a * yi.z + s * yr.z;
            zr[i][3] += a * yr.w - s * yi.w;  zi[i][3] += a * yi.w + s * yr.w;
        }
    }
    float* Zr = g_xr + (size_t)b * H_ * NKC + n0;
    float* Zi = g_xi + (size_t)b * H_ * NKC + n0;
    #pragma unroll
    for (int i = 0; i < 4; i++) {
        int m = mg * 4 + i;
        float4 vr, vi;
        vr.x = zr[i][0] * SC_ORTHO; vr.y = zr[i][1] * SC_ORTHO;
        vr.z = zr[i][2] * SC_ORTHO; vr.w = zr[i][3] * SC_ORTHO;
        vi.x = zi[i][0] * SC_ORTHO; vi.y = zi[i][1] * SC_ORTHO;
        vi.z = zi[i][2] * SC_ORTHO; vi.w = zi[i][3] * SC_ORTHO;
        *(float4*)&Zr[(size_t)m * NKC + quad * 4] = vr;
        *(float4*)&Zi[(size_t)m * NKC + quad * 4] = vi;
    }
}

// =====================================================================
// Kernel 7: inverse DFT along H
// =====================================================================
__global__ __launch_bounds__(256) void fft_h_inv()
{
    int n0 = blockIdx.x * 128;
    int b  = blockIdx.y;
    __shared__ float sGr[H_][128], sGi[H_][128];
    __shared__ float sA[H_ * H_], sB[H_ * H_];
    int tid = threadIdx.x;

    for (int i = tid; i < H_ * H_; i += 256) { sA[i] = g_t2c[i]; sB[i] = g_t2s[i]; }
    const float* Gr = g_r2 + (size_t)b * H_ * NKC + n0;
    const float* Gi = g_i2 + (size_t)b * H_ * NKC + n0;
    for (int i = tid; i < H_ * 32; i += 256) {
        int m = i >> 5, q = i & 31;
        *(float4*)&sGr[m][q * 4] = *(const float4*)&Gr[(size_t)m * NKC + q * 4];
        *(float4*)&sGi[m][q * 4] = *(const float4*)&Gi[(size_t)m * NKC + q * 4];
    }
    __syncthreads();

    int quad = tid & 31, hg = tid >> 5;
    float fr[4][4] = {}, fi[4][4] = {};
    #pragma unroll 8
    for (int m = 0; m < H_; m++) {
        float4 gr = *(const float4*)&sGr[m][quad * 4];
        float4 gi = *(const float4*)&sGi[m][quad * 4];
        #pragma unroll
        for (int i = 0; i < 4; i++) {
            int h = hg * 4 + i;
            float a = sA[h * H_ + m], s = sB[h * H_ + m];
            fr[i][0] += a * gr.x + s * gi.x;  fi[i][0] += a * gi.x - s * gr.x;
            fr[i][1] += a * gr.y + s * gi.y;  fi[i][1] += a * gi.y - s * gr.y;
            fr[i][2] += a * gr.z + s * gi.z;  fi[i][2] += a * gi.z - s * gr.z;
            fr[i][3] += a * gr.w + s * gi.w;  fi[i][3] += a * gi.w - s * gr.w;
        }
    }
    float* Fr = g_xr + (size_t)b * H_ * NKC + n0;
    float* Fi = g_xi + (size_t)b * H_ * NKC + n0;
    #pragma unroll
    for (int i = 0; i < 4; i++) {
        int h = hg * 4 + i;
        *(float4*)&Fr[(size_t)h * NKC + quad * 4] = *(float4*)&fr[i][0];
        *(float4*)&Fi[(size_t)h * NKC + quad * 4] = *(float4*)&fi[i][0];
    }
}

// =====================================================================
// Kernel 8: inverse real DFT along W, accumulate into out
// =====================================================================
__global__ __launch_bounds__(256) void fft_w_inv(float* __restrict__ out)
{
    int bh = blockIdx.x;
    int c0 = blockIdx.y * 64;
    __shared__ float sFr[WH][64], sFi[WH][64];
    __shared__ float sTc[WH * W_], sTs[WH * W_];
    int tid = threadIdx.x;

    for (int i = tid; i < WH * W_; i += 256) { sTc[i] = g_t1c[i]; sTs[i] = g_t1s[i]; }
    const float* Fr = g_xr + (size_t)bh * WH * C_ + c0;
    const float* Fi = g_xi + (size_t)bh * WH * C_ + c0;
    for (int i = tid; i < WH * 16; i += 256) {
        int k = i >> 4, q = i & 15;
        float wt = (k == 0 || k == 32) ? SC_ORTHO : 2.f * SC_ORTHO;
        float4 vr = *(const float4*)&Fr[(size_t)k * C_ + q * 4];
        float4 vi = *(const float4*)&Fi[(size_t)k * C_ + q * 4];
        vr.x *= wt; vr.y *= wt; vr.z *= wt; vr.w *= wt;
        vi.x *= wt; vi.y *= wt; vi.z *= wt; vi.w *= wt;
        *(float4*)&sFr[k][q * 4] = vr;
        *(float4*)&sFi[k][q * 4] = vi;
    }
    __syncthreads();

    int quad = tid & 15, wg = tid >> 4;
    float acc[4][4] = {};
    #pragma unroll 8
    for (int k = 0; k < WH; k++) {
        float4 fr = *(const float4*)&sFr[k][quad * 4];
        float4 fi = *(const float4*)&sFi[k][quad * 4];
        #pragma unroll
        for (int i = 0; i < 4; i++) {
            int w = wg * 4 + i;
            float tc = sTc[k * W_ + w], ts = sTs[k * W_ + w];
            acc[i][0] += fr.x * tc + fi.x * ts;
            acc[i][1] += fr.y * tc + fi.y * ts;
            acc[i][2] += fr.z * tc + fi.z * ts;
            acc[i][3] += fr.w * tc + fi.w * ts;
        }
    }
    float* op = out + (size_t)bh * 64 * C_ + c0;
    #pragma unroll
    for (int i = 0; i < 4; i++) {
        int w = wg * 4 + i;
        float4 cur = *(float4*)&op[(size_t)w * C_ + quad * 4];
        cur.x += acc[i][0]; cur.y += acc[i][1];
        cur.z += acc[i][2]; cur.w += acc[i][3];
        *(float4*)&op[(size_t)w * C_ + quad * 4] = cur;
    }
}

// =====================================================================
extern "C" void kernel_launch(void* const* d_in, const int* in_sizes, int n_in,
                              void* d_out, int out_size)
{
    const float* x  = (const float*)d_in[0];
    const float* w1 = (const float*)d_in[1];
    const float* b1 = (const float*)d_in[2];
    const float* w2 = (const float*)d_in[3];
    const float* b2 = (const float*)d_in[4];
    const float* bw = (const float*)d_in[5];
    const float* bb = (const float*)d_in[6];
    float* out = (float*)d_out;

    init_tables<<<1, 256>>>();

    bias_mma<<<dim3(C_ / TBN, NTOK / TBM), 256>>>(x, bw, bb, out);

    fft_w_fwd<<<dim3(B_ * H_, C_ / 64), 256>>>(x);
    fft_h_fwd<<<dim3(NKC / 128, B_), 256>>>();

    dim3 gFreq(P_ / FM, BS_ / FN, NBLK);    // (132, 3, 4)
    freq_l1_mma<<<gFreq, 256>>>(w1, b1);
    freq_l2_mma<<<gFreq, 256>>>(w2, b2, 0);
    freq_l2_mma<<<gFreq, 256>>>(w2, b2, 1);

    fft_h_inv<<<dim3(NKC / 128, B_), 256>>>();
    fft_w_inv<<<dim3(B_ * H_, C_ / 64), 256>>>(out);
}

// round 7
// speedup vs baseline: 3.8342x; 1.2239x over previous
#include <cuda_runtime.h>
#include <cuda_bf16.h>
#include <cstdint>

// ---------------- problem constants ----------------
#define B_  16
#define H_  32
#define W_  64
#define WH  33            // W/2+1
#define C_  768
#define NBLK 4
#define BS_ 192           // C/NBLK
#define P_  (B_*H_*WH)    // 16896 frequency positions
#define NKC (WH*C_)       // 25344
#define NTOK (B_*H_*W_)   // 32768 spatial tokens

#define SC_ORTHO 0.0220970869120796f   // 1/sqrt(2048)

// ---------------- scratch ----------------
__device__ float g_xr[(size_t)P_ * C_];
__device__ float g_xi[(size_t)P_ * C_];
__device__ float g_r1[(size_t)P_ * C_];
__device__ float g_i1[(size_t)P_ * C_];
__device__ float g_r2[(size_t)P_ * C_];
__device__ float g_i2[(size_t)P_ * C_];

// twiddle tables (w_inv only)
__device__ float g_t1c[WH * W_];
__device__ float g_t1s[WH * W_];

// pre-split 64x64 DFT operator matrices (bf16 hi/lo)
__device__ __nv_bfloat16 g_Ahf_h[4096], g_Ahf_l[4096];   // H fwd (scaled)
__device__ __nv_bfloat16 g_Ahi_h[4096], g_Ahi_l[4096];   // H inv
__device__ __nv_bfloat16 g_Awf_h[4096], g_Awf_l[4096];   // W fwd (k=0..31)

// =====================================================================
// portable tensor-core helpers (mma.sync + ldmatrix)
// =====================================================================
__device__ __forceinline__ uint32_t smem_u32(const void* p) {
    uint32_t a;
    asm("{ .reg .u64 t; cvta.to.shared.u64 t, %1; cvt.u32.u64 %0, t; }" : "=r"(a) : "l"(p));
    return a;
}
__device__ __forceinline__ void mma_bf16(float* d, const uint32_t* a, const uint32_t* b) {
    asm volatile("mma.sync.aligned.m16n8k16.row.col.f32.bf16.bf16.f32 "
        "{%0,%1,%2,%3}, {%4,%5,%6,%7}, {%8,%9}, {%0,%1,%2,%3};"
        : "+f"(d[0]), "+f"(d[1]), "+f"(d[2]), "+f"(d[3])
        : "r"(a[0]), "r"(a[1]), "r"(a[2]), "r"(a[3]), "r"(b[0]), "r"(b[1]));
}
__device__ __forceinline__ void ldsm_x4(uint32_t* r, uint32_t addr) {
    asm volatile("ldmatrix.sync.aligned.m8n8.x4.shared.b16 {%0,%1,%2,%3}, [%4];"
        : "=r"(r[0]), "=r"(r[1]), "=r"(r[2]), "=r"(r[3]) : "r"(addr));
}
__device__ __forceinline__ void ldsm_x2(uint32_t* r, uint32_t addr) {
    asm volatile("ldmatrix.sync.aligned.m8n8.x2.shared.b16 {%0,%1}, [%2];"
        : "=r"(r[0]), "=r"(r[1]) : "r"(addr));
}
__device__ __forceinline__ void ldsm_x2_t(uint32_t* r, uint32_t addr) {
    asm volatile("ldmatrix.sync.aligned.m8n8.x2.trans.shared.b16 {%0,%1}, [%2];"
        : "=r"(r[0]), "=r"(r[1]) : "r"(addr));
}
__device__ __forceinline__ void split4(float4 v, __nv_bfloat16* h, __nv_bfloat16* l) {
    float a[4] = {v.x, v.y, v.z, v.w};
    #pragma unroll
    for (int q = 0; q < 4; q++) {
        h[q] = __float2bfloat16(a[q]);
        l[q] = __float2bfloat16(a[q] - __bfloat162float(h[q]));
    }
}
__device__ __forceinline__ void split1(float v, __nv_bfloat16& h, __nv_bfloat16& l) {
    h = __float2bfloat16(v);
    l = __float2bfloat16(v - __bfloat162float(h));
}

// =====================================================================
__global__ void init_tables()
{
    int tid = threadIdx.x;
    for (int i = tid; i < WH * W_; i += blockDim.x) {
        int k = i / W_, w = i % W_;
        float s, c;
        sincospif(-(float)(k * w) / 32.0f, &s, &c);
        g_t1c[i] = c; g_t1s[i] = s;
    }
    for (int i = tid; i < 4096; i += blockDim.x) {
        int r = i >> 6, q = i & 63;
        // ---- H forward: [Zr;Zi] = A @ [Yr;Yi], scaled
        {
            float s, c;
            sincospif((float)((r & 31) * (q & 31)) / 16.0f, &s, &c);
            float v;
            if (r < 32)  v = (q < 32) ? c : s;
            else         v = (q < 32) ? -s : c;
            split1(v * SC_ORTHO, g_Ahf_h[i], g_Ahf_l[i]);
        }
        // ---- H inverse: [Fr;Fi] = A @ [Gr;Gi]
        {
            float s, c;
            sincospif((float)((r & 31) * (q & 31)) / 16.0f, &s, &c);
            float v;
            if (r < 32)  v = (q < 32) ? c : -s;
            else         v = (q < 32) ? s : c;
            split1(v, g_Ahi_h[i], g_Ahi_l[i]);
        }
        // ---- W forward (k=0..31): rows 0-31 cos, rows 32-63 -sin
        {
            float s, c;
            sincospif((float)((r & 31) * q) / 32.0f, &s, &c);
            float v = (r < 32) ? c : -s;
            split1(v, g_Awf_h[i], g_Awf_l[i]);
        }
    }
}

// =====================================================================
// bias GEMM via mma.sync bf16 split-precision (validated R4)
// =====================================================================
#define TBM 128
#define TBN 128
#define TBK 32
#define KPAD (TBK + 8)

__global__ __launch_bounds__(256) void bias_mma(
    const float* __restrict__ X, const float* __restrict__ Wm,
    const float* __restrict__ bb, float* __restrict__ out)
{
    __shared__ __align__(16) __nv_bfloat16 sAhi[TBM][KPAD];
    __shared__ __align__(16) __nv_bfloat16 sAlo[TBM][KPAD];
    __shared__ __align__(16) __nv_bfloat16 sBhi[TBN][KPAD];
    __shared__ __align__(16) __nv_bfloat16 sBlo[TBN][KPAD];

    int tid = threadIdx.x;
    int wid = tid >> 5, lane = tid & 31;
    int wm = wid >> 2, wn = wid & 3;
    int m0 = blockIdx.y * TBM, n0 = blockIdx.x * TBN;

    float acc[4][4][4] = {};

    int aRow = lane & 15, aKoff = (lane >> 4) * 8;
    int bRow = lane & 7,  bKoff = ((lane >> 3) & 1) * 8;

    for (int kt = 0; kt < C_; kt += TBK) {
        #pragma unroll
        for (int it = 0; it < 4; it++) {
            int lin = tid + 256 * it;
            int r = lin >> 3, cq = (lin & 7) * 4;
            float4 va = *(const float4*)&X [(size_t)(m0 + r) * C_ + kt + cq];
            float4 vb = *(const float4*)&Wm[(size_t)(n0 + r) * C_ + kt + cq];
            __nv_bfloat16 ah[4], al[4], bh[4], bl[4];
            split4(va, ah, al);
            split4(vb, bh, bl);
            *(uint2*)&sAhi[r][cq] = *(uint2*)ah;
            *(uint2*)&sAlo[r][cq] = *(uint2*)al;
            *(uint2*)&sBhi[r][cq] = *(uint2*)bh;
            *(uint2*)&sBlo[r][cq] = *(uint2*)bl;
        }
        __syncthreads();

        #pragma unroll
        for (int s = 0; s < 2; s++) {
            int k0 = s * 16;
            uint32_t a_hi[4][4], a_lo[4][4], b_hi[4][2], b_lo[4][2];
            #pragma unroll
            for (int i = 0; i < 4; i++) {
                int row = wm * 64 + i * 16 + aRow;
                ldsm_x4(a_hi[i], smem_u32(&sAhi[row][k0 + aKoff]));
                ldsm_x4(a_lo[i], smem_u32(&sAlo[row][k0 + aKoff]));
            }
            #pragma unroll
            for (int j = 0; j < 4; j++) {
                int row = wn * 32 + j * 8 + bRow;
                ldsm_x2(b_hi[j], smem_u32(&sBhi[row][k0 + bKoff]));
                ldsm_x2(b_lo[j], smem_u32(&sBlo[row][k0 + bKoff]));
            }
            #pragma unroll
            for (int i = 0; i < 4; i++)
                #pragma unroll
                for (int j = 0; j < 4; j++) {
                    mma_bf16(acc[i][j], a_hi[i], b_hi[j]);
                    mma_bf16(acc[i][j], a_hi[i], b_lo[j]);
                    mma_bf16(acc[i][j], a_lo[i], b_hi[j]);
                }
        }
        __syncthreads();
    }

    int group = lane >> 2, qid = lane & 3;
    #pragma unroll
    for (int i = 0; i < 4; i++) {
        #pragma unroll
        for (int j = 0; j < 4; j++) {
            int col = n0 + wn * 32 + j * 8 + qid * 2;
            float b0 = bb[col], b1 = bb[col + 1];
            int r0 = m0 + wm * 64 + i * 16 + group;
            float2 v0 = {acc[i][j][0] + b0, acc[i][j][1] + b1};
            float2 v1 = {acc[i][j][2] + b0, acc[i][j][3] + b1};
            *(float2*)&out[(size_t)r0 * C_ + col]       = v0;
            *(float2*)&out[(size_t)(r0 + 8) * C_ + col] = v1;
        }
    }
}

// =====================================================================
// FFT-as-GEMM kernels: C[64, N] = A(64x64 pre-split) @ B[64, N]
// dyn smem: A hi/lo [64][72], B hi/lo [64][136]; tile N=128
// =====================================================================
#define FA_STRIDE 72
#define FB_STRIDE 136
#define SM_AH 0
#define SM_AL (SM_AH + 64 * FA_STRIDE * 2)       // 9216
#define SM_BH (SM_AL + 64 * FA_STRIDE * 2)       // 18432
#define SM_BL (SM_BH + 64 * FB_STRIDE * 2)       // 35840
#define SM_FFT_TOTAL (SM_BL + 64 * FB_STRIDE * 2) // 53248

// ---- H-direction DFT (dir 0 = forward from g_r1/g_i1 -> g_xr/g_xi,
//                       dir 1 = inverse from g_r2/g_i2 -> g_xr/g_xi)
__global__ __launch_bounds__(256) void fft_h_mma(int dir)
{
    extern __shared__ char smem[];
    __nv_bfloat16* sAh = (__nv_bfloat16*)(smem + SM_AH);
    __nv_bfloat16* sAl = (__nv_bfloat16*)(smem + SM_AL);
    __nv_bfloat16* sBh = (__nv_bfloat16*)(smem + SM_BH);
    __nv_bfloat16* sBl = (__nv_bfloat16*)(smem + SM_BL);

    int n0 = blockIdx.x * 128;
    int b  = blockIdx.y;
    int tid = threadIdx.x, wid = tid >> 5, lane = tid & 31;
    int wm = wid >> 2, wn = wid & 3;

    const __nv_bfloat16* gAh = dir ? g_Ahi_h : g_Ahf_h;
    const __nv_bfloat16* gAl = dir ? g_Ahi_l : g_Ahf_l;
    const float* Br = (dir ? g_r2 : g_r1) + (size_t)b * H_ * NKC;
    const float* Bi = (dir ? g_i2 : g_i1) + (size_t)b * H_ * NKC;
    float* Or = g_xr + (size_t)b * H_ * NKC;
    float* Oi = g_xi + (size_t)b * H_ * NKC;

    // A fill: 64 x 16 quads
    #pragma unroll
    for (int it = 0; it < 4; it++) {
        int lin = tid + 256 * it;
        int r = lin >> 4, cq = (lin & 15) * 4;
        *(uint2*)&sAh[r * FA_STRIDE + cq] = *(const uint2*)&gAh[r * 64 + cq];
        *(uint2*)&sAl[r * FA_STRIDE + cq] = *(const uint2*)&gAl[r * 64 + cq];
    }
    // B fill: 64 rows x 32 quads
    #pragma unroll
    for (int it = 0; it < 8; it++) {
        int lin = tid + 256 * it;
        int r = lin >> 5, cq = (lin & 31) * 4;
        const float* src = (r < 32) ? &Br[(size_t)r * NKC + n0 + cq]
                                    : &Bi[(size_t)(r - 32) * NKC + n0 + cq];
        float4 v = *(const float4*)src;
        __nv_bfloat16 h[4], l[4];
        split4(v, h, l);
        *(uint2*)&sBh[r * FB_STRIDE + cq] = *(uint2*)h;
        *(uint2*)&sBl[r * FB_STRIDE + cq] = *(uint2*)l;
    }
    __syncthreads();

    float acc[2][4][4] = {};
    int aRow = lane & 15, aK = (lane >> 4) * 8, bK = lane & 15;
    #pragma unroll
    for (int ks = 0; ks < 4; ks++) {
        int k0 = ks * 16;
        uint32_t ah[2][4], al[2][4], bh[4][2], bl[4][2];
        #pragma unroll
        for (int i = 0; i < 2; i++) {
            int row = wm * 32 + i * 16 + aRow;
            ldsm_x4(ah[i], smem_u32(&sAh[row * FA_STRIDE + k0 + aK]));
            ldsm_x4(al[i], smem_u32(&sAl[row * FA_STRIDE + k0 + aK]));
        }
        #pragma unroll
        for (int j = 0; j < 4; j++) {
            int nf = wn * 32 + j * 8;
            ldsm_x2_t(bh[j], smem_u32(&sBh[(k0 + bK) * FB_STRIDE + nf]));
            ldsm_x2_t(bl[j], smem_u32(&sBl[(k0 + bK) * FB_STRIDE + nf]));
        }
        #pragma unroll
        for (int i = 0; i < 2; i++)
            #pragma unroll
            for (int j = 0; j < 4; j++) {
                mma_bf16(acc[i][j], ah[i], bh[j]);
                mma_bf16(acc[i][j], ah[i], bl[j]);
                mma_bf16(acc[i][j], al[i], bh[j]);
            }
    }

    int g = lane >> 2, q = (lane & 3) * 2;
    #pragma unroll
    for (int i = 0; i < 2; i++)
        #pragma unroll
        for (int j = 0; j < 4; j++) {
            int row = wm * 32 + i * 16 + g;
            int col = n0 + wn * 32 + j * 8 + q;
            float* dst = (row < 32) ? Or + (size_t)row * NKC : Oi + (size_t)(row - 32) * NKC;
            float2 v0 = {acc[i][j][0], acc[i][j][1]};
            float2 v1 = {acc[i][j][2], acc[i][j][3]};
            *(float2*)&dst[col]            = v0;
            *(float2*)&dst[8 * NKC + col]  = v1;
        }
}

// ---- W-direction forward DFT: x[(bh*64+w)*768+c] -> g_r1/g_i1 (k rows)
__global__ __launch_bounds__(256) void fft_w_mma(const float* __restrict__ X)
{
    extern __shared__ char smem[];
    __nv_bfloat16* sAh = (__nv_bfloat16*)(smem + SM_AH);
    __nv_bfloat16* sAl = (__nv_bfloat16*)(smem + SM_AL);
    __nv_bfloat16* sBh = (__nv_bfloat16*)(smem + SM_BH);
    __nv_bfloat16* sBl = (__nv_bfloat16*)(smem + SM_BL);

    int bh = blockIdx.x;
    int c0 = blockIdx.y * 128;
    int tid = threadIdx.x, wid = tid >> 5, lane = tid & 31;
    int wm = wid >> 2, wn = wid & 3;

    #pragma unroll
    for (int it = 0; it < 4; it++) {
        int lin = tid + 256 * it;
        int r = lin >> 4, cq = (lin & 15) * 4;
        *(uint2*)&sAh[r * FA_STRIDE + cq] = *(const uint2*)&g_Awf_h[r * 64 + cq];
        *(uint2*)&sAl[r * FA_STRIDE + cq] = *(const uint2*)&g_Awf_l[r * 64 + cq];
    }
    #pragma unroll
    for (int it = 0; it < 8; it++) {
        int lin = tid + 256 * it;
        int r = lin >> 5, cq = (lin & 31) * 4;
        float4 v = *(const float4*)&X[((size_t)bh * 64 + r) * C_ + c0 + cq];
        __nv_bfloat16 h[4], l[4];
        split4(v, h, l);
        *(uint2*)&sBh[r * FB_STRIDE + cq] = *(uint2*)h;
        *(uint2*)&sBl[r * FB_STRIDE + cq] = *(uint2*)l;
    }
    __syncthreads();

    float acc[2][4][4] = {};
    int aRow = lane & 15, aK = (lane >> 4) * 8, bK = lane & 15;
    #pragma unroll
    for (int ks = 0; ks < 4; ks++) {
        int k0 = ks * 16;
        uint32_t ah[2][4], al[2][4], bh[4][2], bl[4][2];
        #pragma unroll
        for (int i = 0; i < 2; i++) {
            int row = wm * 32 + i * 16 + aRow;
            ldsm_x4(ah[i], smem_u32(&sAh[row * FA_STRIDE + k0 + aK]));
            ldsm_x4(al[i], smem_u32(&sAl[row * FA_STRIDE + k0 + aK]));
        }
        #pragma unroll
        for (int j = 0; j < 4; j++) {
            int nf = wn * 32 + j * 8;
            ldsm_x2_t(bh[j], smem_u32(&sBh[(k0 + bK) * FB_STRIDE + nf]));
            ldsm_x2_t(bl[j], smem_u32(&sBl[(k0 + bK) * FB_STRIDE + nf]));
        }
        #pragma unroll
        for (int i = 0; i < 2; i++)
            #pragma unroll
            for (int j = 0; j < 4; j++) {
                mma_bf16(acc[i][j], ah[i], bh[j]);
                mma_bf16(acc[i][j], ah[i], bl[j]);
                mma_bf16(acc[i][j], al[i], bh[j]);
            }
    }

    int g = lane >> 2, q = (lane & 3) * 2;
    float* Yr = g_r1 + (size_t)bh * WH * C_;
    float* Yi = g_i1 + (size_t)bh * WH * C_;
    #pragma unroll
    for (int i = 0; i < 2; i++)
        #pragma unroll
        for (int j = 0; j < 4; j++) {
            int row = wm * 32 + i * 16 + g;
            int col = c0 + wn * 32 + j * 8 + q;
            float* dst = (row < 32) ? Yr + (size_t)row * C_ : Yi + (size_t)(row - 32) * C_;
            float2 v0 = {acc[i][j][0], acc[i][j][1]};
            float2 v1 = {acc[i][j][2], acc[i][j][3]};
            *(float2*)&dst[col]          = v0;
            *(float2*)&dst[8 * C_ + col] = v1;
        }

    // Nyquist row k=32: Yr = sum_w (-1)^w x[w], Yi = 0
    if (tid < 128) {
        float alt = 0.f;
        #pragma unroll 8
        for (int w = 0; w < W_; w++) {
            float xv = __bfloat162float(sBh[w * FB_STRIDE + tid])
                     + __bfloat162float(sBl[w * FB_STRIDE + tid]);
            alt += (w & 1) ? -xv : xv;
        }
        Yr[(size_t)32 * C_ + c0 + tid] = alt;
        Yi[(size_t)32 * C_ + c0 + tid] = 0.f;
    }
}

// =====================================================================
// freq MLP via mma.sync (validated R5)
// =====================================================================
#define FM 128
#define FN 64
#define FK 16
#define XPAD (FK + 8)
#define WPAD (FN + 8)

__global__ __launch_bounds__(256) void freq_l1_mma(
    const float* __restrict__ w1, const float* __restrict__ b1)
{
    __shared__ __align__(16) __nv_bfloat16 sXrh[FM][XPAD], sXrl[FM][XPAD];
    __shared__ __align__(16) __nv_bfloat16 sXih[FM][XPAD], sXil[FM][XPAD];
    __shared__ __align__(16) __nv_bfloat16 sWrh[FK][WPAD], sWrl[FK][WPAD];
    __shared__ __align__(16) __nv_bfloat16 sWih[FK][WPAD], sWil[FK][WPAD];
    __shared__ __align__(16) __nv_bfloat16 sWnh[FK][WPAD], sWnl[FK][WPAD];

    int tid = threadIdx.x, wid = tid >> 5, lane = tid & 31;
    int wm = wid >> 2, wn = wid & 3;
    int p0 = blockIdx.x * FM, j0 = blockIdx.y * FN, nb = blockIdx.z;
    const float* Wr = w1 + (size_t)nb * BS_ * BS_;
    const float* Wi = w1 + (size_t)(NBLK + nb) * BS_ * BS_;

    float accR[4][2][4] = {}, accI[4][2][4] = {};
    int aRow = lane & 15, aK = (lane >> 4) * 8;
    int bKrow = lane & 15;

    for (int kt = 0; kt < BS_; kt += FK) {
        #pragma unroll
        for (int it = 0; it < 2; it++) {
            int lin = tid + 256 * it;
            int r = lin >> 2, cq = (lin & 3) * 4;
            float4 vr = *(const float4*)&g_xr[(size_t)(p0 + r) * C_ + nb * BS_ + kt + cq];
            float4 vi = *(const float4*)&g_xi[(size_t)(p0 + r) * C_ + nb * BS_ + kt + cq];
            __nv_bfloat16 h[4], l[4];
            split4(vr, h, l);
            *(uint2*)&sXrh[r][cq] = *(uint2*)h;
            *(uint2*)&sXrl[r][cq] = *(uint2*)l;
            split4(vi, h, l);
            *(uint2*)&sXih[r][cq] = *(uint2*)h;
            *(uint2*)&sXil[r][cq] = *(uint2*)l;
        }
        {
            int d = tid >> 4, jq = (tid & 15) * 4;
            float4 vr = *(const float4*)&Wr[(size_t)(kt + d) * BS_ + j0 + jq];
            float4 vi = *(const float4*)&Wi[(size_t)(kt + d) * BS_ + j0 + jq];
            __nv_bfloat16 h[4], l[4];
            split4(vr, h, l);
            *(uint2*)&sWrh[d][jq] = *(uint2*)h;
            *(uint2*)&sWrl[d][jq] = *(uint2*)l;
            split4(vi, h, l);
            *(uint2*)&sWih[d][jq] = *(uint2*)h;
            *(uint2*)&sWil[d][jq] = *(uint2*)l;
            float4 vn = {-vi.x, -vi.y, -vi.z, -vi.w};
            split4(vn, h, l);
            *(uint2*)&sWnh[d][jq] = *(uint2*)h;
            *(uint2*)&sWnl[d][jq] = *(uint2*)l;
        }
        __syncthreads();

        uint32_t axrh[4][4], axrl[4][4], axih[4][4], axil[4][4];
        #pragma unroll
        for (int i = 0; i < 4; i++) {
            int row = wm * 64 + i * 16 + aRow;
            ldsm_x4(axrh[i], smem_u32(&sXrh[row][aK]));
            ldsm_x4(axrl[i], smem_u32(&sXrl[row][aK]));
            ldsm_x4(axih[i], smem_u32(&sXih[row][aK]));
            ldsm_x4(axil[i], smem_u32(&sXil[row][aK]));
        }
        uint32_t bwrh[2][2], bwrl[2][2], bwih[2][2], bwil[2][2], bwnh[2][2], bwnl[2][2];
        #pragma unroll
        for (int j = 0; j < 2; j++) {
            int nf = wn * 16 + j * 8;
            ldsm_x2_t(bwrh[j], smem_u32(&sWrh[bKrow][nf]));
            ldsm_x2_t(bwrl[j], smem_u32(&sWrl[bKrow][nf]));
            ldsm_x2_t(bwih[j], smem_u32(&sWih[bKrow][nf]));
            ldsm_x2_t(bwil[j], smem_u32(&sWil[bKrow][nf]));
            ldsm_x2_t(bwnh[j], smem_u32(&sWnh[bKrow][nf]));
            ldsm_x2_t(bwnl[j], smem_u32(&sWnl[bKrow][nf]));
        }
        #pragma unroll
        for (int i = 0; i < 4; i++)
            #pragma unroll
            for (int j = 0; j < 2; j++) {
                mma_bf16(accR[i][j], axrh[i], bwrh[j]);
                mma_bf16(accR[i][j], axrh[i], bwrl[j]);
                mma_bf16(accR[i][j], axrl[i], bwrh[j]);
                mma_bf16(accR[i][j], axih[i], bwnh[j]);
                mma_bf16(accR[i][j], axih[i], bwnl[j]);
                mma_bf16(accR[i][j], axil[i], bwnh[j]);
                mma_bf16(accI[i][j], axrh[i], bwih[j]);
                mma_bf16(accI[i][j], axrh[i], bwil[j]);
                mma_bf16(accI[i][j], axrl[i], bwih[j]);
                mma_bf16(accI[i][j], axih[i], bwrh[j]);
                mma_bf16(accI[i][j], axih[i], bwrl[j]);
                mma_bf16(accI[i][j], axil[i], bwrh[j]);
            }
        __syncthreads();
    }

    const float* br = b1 + (size_t)nb * BS_;
    const float* bi = b1 + (size_t)(NBLK + nb) * BS_;
    int g = lane >> 2, q = (lane & 3) * 2;
    #pragma unroll
    for (int i = 0; i < 4; i++)
        #pragma unroll
        for (int j = 0; j < 2; j++) {
            int col = j0 + wn * 16 + j * 8 + q;
            float br0 = br[col], br1 = br[col + 1];
            float bi0 = bi[col], bi1 = bi[col + 1];
            int r0 = p0 + wm * 64 + i * 16 + g;
            size_t o0 = (size_t)r0 * C_ + nb * BS_ + col;
            size_t o1 = (size_t)(r0 + 8) * C_ + nb * BS_ + col;
            float2 vr0 = {fmaxf(accR[i][j][0] + br0, 0.f), fmaxf(accR[i][j][1] + br1, 0.f)};
            float2 vr1 = {fmaxf(accR[i][j][2] + br0, 0.f), fmaxf(accR[i][j][3] + br1, 0.f)};
            float2 vi0 = {fmaxf(accI[i][j][0] + bi0, 0.f), fmaxf(accI[i][j][1] + bi1, 0.f)};
            float2 vi1 = {fmaxf(accI[i][j][2] + bi0, 0.f), fmaxf(accI[i][j][3] + bi1, 0.f)};
            *(float2*)&g_r1[o0] = vr0;
            *(float2*)&g_r1[o1] = vr1;
            *(float2*)&g_i1[o0] = vi0;
            *(float2*)&g_i1[o1] = vi1;
        }
}

__global__ __launch_bounds__(256) void freq_l2_mma(
    const float* __restrict__ w2, const float* __restrict__ b2, int phase)
{
    __shared__ __align__(16) __nv_bfloat16 sAh[FM][XPAD], sAl[FM][XPAD];
    __shared__ __align__(16) __nv_bfloat16 sBh[FM][XPAD], sBl[FM][XPAD];
    __shared__ __align__(16) __nv_bfloat16 sWah[FK][WPAD], sWal[FK][WPAD];
    __shared__ __align__(16) __nv_bfloat16 sWbh[FK][WPAD], sWbl[FK][WPAD];

    int tid = threadIdx.x, wid = tid >> 5, lane = tid & 31;
    int wm = wid >> 2, wn = wid & 3;
    int p0 = blockIdx.x * FM, j0 = blockIdx.y * FN, nb = blockIdx.z;

    const float* A  = (phase == 0 ? g_r1 : g_r2);
    const float* Bm = g_i1;
    const float* Wa = w2 + (size_t)((phase == 0 ? 0 : NBLK) + nb) * BS_ * BS_;
    const float* Wb = w2 + (size_t)((phase == 0 ? NBLK : 0) + nb) * BS_ * BS_;
    const float* bias = b2 + (size_t)(phase == 0 ? 0 : NBLK) * BS_ + (size_t)nb * BS_;
    float* O = (phase == 0 ? g_r2 : g_i2);
    float sgn = (phase == 0) ? -1.f : 1.f;

    float acc[4][2][4] = {};
    int aRow = lane & 15, aK = (lane >> 4) * 8;
    int bKrow = lane & 15;

    for (int kt = 0; kt < BS_; kt += FK) {
        #pragma unroll
        for (int it = 0; it < 2; it++) {
            int lin = tid + 256 * it;
            int r = lin >> 2, cq = (lin & 3) * 4;
            float4 va = *(const float4*)&A [(size_t)(p0 + r) * C_ + nb * BS_ + kt + cq];
            float4 vb = *(const float4*)&Bm[(size_t)(p0 + r) * C_ + nb * BS_ + kt + cq];
            __nv_bfloat16 h[4], l[4];
            split4(va, h, l);
            *(uint2*)&sAh[r][cq] = *(uint2*)h;
            *(uint2*)&sAl[r][cq] = *(uint2*)l;
            split4(vb, h, l);
            *(uint2*)&sBh[r][cq] = *(uint2*)h;
            *(uint2*)&sBl[r][cq] = *(uint2*)l;
        }
        {
            int d = tid >> 4, jq = (tid & 15) * 4;
            float4 va = *(const float4*)&Wa[(size_t)(kt + d) * BS_ + j0 + jq];
            float4 vb = *(const float4*)&Wb[(size_t)(kt + d) * BS_ + j0 + jq];
            vb.x *= sgn; vb.y *= sgn; vb.z *= sgn; vb.w *= sgn;
            __nv_bfloat16 h[4], l[4];
            split4(va, h, l);
            *(uint2*)&sWah[d][jq] = *(uint2*)h;
            *(uint2*)&sWal[d][jq] = *(uint2*)l;
            split4(vb, h, l);
            *(uint2*)&sWbh[d][jq] = *(uint2*)h;
            *(uint2*)&sWbl[d][jq] = *(uint2*)l;
        }
        __syncthreads();

        uint32_t aah[4][4], aal[4][4], abh[4][4], abl[4][4];
        #pragma unroll
        for (int i = 0; i < 4; i++) {
            int row = wm * 64 + i * 16 + aRow;
            ldsm_x4(aah[i], smem_u32(&sAh[row][aK]));
            ldsm_x4(aal[i], smem_u32(&sAl[row][aK]));
            ldsm_x4(abh[i], smem_u32(&sBh[row][aK]));
            ldsm_x4(abl[i], smem_u32(&sBl[row][aK]));
        }
        uint32_t bah[2][2], bal[2][2], bbh[2][2], bbl[2][2];
        #pragma unroll
        for (int j = 0; j < 2; j++) {
            int nf = wn * 16 + j * 8;
            ldsm_x2_t(bah[j], smem_u32(&sWah[bKrow][nf]));
            ldsm_x2_t(bal[j], smem_u32(&sWal[bKrow][nf]));
            ldsm_x2_t(bbh[j], smem_u32(&sWbh[bKrow][nf]));
            ldsm_x2_t(bbl[j], smem_u32(&sWbl[bKrow][nf]));
        }
        #pragma unroll
        for (int i = 0; i < 4; i++)
            #pragma unroll
            for (int j = 0; j < 2; j++) {
                mma_bf16(acc[i][j], aah[i], bah[j]);
                mma_bf16(acc[i][j], aah[i], bal[j]);
                mma_bf16(acc[i][j], aal[i], bah[j]);
                mma_bf16(acc[i][j], abh[i], bbh[j]);
                mma_bf16(acc[i][j], abh[i], bbl[j]);
                mma_bf16(acc[i][j], abl[i], bbh[j]);
            }
        __syncthreads();
    }

    int g = lane >> 2, q = (lane & 3) * 2;
    #pragma unroll
    for (int i = 0; i < 4; i++)
        #pragma unroll
        for (int j = 0; j < 2; j++) {
            int col = j0 + wn * 16 + j * 8 + q;
            float b0 = bias[col], b1 = bias[col + 1];
            int r0 = p0 + wm * 64 + i * 16 + g;
            float2 v0 = {acc[i][j][0] + b0, acc[i][j][1] + b1};
            float2 v1 = {acc[i][j][2] + b0, acc[i][j][3] + b1};
            *(float2*)&O[(size_t)r0 * C_ + nb * BS_ + col]       = v0;
            *(float2*)&O[(size_t)(r0 + 8) * C_ + nb * BS_ + col] = v1;
        }
}

// =====================================================================
// Kernel 8: inverse real DFT along W (fp32), accumulate into out
// =====================================================================
__global__ __launch_bounds__(256) void fft_w_inv(float* __restrict__ out)
{
    int bh = blockIdx.x;
    int c0 = blockIdx.y * 64;
    __shared__ float sFr[WH][64], sFi[WH][64];
    __shared__ float sTc[WH * W_], sTs[WH * W_];
    int tid = threadIdx.x;

    for (int i = tid; i < WH * W_; i += 256) { sTc[i] = g_t1c[i]; sTs[i] = g_t1s[i]; }
    const float* Fr = g_xr + (size_t)bh * WH * C_ + c0;
    const float* Fi = g_xi + (size_t)bh * WH * C_ + c0;
    for (int i = tid; i < WH * 16; i += 256) {
        int k = i >> 4, q = i & 15;
        float wt = (k == 0 || k == 32) ? SC_ORTHO : 2.f * SC_ORTHO;
        float4 vr = *(const float4*)&Fr[(size_t)k * C_ + q * 4];
        float4 vi = *(const float4*)&Fi[(size_t)k * C_ + q * 4];
        vr.x *= wt; vr.y *= wt; vr.z *= wt; vr.w *= wt;
        vi.x *= wt; vi.y *= wt; vi.z *= wt; vi.w *= wt;
        *(float4*)&sFr[k][q * 4] = vr;
        *(float4*)&sFi[k][q * 4] = vi;
    }
    __syncthreads();

    int quad = tid & 15, wg = tid >> 4;
    float acc[4][4] = {};
    #pragma unroll 8
    for (int k = 0; k < WH; k++) {
        float4 fr = *(const float4*)&sFr[k][quad * 4];
        float4 fi = *(const float4*)&sFi[k][quad * 4];
        #pragma unroll
        for (int i = 0; i < 4; i++) {
            int w = wg * 4 + i;
            float tc = sTc[k * W_ + w], ts = sTs[k * W_ + w];
            acc[i][0] += fr.x * tc + fi.x * ts;
            acc[i][1] += fr.y * tc + fi.y * ts;
            acc[i][2] += fr.z * tc + fi.z * ts;
            acc[i][3] += fr.w * tc + fi.w * ts;
        }
    }
    float* op = out + (size_t)bh * 64 * C_ + c0;
    #pragma unroll
    for (int i = 0; i < 4; i++) {
        int w = wg * 4 + i;
        float4 cur = *(float4*)&op[(size_t)w * C_ + quad * 4];
        cur.x += acc[i][0]; cur.y += acc[i][1];
        cur.z += acc[i][2]; cur.w += acc[i][3];
        *(float4*)&op[(size_t)w * C_ + quad * 4] = cur;
    }
}

// =====================================================================
extern "C" void kernel_launch(void* const* d_in, const int* in_sizes, int n_in,
                              void* d_out, int out_size)
{
    const float* x  = (const float*)d_in[0];
    const float* w1 = (const float*)d_in[1];
    const float* b1 = (const float*)d_in[2];
    const float* w2 = (const float*)d_in[3];
    const float* b2 = (const float*)d_in[4];
    const float* bw = (const float*)d_in[5];
    const float* bb = (const float*)d_in[6];
    float* out = (float*)d_out;

    cudaFuncSetAttribute(fft_h_mma, cudaFuncAttributeMaxDynamicSharedMemorySize, SM_FFT_TOTAL);
    cudaFuncSetAttribute(fft_w_mma, cudaFuncAttributeMaxDynamicSharedMemorySize, SM_FFT_TOTAL);

    init_tables<<<1, 256>>>();

    bias_mma<<<dim3(C_ / TBN, NTOK / TBM), 256>>>(x, bw, bb, out);

    fft_w_mma<<<dim3(B_ * H_, C_ / 128), 256, SM_FFT_TOTAL>>>(x);   // (512, 6)
    fft_h_mma<<<dim3(NKC / 128, B_), 256, SM_FFT_TOTAL>>>(0);       // (198, 16)

    dim3 gFreq(P_ / FM, BS_ / FN, NBLK);    // (132, 3, 4)
    freq_l1_mma<<<gFreq, 256>>>(w1, b1);
    freq_l2_mma<<<gFreq, 256>>>(w2, b2, 0);
    freq_l2_mma<<<gFreq, 256>>>(w2, b2, 1);

    fft_h_mma<<<dim3(NKC / 128, B_), 256, SM_FFT_TOTAL>>>(1);       // (198, 16)
    fft_w_inv<<<dim3(B_ * H_, C_ / 64), 256>>>(out);
}

// round 9
// speedup vs baseline: 4.1007x; 1.0695x over previous
#include <cuda_runtime.h>
#include <cuda_bf16.h>
#include <cstdint>

// ---------------- problem constants ----------------
#define B_  16
#define H_  32
#define W_  64
#define WH  33            // W/2+1
#define C_  768
#define NBLK 4
#define BS_ 192           // C/NBLK
#define P_  (B_*H_*WH)    // 16896 frequency positions
#define NKC (WH*C_)       // 25344
#define NTOK (B_*H_*W_)   // 32768 spatial tokens

#define SC_ORTHO 0.0220970869120796f   // 1/sqrt(2048)

// ---------------- scratch ----------------
__device__ float g_xr[(size_t)P_ * C_];
__device__ float g_xi[(size_t)P_ * C_];
__device__ float g_r1[(size_t)P_ * C_];
__device__ float g_i1[(size_t)P_ * C_];
__device__ float g_r2[(size_t)P_ * C_];
__device__ float g_i2[(size_t)P_ * C_];

// pre-split 64x64 DFT operator matrices (bf16 hi/lo)
__device__ __nv_bfloat16 g_Ahf_h[4096], g_Ahf_l[4096];   // H fwd (scaled)
__device__ __nv_bfloat16 g_Ahi_h[4096], g_Ahi_l[4096];   // H inv
__device__ __nv_bfloat16 g_Awf_h[4096], g_Awf_l[4096];   // W fwd (k=0..31)
__device__ __nv_bfloat16 g_Awi_h[4096], g_Awi_l[4096];   // W inv (weights folded)

// =====================================================================
// portable tensor-core helpers (mma.sync + ldmatrix)
// =====================================================================
__device__ __forceinline__ uint32_t smem_u32(const void* p) {
    uint32_t a;
    asm("{ .reg .u64 t; cvta.to.shared.u64 t, %1; cvt.u32.u64 %0, t; }" : "=r"(a) : "l"(p));
    return a;
}
__device__ __forceinline__ void mma_bf16(float* d, const uint32_t* a, const uint32_t* b) {
    asm volatile("mma.sync.aligned.m16n8k16.row.col.f32.bf16.bf16.f32 "
        "{%0,%1,%2,%3}, {%4,%5,%6,%7}, {%8,%9}, {%0,%1,%2,%3};"
        : "+f"(d[0]), "+f"(d[1]), "+f"(d[2]), "+f"(d[3])
        : "r"(a[0]), "r"(a[1]), "r"(a[2]), "r"(a[3]), "r"(b[0]), "r"(b[1]));
}
__device__ __forceinline__ void ldsm_x4(uint32_t* r, uint32_t addr) {
    asm volatile("ldmatrix.sync.aligned.m8n8.x4.shared.b16 {%0,%1,%2,%3}, [%4];"
        : "=r"(r[0]), "=r"(r[1]), "=r"(r[2]), "=r"(r[3]) : "r"(addr));
}
__device__ __forceinline__ void ldsm_x2(uint32_t* r, uint32_t addr) {
    asm volatile("ldmatrix.sync.aligned.m8n8.x2.shared.b16 {%0,%1}, [%2];"
        : "=r"(r[0]), "=r"(r[1]) : "r"(addr));
}
__device__ __forceinline__ void ldsm_x2_t(uint32_t* r, uint32_t addr) {
    asm volatile("ldmatrix.sync.aligned.m8n8.x2.trans.shared.b16 {%0,%1}, [%2];"
        : "=r"(r[0]), "=r"(r[1]) : "r"(addr));
}
__device__ __forceinline__ void split4(float4 v, __nv_bfloat16* h, __nv_bfloat16* l) {
    float a[4] = {v.x, v.y, v.z, v.w};
    #pragma unroll
    for (int q = 0; q < 4; q++) {
        h[q] = __float2bfloat16(a[q]);
        l[q] = __float2bfloat16(a[q] - __bfloat162float(h[q]));
    }
}
__device__ __forceinline__ void split1(float v, __nv_bfloat16& h, __nv_bfloat16& l) {
    h = __float2bfloat16(v);
    l = __float2bfloat16(v - __bfloat162float(h));
}

// =====================================================================
__global__ void init_tables()
{
    int idx = blockIdx.x * blockDim.x + threadIdx.x;
    for (int i = idx; i < 4096; i += gridDim.x * blockDim.x) {
        int r = i >> 6, q = i & 63;
        // ---- H forward
        {
            float s, c;
            sincospif((float)((r & 31) * (q & 31)) / 16.0f, &s, &c);
            float v;
            if (r < 32)  v = (q < 32) ? c : s;
            else         v = (q < 32) ? -s : c;
            split1(v * SC_ORTHO, g_Ahf_h[i], g_Ahf_l[i]);
        }
        // ---- H inverse
        {
            float s, c;
            sincospif((float)((r & 31) * (q & 31)) / 16.0f, &s, &c);
            float v;
            if (r < 32)  v = (q < 32) ? c : -s;
            else         v = (q < 32) ? s : c;
            split1(v, g_Ahi_h[i], g_Ahi_l[i]);
        }
        // ---- W forward (k=0..31): rows 0-31 cos, rows 32-63 -sin
        {
            float s, c;
            sincospif((float)((r & 31) * q) / 32.0f, &s, &c);
            float v = (r < 32) ? c : -s;
            split1(v, g_Awf_h[i], g_Awf_l[i]);
        }
        // ---- W inverse: row = w, col q: 0..31 -> Fr[k=q] ; 32 -> Fr[32] ; 33..63 -> Fi[k=q-32]
        {
            float v;
            if (q == 0) {
                v = SC_ORTHO;
            } else if (q < 32) {
                float s, c;
                sincospif((float)(q * r) / 32.0f, &s, &c);
                v = 2.f * SC_ORTHO * c;
            } else if (q == 32) {
                v = (r & 1) ? -SC_ORTHO : SC_ORTHO;
            } else {
                int k = q - 32;
                float s, c;
                sincospif((float)(k * r) / 32.0f, &s, &c);
                v = -2.f * SC_ORTHO * s;
            }
            split1(v, g_Awi_h[i], g_Awi_l[i]);
        }
    }
}

// =====================================================================
// bias GEMM via mma.sync bf16 split-precision (validated R4)
// =====================================================================
#define TBM 128
#define TBN 128
#define TBK 32
#define KPAD (TBK + 8)

__global__ __launch_bounds__(256) void bias_mma(
    const float* __restrict__ X, const float* __restrict__ Wm,
    const float* __restrict__ bb, float* __restrict__ out)
{
    __shared__ __align__(16) __nv_bfloat16 sAhi[TBM][KPAD];
    __shared__ __align__(16) __nv_bfloat16 sAlo[TBM][KPAD];
    __shared__ __align__(16) __nv_bfloat16 sBhi[TBN][KPAD];
    __shared__ __align__(16) __nv_bfloat16 sBlo[TBN][KPAD];

    int tid = threadIdx.x;
    int wid = tid >> 5, lane = tid & 31;
    int wm = wid >> 2, wn = wid & 3;
    int m0 = blockIdx.y * TBM, n0 = blockIdx.x * TBN;

    float acc[4][4][4] = {};

    int aRow = lane & 15, aKoff = (lane >> 4) * 8;
    int bRow = lane & 7,  bKoff = ((lane >> 3) & 1) * 8;

    for (int kt = 0; kt < C_; kt += TBK) {
        #pragma unroll
        for (int it = 0; it < 4; it++) {
            int lin = tid + 256 * it;
            int r = lin >> 3, cq = (lin & 7) * 4;
            float4 va = *(const float4*)&X [(size_t)(m0 + r) * C_ + kt + cq];
            float4 vb = *(const float4*)&Wm[(size_t)(n0 + r) * C_ + kt + cq];
            __nv_bfloat16 ah[4], al[4], bh[4], bl[4];
            split4(va, ah, al);
            split4(vb, bh, bl);
            *(uint2*)&sAhi[r][cq] = *(uint2*)ah;
            *(uint2*)&sAlo[r][cq] = *(uint2*)al;
            *(uint2*)&sBhi[r][cq] = *(uint2*)bh;
            *(uint2*)&sBlo[r][cq] = *(uint2*)bl;
        }
        __syncthreads();

        #pragma unroll
        for (int s = 0; s < 2; s++) {
            int k0 = s * 16;
            uint32_t a_hi[4][4], a_lo[4][4], b_hi[4][2], b_lo[4][2];
            #pragma unroll
            for (int i = 0; i < 4; i++) {
                int row = wm * 64 + i * 16 + aRow;
                ldsm_x4(a_hi[i], smem_u32(&sAhi[row][k0 + aKoff]));
                ldsm_x4(a_lo[i], smem_u32(&sAlo[row][k0 + aKoff]));
            }
            #pragma unroll
            for (int j = 0; j < 4; j++) {
                int row = wn * 32 + j * 8 + bRow;
                ldsm_x2(b_hi[j], smem_u32(&sBhi[row][k0 + bKoff]));
                ldsm_x2(b_lo[j], smem_u32(&sBlo[row][k0 + bKoff]));
            }
            #pragma unroll
            for (int i = 0; i < 4; i++)
                #pragma unroll
                for (int j = 0; j < 4; j++) {
                    mma_bf16(acc[i][j], a_hi[i], b_hi[j]);
                    mma_bf16(acc[i][j], a_hi[i], b_lo[j]);
                    mma_bf16(acc[i][j], a_lo[i], b_hi[j]);
                }
        }
        __syncthreads();
    }

    int group = lane >> 2, qid = lane & 3;
    #pragma unroll
    for (int i = 0; i < 4; i++) {
        #pragma unroll
        for (int j = 0; j < 4; j++) {
            int col = n0 + wn * 32 + j * 8 + qid * 2;
            float b0 = bb[col], b1 = bb[col + 1];
            int r0 = m0 + wm * 64 + i * 16 + group;
            float2 v0 = {acc[i][j][0] + b0, acc[i][j][1] + b1};
            float2 v1 = {acc[i][j][2] + b0, acc[i][j][3] + b1};
            *(float2*)&out[(size_t)r0 * C_ + col]       = v0;
            *(float2*)&out[(size_t)(r0 + 8) * C_ + col] = v1;
        }
    }
}

// =====================================================================
// FFT-as-GEMM kernels: C[64, N] = A(64x64 pre-split) @ B[64, N]
// =====================================================================
#define FA_STRIDE 72
#define FB_STRIDE 136
#define SM_AH 0
#define SM_AL (SM_AH + 64 * FA_STRIDE * 2)
#define SM_BH (SM_AL + 64 * FA_STRIDE * 2)
#define SM_BL (SM_BH + 64 * FB_STRIDE * 2)
#define SM_FFT_TOTAL (SM_BL + 64 * FB_STRIDE * 2)

// ---- H-direction DFT (dir 0 = fwd g_r1/g_i1 -> g_xr/g_xi, dir 1 = inv g_r2/g_i2 -> g_xr/g_xi)
__global__ __launch_bounds__(256) void fft_h_mma(int dir)
{
    extern __shared__ char smem[];
    __nv_bfloat16* sAh = (__nv_bfloat16*)(smem + SM_AH);
    __nv_bfloat16* sAl = (__nv_bfloat16*)(smem + SM_AL);
    __nv_bfloat16* sBh = (__nv_bfloat16*)(smem + SM_BH);
    __nv_bfloat16* sBl = (__nv_bfloat16*)(smem + SM_BL);

    int n0 = blockIdx.x * 128;
    int b  = blockIdx.y;
    int tid = threadIdx.x, wid = tid >> 5, lane = tid & 31;
    int wm = wid >> 2, wn = wid & 3;

    const __nv_bfloat16* gAh = dir ? g_Ahi_h : g_Ahf_h;
    const __nv_bfloat16* gAl = dir ? g_Ahi_l : g_Ahf_l;
    const float* Br = (dir ? g_r2 : g_r1) + (size_t)b * H_ * NKC;
    const float* Bi = (dir ? g_i2 : g_i1) + (size_t)b * H_ * NKC;
    float* Or = g_xr + (size_t)b * H_ * NKC;
    float* Oi = g_xi + (size_t)b * H_ * NKC;

    #pragma unroll
    for (int it = 0; it < 4; it++) {
        int lin = tid + 256 * it;
        int r = lin >> 4, cq = (lin & 15) * 4;
        *(uint2*)&sAh[r * FA_STRIDE + cq] = *(const uint2*)&gAh[r * 64 + cq];
        *(uint2*)&sAl[r * FA_STRIDE + cq] = *(const uint2*)&gAl[r * 64 + cq];
    }
    #pragma unroll
    for (int it = 0; it < 8; it++) {
        int lin = tid + 256 * it;
        int r = lin >> 5, cq = (lin & 31) * 4;
        const float* src = (r < 32) ? &Br[(size_t)r * NKC + n0 + cq]
                                    : &Bi[(size_t)(r - 32) * NKC + n0 + cq];
        float4 v = *(const float4*)src;
        __nv_bfloat16 h[4], l[4];
        split4(v, h, l);
        *(uint2*)&sBh[r * FB_STRIDE + cq] = *(uint2*)h;
        *(uint2*)&sBl[r * FB_STRIDE + cq] = *(uint2*)l;
    }
    __syncthreads();

    float acc[2][4][4] = {};
    int aRow = lane & 15, aK = (lane >> 4) * 8, bK = lane & 15;
    #pragma unroll
    for (int ks = 0; ks < 4; ks++) {
        int k0 = ks * 16;
        uint32_t ah[2][4], al[2][4], bh[4][2], bl[4][2];
        #pragma unroll
        for (int i = 0; i < 2; i++) {
            int row = wm * 32 + i * 16 + aRow;
            ldsm_x4(ah[i], smem_u32(&sAh[row * FA_STRIDE + k0 + aK]));
            ldsm_x4(al[i], smem_u32(&sAl[row * FA_STRIDE + k0 + aK]));
        }
        #pragma unroll
        for (int j = 0; j < 4; j++) {
            int nf = wn * 32 + j * 8;
            ldsm_x2_t(bh[j], smem_u32(&sBh[(k0 + bK) * FB_STRIDE + nf]));
            ldsm_x2_t(bl[j], smem_u32(&sBl[(k0 + bK) * FB_STRIDE + nf]));
        }
        #pragma unroll
        for (int i = 0; i < 2; i++)
            #pragma unroll
            for (int j = 0; j < 4; j++) {
                mma_bf16(acc[i][j], ah[i], bh[j]);
                mma_bf16(acc[i][j], ah[i], bl[j]);
                mma_bf16(acc[i][j], al[i], bh[j]);
            }
    }

    int g = lane >> 2, q = (lane & 3) * 2;
    #pragma unroll
    for (int i = 0; i < 2; i++)
        #pragma unroll
        for (int j = 0; j < 4; j++) {
            int row = wm * 32 + i * 16 + g;
            int col = n0 + wn * 32 + j * 8 + q;
            float* dst = (row < 32) ? Or + (size_t)row * NKC : Oi + (size_t)(row - 32) * NKC;
            float2 v0 = {acc[i][j][0], acc[i][j][1]};
            float2 v1 = {acc[i][j][2], acc[i][j][3]};
            *(float2*)&dst[col]            = v0;
            *(float2*)&dst[8 * NKC + col]  = v1;
        }
}

// ---- W-direction forward DFT: x -> g_r1/g_i1
__global__ __launch_bounds__(256) void fft_w_mma(const float* __restrict__ X)
{
    extern __shared__ char smem[];
    __nv_bfloat16* sAh = (__nv_bfloat16*)(smem + SM_AH);
    __nv_bfloat16* sAl = (__nv_bfloat16*)(smem + SM_AL);
    __nv_bfloat16* sBh = (__nv_bfloat16*)(smem + SM_BH);
    __nv_bfloat16* sBl = (__nv_bfloat16*)(smem + SM_BL);

    int bh = blockIdx.x;
    int c0 = blockIdx.y * 128;
    int tid = threadIdx.x, wid = tid >> 5, lane = tid & 31;
    int wm = wid >> 2, wn = wid & 3;

    #pragma unroll
    for (int it = 0; it < 4; it++) {
        int lin = tid + 256 * it;
        int r = lin >> 4, cq = (lin & 15) * 4;
        *(uint2*)&sAh[r * FA_STRIDE + cq] = *(const uint2*)&g_Awf_h[r * 64 + cq];
        *(uint2*)&sAl[r * FA_STRIDE + cq] = *(const uint2*)&g_Awf_l[r * 64 + cq];
    }
    #pragma unroll
    for (int it = 0; it < 8; it++) {
        int lin = tid + 256 * it;
        int r = lin >> 5, cq = (lin & 31) * 4;
        float4 v = *(const float4*)&X[((size_t)bh * 64 + r) * C_ + c0 + cq];
        __nv_bfloat16 h[4], l[4];
        split4(v, h, l);
        *(uint2*)&sBh[r * FB_STRIDE + cq] = *(uint2*)h;
        *(uint2*)&sBl[r * FB_STRIDE + cq] = *(uint2*)l;
    }
    __syncthreads();

    float acc[2][4][4] = {};
    int aRow = lane & 15, aK = (lane >> 4) * 8, bK = lane & 15;
    #pragma unroll
    for (int ks = 0; ks < 4; ks++) {
        int k0 = ks * 16;
        uint32_t ah[2][4], al[2][4], bh[4][2], bl[4][2];
        #pragma unroll
        for (int i = 0; i < 2; i++) {
            int row = wm * 32 + i * 16 + aRow;
            ldsm_x4(ah[i], smem_u32(&sAh[row * FA_STRIDE + k0 + aK]));
            ldsm_x4(al[i], smem_u32(&sAl[row * FA_STRIDE + k0 + aK]));
        }
        #pragma unroll
        for (int j = 0; j < 4; j++) {
            int nf = wn * 32 + j * 8;
            ldsm_x2_t(bh[j], smem_u32(&sBh[(k0 + bK) * FB_STRIDE + nf]));
            ldsm_x2_t(bl[j], smem_u32(&sBl[(k0 + bK) * FB_STRIDE + nf]));
        }
        #pragma unroll
        for (int i = 0; i < 2; i++)
            #pragma unroll
            for (int j = 0; j < 4; j++) {
                mma_bf16(acc[i][j], ah[i], bh[j]);
                mma_bf16(acc[i][j], ah[i], bl[j]);
                mma_bf16(acc[i][j], al[i], bh[j]);
            }
    }

    int g = lane >> 2, q = (lane & 3) * 2;
    float* Yr = g_r1 + (size_t)bh * WH * C_;
    float* Yi = g_i1 + (size_t)bh * WH * C_;
    #pragma unroll
    for (int i = 0; i < 2; i++)
        #pragma unroll
        for (int j = 0; j < 4; j++) {
            int row = wm * 32 + i * 16 + g;
            int col = c0 + wn * 32 + j * 8 + q;
            float* dst = (row < 32) ? Yr + (size_t)row * C_ : Yi + (size_t)(row - 32) * C_;
            float2 v0 = {acc[i][j][0], acc[i][j][1]};
            float2 v1 = {acc[i][j][2], acc[i][j][3]};
            *(float2*)&dst[col]          = v0;
            *(float2*)&dst[8 * C_ + col] = v1;
        }

    // Nyquist row k=32
    if (tid < 128) {
        float alt = 0.f;
        #pragma unroll 8
        for (int w = 0; w < W_; w++) {
            float xv = __bfloat162float(sBh[w * FB_STRIDE + tid])
                     + __bfloat162float(sBl[w * FB_STRIDE + tid]);
            alt += (w & 1) ? -xv : xv;
        }
        Yr[(size_t)32 * C_ + c0 + tid] = alt;
        Yi[(size_t)32 * C_ + c0 + tid] = 0.f;
    }
}

// ---- W-direction inverse real DFT (MMA): g_xr/g_xi -> out (accumulate)
// B rows: 0..32 <- Fr[k], 33..63 <- Fi[k=row-32]; weights folded in A.
__global__ __launch_bounds__(256) void fft_w_inv_mma(float* __restrict__ out)
{
    extern __shared__ char smem[];
    __nv_bfloat16* sAh = (__nv_bfloat16*)(smem + SM_AH);
    __nv_bfloat16* sAl = (__nv_bfloat16*)(smem + SM_AL);
    __nv_bfloat16* sBh = (__nv_bfloat16*)(smem + SM_BH);
    __nv_bfloat16* sBl = (__nv_bfloat16*)(smem + SM_BL);

    int bh = blockIdx.x;
    int c0 = blockIdx.y * 128;
    int tid = threadIdx.x, wid = tid >> 5, lane = tid & 31;
    int wm = wid >> 2, wn = wid & 3;

    const float* Fr = g_xr + (size_t)bh * WH * C_;
    const float* Fi = g_xi + (size_t)bh * WH * C_;

    #pragma unroll
    for (int it = 0; it < 4; it++) {
        int lin = tid + 256 * it;
        int r = lin >> 4, cq = (lin & 15) * 4;
        *(uint2*)&sAh[r * FA_STRIDE + cq] = *(const uint2*)&g_Awi_h[r * 64 + cq];
        *(uint2*)&sAl[r * FA_STRIDE + cq] = *(const uint2*)&g_Awi_l[r * 64 + cq];
    }
    #pragma unroll
    for (int it = 0; it < 8; it++) {
        int lin = tid + 256 * it;
        int r = lin >> 5, cq = (lin & 31) * 4;
        const float* src = (r < 33) ? &Fr[(size_t)r * C_ + c0 + cq]
                                    : &Fi[(size_t)(r - 32) * C_ + c0 + cq];
        float4 v = *(const float4*)src;
        __nv_bfloat16 h[4], l[4];
        split4(v, h, l);
        *(uint2*)&sBh[r * FB_STRIDE + cq] = *(uint2*)h;
        *(uint2*)&sBl[r * FB_STRIDE + cq] = *(uint2*)l;
    }
    __syncthreads();

    float acc[2][4][4] = {};
    int aRow = lane & 15, aK = (lane >> 4) * 8, bK = lane & 15;
    #pragma unroll
    for (int ks = 0; ks < 4; ks++) {
        int k0 = ks * 16;
        uint32_t ah[2][4], al[2][4], bh[4][2], bl[4][2];
        #pragma unroll
        for (int i = 0; i < 2; i++) {
            int row = wm * 32 + i * 16 + aRow;
            ldsm_x4(ah[i], smem_u32(&sAh[row * FA_STRIDE + k0 + aK]));
            ldsm_x4(al[i], smem_u32(&sAl[row * FA_STRIDE + k0 + aK]));
        }
        #pragma unroll
        for (int j = 0; j < 4; j++) {
            int nf = wn * 32 + j * 8;
            ldsm_x2_t(bh[j], smem_u32(&sBh[(k0 + bK) * FB_STRIDE + nf]));
            ldsm_x2_t(bl[j], smem_u32(&sBl[(k0 + bK) * FB_STRIDE + nf]));
        }
        #pragma unroll
        for (int i = 0; i < 2; i++)
            #pragma unroll
            for (int j = 0; j < 4; j++) {
                mma_bf16(acc[i][j], ah[i], bh[j]);
                mma_bf16(acc[i][j], ah[i], bl[j]);
                mma_bf16(acc[i][j], al[i], bh[j]);
            }
    }

    int g = lane >> 2, q = (lane & 3) * 2;
    float* op = out + (size_t)bh * 64 * C_;
    #pragma unroll
    for (int i = 0; i < 2; i++)
        #pragma unroll
        for (int j = 0; j < 4; j++) {
            int w = wm * 32 + i * 16 + g;
            int col = c0 + wn * 32 + j * 8 + q;
            float* d0 = &op[(size_t)w * C_ + col];
            float* d1 = &op[(size_t)(w + 8) * C_ + col];
            float2 c0v = *(float2*)d0;
            float2 c1v = *(float2*)d1;
            c0v.x += acc[i][j][0]; c0v.y += acc[i][j][1];
            c1v.x += acc[i][j][2]; c1v.y += acc[i][j][3];
            *(float2*)d0 = c0v;
            *(float2*)d1 = c1v;
        }
}

// =====================================================================
// freq MLP via mma.sync (validated R5)
// =====================================================================
#define FM 128
#define FN 64
#define FK 16
#define XPAD (FK + 8)
#define WPAD (FN + 8)

__global__ __launch_bounds__(256) void freq_l1_mma(
    const float* __restrict__ w1, const float* __restrict__ b1)
{
    __shared__ __align__(16) __nv_bfloat16 sXrh[FM][XPAD], sXrl[FM][XPAD];
    __shared__ __align__(16) __nv_bfloat16 sXih[FM][XPAD], sXil[FM][XPAD];
    __shared__ __align__(16) __nv_bfloat16 sWrh[FK][WPAD], sWrl[FK][WPAD];
    __shared__ __align__(16) __nv_bfloat16 sWih[FK][WPAD], sWil[FK][WPAD];
    __shared__ __align__(16) __nv_bfloat16 sWnh[FK][WPAD], sWnl[FK][WPAD];

    int tid = threadIdx.x, wid = tid >> 5, lane = tid & 31;
    int wm = wid >> 2, wn = wid & 3;
    int p0 = blockIdx.x * FM, j0 = blockIdx.y * FN, nb = blockIdx.z;
    const float* Wr = w1 + (size_t)nb * BS_ * BS_;
    const float* Wi = w1 + (size_t)(NBLK + nb) * BS_ * BS_;

    float accR[4][2][4] = {}, accI[4][2][4] = {};
    int aRow = lane & 15, aK = (lane >> 4) * 8;
    int bKrow = lane & 15;

    for (int kt = 0; kt < BS_; kt += FK) {
        #pragma unroll
        for (int it = 0; it < 2; it++) {
            int lin = tid + 256 * it;
            int r = lin >> 2, cq = (lin & 3) * 4;
            float4 vr = *(const float4*)&g_xr[(size_t)(p0 + r) * C_ + nb * BS_ + kt + cq];
            float4 vi = *(const float4*)&g_xi[(size_t)(p0 + r) * C_ + nb * BS_ + kt + cq];
            __nv_bfloat16 h[4], l[4];
            split4(vr, h, l);
            *(uint2*)&sXrh[r][cq] = *(uint2*)h;
            *(uint2*)&sXrl[r][cq] = *(uint2*)l;
            split4(vi, h, l);
            *(uint2*)&sXih[r][cq] = *(uint2*)h;
            *(uint2*)&sXil[r][cq] = *(uint2*)l;
        }
        {
            int d = tid >> 4, jq = (tid & 15) * 4;
            float4 vr = *(const float4*)&Wr[(size_t)(kt + d) * BS_ + j0 + jq];
            float4 vi = *(const float4*)&Wi[(size_t)(kt + d) * BS_ + j0 + jq];
            __nv_bfloat16 h[4], l[4];
            split4(vr, h, l);
            *(uint2*)&sWrh[d][jq] = *(uint2*)h;
            *(uint2*)&sWrl[d][jq] = *(uint2*)l;
            split4(vi, h, l);
            *(uint2*)&sWih[d][jq] = *(uint2*)h;
            *(uint2*)&sWil[d][jq] = *(uint2*)l;
            float4 vn = {-vi.x, -vi.y, -vi.z, -vi.w};
            split4(vn, h, l);
            *(uint2*)&sWnh[d][jq] = *(uint2*)h;
            *(uint2*)&sWnl[d][jq] = *(uint2*)l;
        }
        __syncthreads();

        uint32_t axrh[4][4], axrl[4][4], axih[4][4], axil[4][4];
        #pragma unroll
        for (int i = 0; i < 4; i++) {
            int row = wm * 64 + i * 16 + aRow;
            ldsm_x4(axrh[i], smem_u32(&sXrh[row][aK]));
            ldsm_x4(axrl[i], smem_u32(&sXrl[row][aK]));
            ldsm_x4(axih[i], smem_u32(&sXih[row][aK]));
            ldsm_x4(axil[i], smem_u32(&sXil[row][aK]));
        }
        uint32_t bwrh[2][2], bwrl[2][2], bwih[2][2], bwil[2][2], bwnh[2][2], bwnl[2][2];
        #pragma unroll
        for (int j = 0; j < 2; j++) {
            int nf = wn * 16 + j * 8;
            ldsm_x2_t(bwrh[j], smem_u32(&sWrh[bKrow][nf]));
            ldsm_x2_t(bwrl[j], smem_u32(&sWrl[bKrow][nf]));
            ldsm_x2_t(bwih[j], smem_u32(&sWih[bKrow][nf]));
            ldsm_x2_t(bwil[j], smem_u32(&sWil[bKrow][nf]));
            ldsm_x2_t(bwnh[j], smem_u32(&sWnh[bKrow][nf]));
            ldsm_x2_t(bwnl[j], smem_u32(&sWnl[bKrow][nf]));
        }
        #pragma unroll
        for (int i = 0; i < 4; i++)
            #pragma unroll
            for (int j = 0; j < 2; j++) {
                mma_bf16(accR[i][j], axrh[i], bwrh[j]);
                mma_bf16(accR[i][j], axrh[i], bwrl[j]);
                mma_bf16(accR[i][j], axrl[i], bwrh[j]);
                mma_bf16(accR[i][j], axih[i], bwnh[j]);
                mma_bf16(accR[i][j], axih[i], bwnl[j]);
                mma_bf16(accR[i][j], axil[i], bwnh[j]);
                mma_bf16(accI[i][j], axrh[i], bwih[j]);
                mma_bf16(accI[i][j], axrh[i], bwil[j]);
                mma_bf16(accI[i][j], axrl[i], bwih[j]);
                mma_bf16(accI[i][j], axih[i], bwrh[j]);
                mma_bf16(accI[i][j], axih[i], bwrl[j]);
                mma_bf16(accI[i][j], axil[i], bwrh[j]);
            }
        __syncthreads();
    }

    const float* br = b1 + (size_t)nb * BS_;
    const float* bi = b1 + (size_t)(NBLK + nb) * BS_;
    int g = lane >> 2, q = (lane & 3) * 2;
    #pragma unroll
    for (int i = 0; i < 4; i++)
        #pragma unroll
        for (int j = 0; j < 2; j++) {
            int col = j0 + wn * 16 + j * 8 + q;
            float br0 = br[col], br1 = br[col + 1];
            float bi0 = bi[col], bi1 = bi[col + 1];
            int r0 = p0 + wm * 64 + i * 16 + g;
            size_t o0 = (size_t)r0 * C_ + nb * BS_ + col;
            size_t o1 = (size_t)(r0 + 8) * C_ + nb * BS_ + col;
            float2 vr0 = {fmaxf(accR[i][j][0] + br0, 0.f), fmaxf(accR[i][j][1] + br1, 0.f)};
            float2 vr1 = {fmaxf(accR[i][j][2] + br0, 0.f), fmaxf(accR[i][j][3] + br1, 0.f)};
            float2 vi0 = {fmaxf(accI[i][j][0] + bi0, 0.f), fmaxf(accI[i][j][1] + bi1, 0.f)};
            float2 vi1 = {fmaxf(accI[i][j][2] + bi0, 0.f), fmaxf(accI[i][j][3] + bi1, 0.f)};
            *(float2*)&g_r1[o0] = vr0;
            *(float2*)&g_r1[o1] = vr1;
            *(float2*)&g_i1[o0] = vi0;
            *(float2*)&g_i1[o1] = vi1;
        }
}

__global__ __launch_bounds__(256) void freq_l2_mma(
    const float* __restrict__ w2, const float* __restrict__ b2, int phase)
{
    __shared__ __align__(16) __nv_bfloat16 sAh[FM][XPAD], sAl[FM][XPAD];
    __shared__ __align__(16) __nv_bfloat16 sBh[FM][XPAD], sBl[FM][XPAD];
    __shared__ __align__(16) __nv_bfloat16 sWah[FK][WPAD], sWal[FK][WPAD];
    __shared__ __align__(16) __nv_bfloat16 sWbh[FK][WPAD], sWbl[FK][WPAD];

    int tid = threadIdx.x, wid = tid >> 5, lane = tid & 31;
    int wm = wid >> 2, wn = wid & 3;
    int p0 = blockIdx.x * FM, j0 = blockIdx.y * FN, nb = blockIdx.z;

    const float* A  = (phase == 0 ? g_r1 : g_r2);
    const float* Bm = g_i1;
    const float* Wa = w2 + (size_t)((phase == 0 ? 0 : NBLK) + nb) * BS_ * BS_;
    const float* Wb = w2 + (size_t)((phase == 0 ? NBLK : 0) + nb) * BS_ * BS_;
    const float* bias = b2 + (size_t)(phase == 0 ? 0 : NBLK) * BS_ + (size_t)nb * BS_;
    float* O = (phase == 0 ? g_r2 : g_i2);
    float sgn = (phase == 0) ? -1.f : 1.f;

    float acc[4][2][4] = {};
    int aRow = lane & 15, aK = (lane >> 4) * 8;
    int bKrow = lane & 15;

    for (int kt = 0; kt < BS_; kt += FK) {
        #pragma unroll
        for (int it = 0; it < 2; it++) {
            int lin = tid + 256 * it;
            int r = lin >> 2, cq = (lin & 3) * 4;
            float4 va = *(const float4*)&A [(size_t)(p0 + r) * C_ + nb * BS_ + kt + cq];
            float4 vb = *(const float4*)&Bm[(size_t)(p0 + r) * C_ + nb * BS_ + kt + cq];
            __nv_bfloat16 h[4], l[4];
            split4(va, h, l);
            *(uint2*)&sAh[r][cq] = *(uint2*)h;
            *(uint2*)&sAl[r][cq] = *(uint2*)l;
            split4(vb, h, l);
            *(uint2*)&sBh[r][cq] = *(uint2*)h;
            *(uint2*)&sBl[r][cq] = *(uint2*)l;
        }
        {
            int d = tid >> 4, jq = (tid & 15) * 4;
            float4 va = *(const float4*)&Wa[(size_t)(kt + d) * BS_ + j0 + jq];
            float4 vb = *(const float4*)&Wb[(size_t)(kt + d) * BS_ + j0 + jq];
            vb.x *= sgn; vb.y *= sgn; vb.z *= sgn; vb.w *= sgn;
            __nv_bfloat16 h[4], l[4];
            split4(va, h, l);
            *(uint2*)&sWah[d][jq] = *(uint2*)h;
            *(uint2*)&sWal[d][jq] = *(uint2*)l;
            split4(vb, h, l);
            *(uint2*)&sWbh[d][jq] = *(uint2*)h;
            *(uint2*)&sWbl[d][jq] = *(uint2*)l;
        }
        __syncthreads();

        uint32_t aah[4][4], aal[4][4], abh[4][4], abl[4][4];
        #pragma unroll
        for (int i = 0; i < 4; i++) {
            int row = wm * 64 + i * 16 + aRow;
            ldsm_x4(aah[i], smem_u32(&sAh[row][aK]));
            ldsm_x4(aal[i], smem_u32(&sAl[row][aK]));
            ldsm_x4(abh[i], smem_u32(&sBh[row][aK]));
            ldsm_x4(abl[i], smem_u32(&sBl[row][aK]));
        }
        uint32_t bah[2][2], bal[2][2], bbh[2][2], bbl[2][2];
        #pragma unroll
        for (int j = 0; j < 2; j++) {
            int nf = wn * 16 + j * 8;
            ldsm_x2_t(bah[j], smem_u32(&sWah[bKrow][nf]));
            ldsm_x2_t(bal[j], smem_u32(&sWal[bKrow][nf]));
            ldsm_x2_t(bbh[j], smem_u32(&sWbh[bKrow][nf]));
            ldsm_x2_t(bbl[j], smem_u32(&sWbl[bKrow][nf]));
        }
        #pragma unroll
        for (int i = 0; i < 4; i++)
            #pragma unroll
            for (int j = 0; j < 2; j++) {
                mma_bf16(acc[i][j], aah[i], bah[j]);
                mma_bf16(acc[i][j], aah[i], bal[j]);
                mma_bf16(acc[i][j], aal[i], bah[j]);
                mma_bf16(acc[i][j], abh[i], bbh[j]);
                mma_bf16(acc[i][j], abh[i], bbl[j]);
                mma_bf16(acc[i][j], abl[i], bbh[j]);
            }
        __syncthreads();
    }

    int g = lane >> 2, q = (lane & 3) * 2;
    #pragma unroll
    for (int i = 0; i < 4; i++)
        #pragma unroll
        for (int j = 0; j < 2; j++) {
            int col = j0 + wn * 16 + j * 8 + q;
            float b0 = bias[col], b1 = bias[col + 1];
            int r0 = p0 + wm * 64 + i * 16 + g;
            float2 v0 = {acc[i][j][0] + b0, acc[i][j][1] + b1};
            float2 v1 = {acc[i][j][2] + b0, acc[i][j][3] + b1};
            *(float2*)&O[(size_t)r0 * C_ + nb * BS_ + col]       = v0;
            *(float2*)&O[(size_t)(r0 + 8) * C_ + nb * BS_ + col] = v1;
        }
}

// =====================================================================
extern "C" void kernel_launch(void* const* d_in, const int* in_sizes, int n_in,
                              void* d_out, int out_size)
{
    const float* x  = (const float*)d_in[0];
    const float* w1 = (const float*)d_in[1];
    const float* b1 = (const float*)d_in[2];
    const float* w2 = (const float*)d_in[3];
    const float* b2 = (const float*)d_in[4];
    const float* bw = (const float*)d_in[5];
    const float* bb = (const float*)d_in[6];
    float* out = (float*)d_out;

    cudaFuncSetAttribute(fft_h_mma, cudaFuncAttributeMaxDynamicSharedMemorySize, SM_FFT_TOTAL);
    cudaFuncSetAttribute(fft_w_mma, cudaFuncAttributeMaxDynamicSharedMemorySize, SM_FFT_TOTAL);
    cudaFuncSetAttribute(fft_w_inv_mma, cudaFuncAttributeMaxDynamicSharedMemorySize, SM_FFT_TOTAL);

    init_tables<<<32, 256>>>();

    bias_mma<<<dim3(C_ / TBN, NTOK / TBM), 256>>>(x, bw, bb, out);

    fft_w_mma<<<dim3(B_ * H_, C_ / 128), 256, SM_FFT_TOTAL>>>(x);   // (512, 6)
    fft_h_mma<<<dim3(NKC / 128, B_), 256, SM_FFT_TOTAL>>>(0);       // (198, 16)

    dim3 gFreq(P_ / FM, BS_ / FN, NBLK);    // (132, 3, 4)
    freq_l1_mma<<<gFreq, 256>>>(w1, b1);
    freq_l2_mma<<<gFreq, 256>>>(w2, b2, 0);
    freq_l2_mma<<<gFreq, 256>>>(w2, b2, 1);

    fft_h_mma<<<dim3(NKC / 128, B_), 256, SM_FFT_TOTAL>>>(1);       // (198, 16)
    fft_w_inv_mma<<<dim3(B_ * H_, C_ / 128), 256, SM_FFT_TOTAL>>>(out);  // (512, 6)
}

// round 10
// speedup vs baseline: 5.3622x; 1.3076x over previous
#include <cuda_runtime.h>
#include <cuda_bf16.h>
#include <cstdint>

// ---------------- problem constants ----------------
#define B_  16
#define H_  32
#define W_  64
#define WH  33            // W/2+1
#define C_  768
#define NBLK 4
#define BS_ 192           // C/NBLK
#define P_  (B_*H_*WH)    // 16896 frequency positions
#define NKC (WH*C_)       // 25344
#define NTOK (B_*H_*W_)   // 32768 spatial tokens

#define SC_ORTHO 0.0220970869120796f   // 1/sqrt(2048)

// ---------------- scratch (bf16 freq-domain data path) ----------------
__device__ __nv_bfloat16 g_xr[(size_t)P_ * C_];
__device__ __nv_bfloat16 g_xi[(size_t)P_ * C_];
__device__ __nv_bfloat16 g_r1[(size_t)P_ * C_];
__device__ __nv_bfloat16 g_i1[(size_t)P_ * C_];
__device__ __nv_bfloat16 g_r2[(size_t)P_ * C_];
__device__ __nv_bfloat16 g_i2[(size_t)P_ * C_];

// pre-split 64x64 DFT operator matrices (bf16 hi/lo)
__device__ __nv_bfloat16 g_Ahf_h[4096], g_Ahf_l[4096];   // H fwd (scaled)
__device__ __nv_bfloat16 g_Ahi_h[4096], g_Ahi_l[4096];   // H inv
__device__ __nv_bfloat16 g_Awf_h[4096], g_Awf_l[4096];   // W fwd (k=0..31)
__device__ __nv_bfloat16 g_Awi_h[4096], g_Awi_l[4096];   // W inv (weights folded)

// =====================================================================
// portable tensor-core helpers
// =====================================================================
__device__ __forceinline__ uint32_t smem_u32(const void* p) {
    uint32_t a;
    asm("{ .reg .u64 t; cvta.to.shared.u64 t, %1; cvt.u32.u64 %0, t; }" : "=r"(a) : "l"(p));
    return a;
}
__device__ __forceinline__ void mma_bf16(float* d, const uint32_t* a, const uint32_t* b) {
    asm volatile("mma.sync.aligned.m16n8k16.row.col.f32.bf16.bf16.f32 "
        "{%0,%1,%2,%3}, {%4,%5,%6,%7}, {%8,%9}, {%0,%1,%2,%3};"
        : "+f"(d[0]), "+f"(d[1]), "+f"(d[2]), "+f"(d[3])
        : "r"(a[0]), "r"(a[1]), "r"(a[2]), "r"(a[3]), "r"(b[0]), "r"(b[1]));
}
__device__ __forceinline__ void ldsm_x4(uint32_t* r, uint32_t addr) {
    asm volatile("ldmatrix.sync.aligned.m8n8.x4.shared.b16 {%0,%1,%2,%3}, [%4];"
        : "=r"(r[0]), "=r"(r[1]), "=r"(r[2]), "=r"(r[3]) : "r"(addr));
}
__device__ __forceinline__ void ldsm_x2(uint32_t* r, uint32_t addr) {
    asm volatile("ldmatrix.sync.aligned.m8n8.x2.shared.b16 {%0,%1}, [%2];"
        : "=r"(r[0]), "=r"(r[1]) : "r"(addr));
}
__device__ __forceinline__ void ldsm_x2_t(uint32_t* r, uint32_t addr) {
    asm volatile("ldmatrix.sync.aligned.m8n8.x2.trans.shared.b16 {%0,%1}, [%2];"
        : "=r"(r[0]), "=r"(r[1]) : "r"(addr));
}
__device__ __forceinline__ void split4(float4 v, __nv_bfloat16* h, __nv_bfloat16* l) {
    float a[4] = {v.x, v.y, v.z, v.w};
    #pragma unroll
    for (int q = 0; q < 4; q++) {
        h[q] = __float2bfloat16(a[q]);
        l[q] = __float2bfloat16(a[q] - __bfloat162float(h[q]));
    }
}
__device__ __forceinline__ void cvt4(float4 v, __nv_bfloat16* h) {
    h[0] = __float2bfloat16(v.x);
    h[1] = __float2bfloat16(v.y);
    h[2] = __float2bfloat16(v.z);
    h[3] = __float2bfloat16(v.w);
}
__device__ __forceinline__ void split1(float v, __nv_bfloat16& h, __nv_bfloat16& l) {
    h = __float2bfloat16(v);
    l = __float2bfloat16(v - __bfloat162float(h));
}
__device__ __forceinline__ uint32_t pack_bf2(float a, float b) {
    __nv_bfloat162 t = __floats2bfloat162_rn(a, b);   // .x = a (low), .y = b (high)
    return *(uint32_t*)&t;
}

// =====================================================================
__global__ void init_tables()
{
    int idx = blockIdx.x * blockDim.x + threadIdx.x;
    for (int i = idx; i < 4096; i += gridDim.x * blockDim.x) {
        int r = i >> 6, q = i & 63;
        // ---- H forward (scaled)
        {
            float s, c;
            sincospif((float)((r & 31) * (q & 31)) / 16.0f, &s, &c);
            float v;
            if (r < 32)  v = (q < 32) ? c : s;
            else         v = (q < 32) ? -s : c;
            split1(v * SC_ORTHO, g_Ahf_h[i], g_Ahf_l[i]);
        }
        // ---- H inverse
        {
            float s, c;
            sincospif((float)((r & 31) * (q & 31)) / 16.0f, &s, &c);
            float v;
            if (r < 32)  v = (q < 32) ? c : -s;
            else         v = (q < 32) ? s : c;
            split1(v, g_Ahi_h[i], g_Ahi_l[i]);
        }
        // ---- W forward: rows 0-31 cos, rows 32-63 -sin
        {
            float s, c;
            sincospif((float)((r & 31) * q) / 32.0f, &s, &c);
            float v = (r < 32) ? c : -s;
            split1(v, g_Awf_h[i], g_Awf_l[i]);
        }
        // ---- W inverse, weights folded
        {
            float v;
            if (q == 0) {
                v = SC_ORTHO;
            } else if (q < 32) {
                float s, c;
                sincospif((float)(q * r) / 32.0f, &s, &c);
                v = 2.f * SC_ORTHO * c;
            } else if (q == 32) {
                v = (r & 1) ? -SC_ORTHO : SC_ORTHO;
            } else {
                int k = q - 32;
                float s, c;
                sincospif((float)(k * r) / 32.0f, &s, &c);
                v = -2.f * SC_ORTHO * s;
            }
            split1(v, g_Awi_h[i], g_Awi_l[i]);
        }
    }
}

// =====================================================================
// bias GEMM via mma.sync bf16 split-precision (validated; untouched)
// =====================================================================
#define TBM 128
#define TBN 128
#define TBK 32
#define KPAD (TBK + 8)

__global__ __launch_bounds__(256) void bias_mma(
    const float* __restrict__ X, const float* __restrict__ Wm,
    const float* __restrict__ bb, float* __restrict__ out)
{
    __shared__ __align__(16) __nv_bfloat16 sAhi[TBM][KPAD];
    __shared__ __align__(16) __nv_bfloat16 sAlo[TBM][KPAD];
    __shared__ __align__(16) __nv_bfloat16 sBhi[TBN][KPAD];
    __shared__ __align__(16) __nv_bfloat16 sBlo[TBN][KPAD];

    int tid = threadIdx.x;
    int wid = tid >> 5, lane = tid & 31;
    int wm = wid >> 2, wn = wid & 3;
    int m0 = blockIdx.y * TBM, n0 = blockIdx.x * TBN;

    float acc[4][4][4] = {};

    int aRow = lane & 15, aKoff = (lane >> 4) * 8;
    int bRow = lane & 7,  bKoff = ((lane >> 3) & 1) * 8;

    for (int kt = 0; kt < C_; kt += TBK) {
        #pragma unroll
        for (int it = 0; it < 4; it++) {
            int lin = tid + 256 * it;
            int r = lin >> 3, cq = (lin & 7) * 4;
            float4 va = *(const float4*)&X [(size_t)(m0 + r) * C_ + kt + cq];
            float4 vb = *(const float4*)&Wm[(size_t)(n0 + r) * C_ + kt + cq];
            __nv_bfloat16 ah[4], al[4], bh[4], bl[4];
            split4(va, ah, al);
            split4(vb, bh, bl);
            *(uint2*)&sAhi[r][cq] = *(uint2*)ah;
            *(uint2*)&sAlo[r][cq] = *(uint2*)al;
            *(uint2*)&sBhi[r][cq] = *(uint2*)bh;
            *(uint2*)&sBlo[r][cq] = *(uint2*)bl;
        }
        __syncthreads();

        #pragma unroll
        for (int s = 0; s < 2; s++) {
            int k0 = s * 16;
            uint32_t a_hi[4][4], a_lo[4][4], b_hi[4][2], b_lo[4][2];
            #pragma unroll
            for (int i = 0; i < 4; i++) {
                int row = wm * 64 + i * 16 + aRow;
                ldsm_x4(a_hi[i], smem_u32(&sAhi[row][k0 + aKoff]));
                ldsm_x4(a_lo[i], smem_u32(&sAlo[row][k0 + aKoff]));
            }
            #pragma unroll
            for (int j = 0; j < 4; j++) {
                int row = wn * 32 + j * 8 + bRow;
                ldsm_x2(b_hi[j], smem_u32(&sBhi[row][k0 + bKoff]));
                ldsm_x2(b_lo[j], smem_u32(&sBlo[row][k0 + bKoff]));
            }
            #pragma unroll
            for (int i = 0; i < 4; i++)
                #pragma unroll
                for (int j = 0; j < 4; j++) {
                    mma_bf16(acc[i][j], a_hi[i], b_hi[j]);
                    mma_bf16(acc[i][j], a_hi[i], b_lo[j]);
                    mma_bf16(acc[i][j], a_lo[i], b_hi[j]);
                }
        }
        __syncthreads();
    }

    int group = lane >> 2, qid = lane & 3;
    #pragma unroll
    for (int i = 0; i < 4; i++) {
        #pragma unroll
        for (int j = 0; j < 4; j++) {
            int col = n0 + wn * 32 + j * 8 + qid * 2;
            float b0 = bb[col], b1 = bb[col + 1];
            int r0 = m0 + wm * 64 + i * 16 + group;
            float2 v0 = {acc[i][j][0] + b0, acc[i][j][1] + b1};
            float2 v1 = {acc[i][j][2] + b0, acc[i][j][3] + b1};
            *(float2*)&out[(size_t)r0 * C_ + col]       = v0;
            *(float2*)&out[(size_t)(r0 + 8) * C_ + col] = v1;
        }
    }
}

// =====================================================================
// FFT-as-GEMM kernels: C[64, N] = A(64x64, split 2-term) @ B[64, N] (bf16)
// =====================================================================
#define FA_STRIDE 72
#define FB_STRIDE 136

// ---- H-direction DFT (dir 0 = fwd g_r1/g_i1 -> g_xr/g_xi, dir 1 = inv g_r2/g_i2 -> g_xr/g_xi)
__global__ __launch_bounds__(256) void fft_h_mma(int dir)
{
    __shared__ __align__(16) __nv_bfloat16 sAh[64 * FA_STRIDE];
    __shared__ __align__(16) __nv_bfloat16 sAl[64 * FA_STRIDE];
    __shared__ __align__(16) __nv_bfloat16 sB [64 * FB_STRIDE];

    int n0 = blockIdx.x * 128;
    int b  = blockIdx.y;
    int tid = threadIdx.x, wid = tid >> 5, lane = tid & 31;
    int wm = wid >> 2, wn = wid & 3;

    const __nv_bfloat16* gAh = dir ? g_Ahi_h : g_Ahf_h;
    const __nv_bfloat16* gAl = dir ? g_Ahi_l : g_Ahf_l;
    const __nv_bfloat16* Br = (dir ? g_r2 : g_r1) + (size_t)b * H_ * NKC;
    const __nv_bfloat16* Bi = (dir ? g_i2 : g_i1) + (size_t)b * H_ * NKC;
    __nv_bfloat16* Or = g_xr + (size_t)b * H_ * NKC;
    __nv_bfloat16* Oi = g_xi + (size_t)b * H_ * NKC;

    // A fill: 64x64 hi/lo
    #pragma unroll
    for (int it = 0; it < 4; it++) {
        int lin = tid + 256 * it;
        int r = lin >> 4, cq = (lin & 15) * 4;
        *(uint2*)&sAh[r * FA_STRIDE + cq] = *(const uint2*)&gAh[r * 64 + cq];
        *(uint2*)&sAl[r * FA_STRIDE + cq] = *(const uint2*)&gAl[r * 64 + cq];
    }
    // B fill: 64 rows x 128 bf16 cols (8 per thread-iter)
    #pragma unroll
    for (int it = 0; it < 4; it++) {
        int lin = tid + 256 * it;
        int r = lin >> 4, cq = (lin & 15) * 8;
        const __nv_bfloat16* src = (r < 32) ? &Br[(size_t)r * NKC + n0 + cq]
                                            : &Bi[(size_t)(r - 32) * NKC + n0 + cq];
        *(uint4*)&sB[r * FB_STRIDE + cq] = *(const uint4*)src;
    }
    __syncthreads();

    float acc[2][4][4] = {};
    int aRow = lane & 15, aK = (lane >> 4) * 8, bK = lane & 15;
    #pragma unroll
    for (int ks = 0; ks < 4; ks++) {
        int k0 = ks * 16;
        uint32_t ah[2][4], al[2][4], bf[4][2];
        #pragma unroll
        for (int i = 0; i < 2; i++) {
            int row = wm * 32 + i * 16 + aRow;
            ldsm_x4(ah[i], smem_u32(&sAh[row * FA_STRIDE + k0 + aK]));
            ldsm_x4(al[i], smem_u32(&sAl[row * FA_STRIDE + k0 + aK]));
        }
        #pragma unroll
        for (int j = 0; j < 4; j++) {
            int nf = wn * 32 + j * 8;
            ldsm_x2_t(bf[j], smem_u32(&sB[(k0 + bK) * FB_STRIDE + nf]));
        }
        #pragma unroll
        for (int i = 0; i < 2; i++)
            #pragma unroll
            for (int j = 0; j < 4; j++) {
                mma_bf16(acc[i][j], ah[i], bf[j]);
                mma_bf16(acc[i][j], al[i], bf[j]);
            }
    }

    int g = lane >> 2, q = (lane & 3) * 2;
    #pragma unroll
    for (int i = 0; i < 2; i++)
        #pragma unroll
        for (int j = 0; j < 4; j++) {
            int row = wm * 32 + i * 16 + g;
            int col = n0 + wn * 32 + j * 8 + q;
            __nv_bfloat16* dst = (row < 32) ? Or + (size_t)row * NKC : Oi + (size_t)(row - 32) * NKC;
            *(uint32_t*)&dst[col]           = pack_bf2(acc[i][j][0], acc[i][j][1]);
            *(uint32_t*)&dst[8 * NKC + col] = pack_bf2(acc[i][j][2], acc[i][j][3]);
        }
}

// ---- W-direction forward DFT: x (fp32) -> g_r1/g_i1 (bf16)
__global__ __launch_bounds__(256) void fft_w_mma(const float* __restrict__ X)
{
    __shared__ __align__(16) __nv_bfloat16 sAh[64 * FA_STRIDE];
    __shared__ __align__(16) __nv_bfloat16 sAl[64 * FA_STRIDE];
    __shared__ __align__(16) __nv_bfloat16 sB [64 * FB_STRIDE];

    int bh = blockIdx.x;
    int c0 = blockIdx.y * 128;
    int tid = threadIdx.x, wid = tid >> 5, lane = tid & 31;
    int wm = wid >> 2, wn = wid & 3;

    #pragma unroll
    for (int it = 0; it < 4; it++) {
        int lin = tid + 256 * it;
        int r = lin >> 4, cq = (lin & 15) * 4;
        *(uint2*)&sAh[r * FA_STRIDE + cq] = *(const uint2*)&g_Awf_h[r * 64 + cq];
        *(uint2*)&sAl[r * FA_STRIDE + cq] = *(const uint2*)&g_Awf_l[r * 64 + cq];
    }
    #pragma unroll
    for (int it = 0; it < 8; it++) {
        int lin = tid + 256 * it;
        int r = lin >> 5, cq = (lin & 31) * 4;
        float4 v = *(const float4*)&X[((size_t)bh * 64 + r) * C_ + c0 + cq];
        __nv_bfloat16 h[4];
        cvt4(v, h);
        *(uint2*)&sB[r * FB_STRIDE + cq] = *(uint2*)h;
    }
    __syncthreads();

    float acc[2][4][4] = {};
    int aRow = lane & 15, aK = (lane >> 4) * 8, bK = lane & 15;
    #pragma unroll
    for (int ks = 0; ks < 4; ks++) {
        int k0 = ks * 16;
        uint32_t ah[2][4], al[2][4], bf[4][2];
        #pragma unroll
        for (int i = 0; i < 2; i++) {
            int row = wm * 32 + i * 16 + aRow;
            ldsm_x4(ah[i], smem_u32(&sAh[row * FA_STRIDE + k0 + aK]));
            ldsm_x4(al[i], smem_u32(&sAl[row * FA_STRIDE + k0 + aK]));
        }
        #pragma unroll
        for (int j = 0; j < 4; j++) {
            int nf = wn * 32 + j * 8;
            ldsm_x2_t(bf[j], smem_u32(&sB[(k0 + bK) * FB_STRIDE + nf]));
        }
        #pragma unroll
        for (int i = 0; i < 2; i++)
            #pragma unroll
            for (int j = 0; j < 4; j++) {
                mma_bf16(acc[i][j], ah[i], bf[j]);
                mma_bf16(acc[i][j], al[i], bf[j]);
            }
    }

    int g = lane >> 2, q = (lane & 3) * 2;
    __nv_bfloat16* Yr = g_r1 + (size_t)bh * WH * C_;
    __nv_bfloat16* Yi = g_i1 + (size_t)bh * WH * C_;
    #pragma unroll
    for (int i = 0; i < 2; i++)
        #pragma unroll
        for (int j = 0; j < 4; j++) {
            int row = wm * 32 + i * 16 + g;
            int col = c0 + wn * 32 + j * 8 + q;
            __nv_bfloat16* dst = (row < 32) ? Yr + (size_t)row * C_ : Yi + (size_t)(row - 32) * C_;
            *(uint32_t*)&dst[col]          = pack_bf2(acc[i][j][0], acc[i][j][1]);
            *(uint32_t*)&dst[8 * C_ + col] = pack_bf2(acc[i][j][2], acc[i][j][3]);
        }

    // Nyquist row k=32: Yr = sum_w (-1)^w x[w], Yi = 0
    if (tid < 128) {
        float alt = 0.f;
        #pragma unroll 8
        for (int w = 0; w < W_; w++) {
            float xv = __bfloat162float(sB[w * FB_STRIDE + tid]);
            alt += (w & 1) ? -xv : xv;
        }
        Yr[(size_t)32 * C_ + c0 + tid] = __float2bfloat16(alt);
        Yi[(size_t)32 * C_ + c0 + tid] = __float2bfloat16(0.f);
    }
}

// ---- W-direction inverse real DFT (MMA): g_xr/g_xi (bf16) -> out (fp32, accumulate)
__global__ __launch_bounds__(256) void fft_w_inv_mma(float* __restrict__ out)
{
    __shared__ __align__(16) __nv_bfloat16 sAh[64 * FA_STRIDE];
    __shared__ __align__(16) __nv_bfloat16 sAl[64 * FA_STRIDE];
    __shared__ __align__(16) __nv_bfloat16 sB [64 * FB_STRIDE];

    int bh = blockIdx.x;
    int c0 = blockIdx.y * 128;
    int tid = threadIdx.x, wid = tid >> 5, lane = tid & 31;
    int wm = wid >> 2, wn = wid & 3;

    const __nv_bfloat16* Fr = g_xr + (size_t)bh * WH * C_;
    const __nv_bfloat16* Fi = g_xi + (size_t)bh * WH * C_;

    #pragma unroll
    for (int it = 0; it < 4; it++) {
        int lin = tid + 256 * it;
        int r = lin >> 4, cq = (lin & 15) * 4;
        *(uint2*)&sAh[r * FA_STRIDE + cq] = *(const uint2*)&g_Awi_h[r * 64 + cq];
        *(uint2*)&sAl[r * FA_STRIDE + cq] = *(const uint2*)&g_Awi_l[r * 64 + cq];
    }
    #pragma unroll
    for (int it = 0; it < 4; it++) {
        int lin = tid + 256 * it;
        int r = lin >> 4, cq = (lin & 15) * 8;
        const __nv_bfloat16* src = (r < 33) ? &Fr[(size_t)r * C_ + c0 + cq]
                                            : &Fi[(size_t)(r - 32) * C_ + c0 + cq];
        *(uint4*)&sB[r * FB_STRIDE + cq] = *(const uint4*)src;
    }
    __syncthreads();

    float acc[2][4][4] = {};
    int aRow = lane & 15, aK = (lane >> 4) * 8, bK = lane & 15;
    #pragma unroll
    for (int ks = 0; ks < 4; ks++) {
        int k0 = ks * 16;
        uint32_t ah[2][4], al[2][4], bf[4][2];
        #pragma unroll
        for (int i = 0; i < 2; i++) {
            int row = wm * 32 + i * 16 + aRow;
            ldsm_x4(ah[i], smem_u32(&sAh[row * FA_STRIDE + k0 + aK]));
            ldsm_x4(al[i], smem_u32(&sAl[row * FA_STRIDE + k0 + aK]));
        }
        #pragma unroll
        for (int j = 0; j < 4; j++) {
            int nf = wn * 32 + j * 8;
            ldsm_x2_t(bf[j], smem_u32(&sB[(k0 + bK) * FB_STRIDE + nf]));
        }
        #pragma unroll
        for (int i = 0; i < 2; i++)
            #pragma unroll
            for (int j = 0; j < 4; j++) {
                mma_bf16(acc[i][j], ah[i], bf[j]);
                mma_bf16(acc[i][j], al[i], bf[j]);
            }
    }

    int g = lane >> 2, q = (lane & 3) * 2;
    float* op = out + (size_t)bh * 64 * C_;
    #pragma unroll
    for (int i = 0; i < 2; i++)
        #pragma unroll
        for (int j = 0; j < 4; j++) {
            int w = wm * 32 + i * 16 + g;
            int col = c0 + wn * 32 + j * 8 + q;
            float* d0 = &op[(size_t)w * C_ + col];
            float* d1 = &op[(size_t)(w + 8) * C_ + col];
            float2 c0v = *(float2*)d0;
            float2 c1v = *(float2*)d1;
            c0v.x += acc[i][j][0]; c0v.y += acc[i][j][1];
            c1v.x += acc[i][j][2]; c1v.y += acc[i][j][3];
            *(float2*)d0 = c0v;
            *(float2*)d1 = c1v;
        }
}

// =====================================================================
// freq MLP via mma.sync, plain bf16 (1-term)
// =====================================================================
#define FM 128
#define FN 64
#define FK 16
#define XPAD (FK + 8)
#define WPAD (FN + 8)

__global__ __launch_bounds__(256) void freq_l1_mma(
    const float* __restrict__ w1, const float* __restrict__ b1)
{
    __shared__ __align__(16) __nv_bfloat16 sXr[FM][XPAD], sXi[FM][XPAD];
    __shared__ __align__(16) __nv_bfloat16 sWr[FK][WPAD], sWi[FK][WPAD], sWn[FK][WPAD];

    int tid = threadIdx.x, wid = tid >> 5, lane = tid & 31;
    int wm = wid >> 2, wn = wid & 3;
    int p0 = blockIdx.x * FM, j0 = blockIdx.y * FN, nb = blockIdx.z;
    const float* Wr = w1 + (size_t)nb * BS_ * BS_;
    const float* Wi = w1 + (size_t)(NBLK + nb) * BS_ * BS_;

    float accR[4][2][4] = {}, accI[4][2][4] = {};
    int aRow = lane & 15, aK = (lane >> 4) * 8;
    int bKrow = lane & 15;

    for (int kt = 0; kt < BS_; kt += FK) {
        // X fill: 128 rows x 16 bf16 cols, 8 per thread
        {
            int r = tid >> 1, cq = (tid & 1) * 8;
            *(uint4*)&sXr[r][cq] = *(const uint4*)&g_xr[(size_t)(p0 + r) * C_ + nb * BS_ + kt + cq];
            *(uint4*)&sXi[r][cq] = *(const uint4*)&g_xi[(size_t)(p0 + r) * C_ + nb * BS_ + kt + cq];
        }
        // W fill: 16 rows x 64 fp32 -> bf16
        {
            int d = tid >> 4, jq = (tid & 15) * 4;
            float4 vr = *(const float4*)&Wr[(size_t)(kt + d) * BS_ + j0 + jq];
            float4 vi = *(const float4*)&Wi[(size_t)(kt + d) * BS_ + j0 + jq];
            __nv_bfloat16 h[4];
            cvt4(vr, h);
            *(uint2*)&sWr[d][jq] = *(uint2*)h;
            cvt4(vi, h);
            *(uint2*)&sWi[d][jq] = *(uint2*)h;
            float4 vn = {-vi.x, -vi.y, -vi.z, -vi.w};
            cvt4(vn, h);
            *(uint2*)&sWn[d][jq] = *(uint2*)h;
        }
        __syncthreads();

        uint32_t axr[4][4], axi[4][4];
        #pragma unroll
        for (int i = 0; i < 4; i++) {
            int row = wm * 64 + i * 16 + aRow;
            ldsm_x4(axr[i], smem_u32(&sXr[row][aK]));
            ldsm_x4(axi[i], smem_u32(&sXi[row][aK]));
        }
        uint32_t bwr[2][2], bwi[2][2], bwn[2][2];
        #pragma unroll
        for (int j = 0; j < 2; j++) {
            int nf = wn * 16 + j * 8;
            ldsm_x2_t(bwr[j], smem_u32(&sWr[bKrow][nf]));
            ldsm_x2_t(bwi[j], smem_u32(&sWi[bKrow][nf]));
            ldsm_x2_t(bwn[j], smem_u32(&sWn[bKrow][nf]));
        }
        #pragma unroll
        for (int i = 0; i < 4; i++)
            #pragma unroll
            for (int j = 0; j < 2; j++) {
                mma_bf16(accR[i][j], axr[i], bwr[j]);   // Xr*Wr
                mma_bf16(accR[i][j], axi[i], bwn[j]);   // Xi*(-Wi)
                mma_bf16(accI[i][j], axr[i], bwi[j]);   // Xr*Wi
                mma_bf16(accI[i][j], axi[i], bwr[j]);   // Xi*Wr
            }
        __syncthreads();
    }

    const float* br = b1 + (size_t)nb * BS_;
    const float* bi = b1 + (size_t)(NBLK + nb) * BS_;
    int g = lane >> 2, q = (lane & 3) * 2;
    #pragma unroll
    for (int i = 0; i < 4; i++)
        #pragma unroll
        for (int j = 0; j < 2; j++) {
            int col = j0 + wn * 16 + j * 8 + q;
            float br0 = br[col], br1 = br[col + 1];
            float bi0 = bi[col], bi1 = bi[col + 1];
            int r0 = p0 + wm * 64 + i * 16 + g;
            size_t o0 = (size_t)r0 * C_ + nb * BS_ + col;
            size_t o1 = (size_t)(r0 + 8) * C_ + nb * BS_ + col;
            *(uint32_t*)&g_r1[o0] = pack_bf2(fmaxf(accR[i][j][0] + br0, 0.f), fmaxf(accR[i][j][1] + br1, 0.f));
            *(uint32_t*)&g_r1[o1] = pack_bf2(fmaxf(accR[i][j][2] + br0, 0.f), fmaxf(accR[i][j][3] + br1, 0.f));
            *(uint32_t*)&g_i1[o0] = pack_bf2(fmaxf(accI[i][j][0] + bi0, 0.f), fmaxf(accI[i][j][1] + bi1, 0.f));
            *(uint32_t*)&g_i1[o1] = pack_bf2(fmaxf(accI[i][j][2] + bi0, 0.f), fmaxf(accI[i][j][3] + bi1, 0.f));
        }
}

__global__ __launch_bounds__(256) void freq_l2_mma(
    const float* __restrict__ w2, const float* __restrict__ b2, int phase)
{
    __shared__ __align__(16) __nv_bfloat16 sA[FM][XPAD], sBm[FM][XPAD];
    __shared__ __align__(16) __nv_bfloat16 sWa[FK][WPAD], sWb[FK][WPAD];

    int tid = threadIdx.x, wid = tid >> 5, lane = tid & 31;
    int wm = wid >> 2, wn = wid & 3;
    int p0 = blockIdx.x * FM, j0 = blockIdx.y * FN, nb = blockIdx.z;

    const __nv_bfloat16* A  = (phase == 0 ? g_r1 : g_r2);
    const __nv_bfloat16* Bm = g_i1;
    const float* Wa = w2 + (size_t)((phase == 0 ? 0 : NBLK) + nb) * BS_ * BS_;
    const float* Wb = w2 + (size_t)((phase == 0 ? NBLK : 0) + nb) * BS_ * BS_;
    const float* bias = b2 + (size_t)(phase == 0 ? 0 : NBLK) * BS_ + (size_t)nb * BS_;
    __nv_bfloat16* O = (phase == 0 ? g_r2 : g_i2);
    float sgn = (phase == 0) ? -1.f : 1.f;

    float acc[4][2][4] = {};
    int aRow = lane & 15, aK = (lane >> 4) * 8;
    int bKrow = lane & 15;

    for (int kt = 0; kt < BS_; kt += FK) {
        {
            int r = tid >> 1, cq = (tid & 1) * 8;
            *(uint4*)&sA [r][cq] = *(const uint4*)&A [(size_t)(p0 + r) * C_ + nb * BS_ + kt + cq];
            *(uint4*)&sBm[r][cq] = *(const uint4*)&Bm[(size_t)(p0 + r) * C_ + nb * BS_ + kt + cq];
        }
        {
            int d = tid >> 4, jq = (tid & 15) * 4;
            float4 va = *(const float4*)&Wa[(size_t)(kt + d) * BS_ + j0 + jq];
            float4 vb = *(const float4*)&Wb[(size_t)(kt + d) * BS_ + j0 + jq];
            vb.x *= sgn; vb.y *= sgn; vb.z *= sgn; vb.w *= sgn;
            __nv_bfloat16 h[4];
            cvt4(va, h);
            *(uint2*)&sWa[d][jq] = *(uint2*)h;
            cvt4(vb, h);
            *(uint2*)&sWb[d][jq] = *(uint2*)h;
        }
        __syncthreads();

        uint32_t aa[4][4], ab[4][4];
        #pragma unroll
        for (int i = 0; i < 4; i++) {
            int row = wm * 64 + i * 16 + aRow;
            ldsm_x4(aa[i], smem_u32(&sA [row][aK]));
            ldsm_x4(ab[i], smem_u32(&sBm[row][aK]));
        }
        uint32_t ba[2][2], bbf[2][2];
        #pragma unroll
        for (int j = 0; j < 2; j++) {
            int nf = wn * 16 + j * 8;
            ldsm_x2_t(ba[j],  smem_u32(&sWa[bKrow][nf]));
            ldsm_x2_t(bbf[j], smem_u32(&sWb[bKrow][nf]));
        }
        #pragma unroll
        for (int i = 0; i < 4; i++)
            #pragma unroll
            for (int j = 0; j < 2; j++) {
                mma_bf16(acc[i][j], aa[i], ba[j]);
                mma_bf16(acc[i][j], ab[i], bbf[j]);
            }
        __syncthreads();
    }

    int g = lane >> 2, q = (lane & 3) * 2;
    #pragma unroll
    for (int i = 0; i < 4; i++)
        #pragma unroll
        for (int j = 0; j < 2; j++) {
            int col = j0 + wn * 16 + j * 8 + q;
            float b0 = bias[col], b1 = bias[col + 1];
            int r0 = p0 + wm * 64 + i * 16 + g;
            size_t o0 = (size_t)r0 * C_ + nb * BS_ + col;
            size_t o1 = (size_t)(r0 + 8) * C_ + nb * BS_ + col;
            *(uint32_t*)&O[o0] = pack_bf2(acc[i][j][0] + b0, acc[i][j][1] + b1);
            *(uint32_t*)&O[o1] = pack_bf2(acc[i][j][2] + b0, acc[i][j][3] + b1);
        }
}

// =====================================================================
extern "C" void kernel_launch(void* const* d_in, const int* in_sizes, int n_in,
                              void* d_out, int out_size)
{
    const float* x  = (const float*)d_in[0];
    const float* w1 = (const float*)d_in[1];
    const float* b1 = (const float*)d_in[2];
    const float* w2 = (const float*)d_in[3];
    const float* b2 = (const float*)d_in[4];
    const float* bw = (const float*)d_in[5];
    const float* bb = (const float*)d_in[6];
    float* out = (float*)d_out;

    init_tables<<<32, 256>>>();

    bias_mma<<<dim3(C_ / TBN, NTOK / TBM), 256>>>(x, bw, bb, out);

    fft_w_mma<<<dim3(B_ * H_, C_ / 128), 256>>>(x);        // (512, 6)
    fft_h_mma<<<dim3(NKC / 128, B_), 256>>>(0);            // (198, 16)

    dim3 gFreq(P_ / FM, BS_ / FN, NBLK);                   // (132, 3, 4)
    freq_l1_mma<<<gFreq, 256>>>(w1, b1);
    freq_l2_mma<<<gFreq, 256>>>(w2, b2, 0);
    freq_l2_mma<<<gFreq, 256>>>(w2, b2, 1);

    fft_h_mma<<<dim3(NKC / 128, B_), 256>>>(1);            // (198, 16)
    fft_w_inv_mma<<<dim3(B_ * H_, C_ / 128), 256>>>(out);  // (512, 6)
}